// round 11
// baseline (speedup 1.0000x reference)
#include <cuda_runtime.h>
#include <cuda_bf16.h>
#include <math.h>
#include <stdint.h>

#define N_NODES 50000
#define N_EDGES 800000
#define ETOT    850000   // edges + self loops
#define HID     64
#define HEADS   4
#define DDIM    256      // HID*HEADS
#define OUTF    40
#define NGRP    8
#define EPS_LN  1e-5f
#define CAP     96

// ---------------- scratch (device globals; no dynamic alloc allowed) ----------------
__device__ __nv_bfloat16 g_bufA[(size_t)N_NODES * DDIM];
__device__ __nv_bfloat16 g_bufB[(size_t)N_NODES * DDIM];
__device__ __nv_bfloat16 g_projb[(size_t)N_NODES * DDIM];
__device__ float g_als[N_NODES * HEADS];
__device__ float g_ald[N_NODES * HEADS];
__device__ int   g_deg[N_NODES];
__device__ int   g_off[N_NODES + 1];
__device__ int   g_cur[N_NODES];
__device__ int   g_adj[ETOT];
__device__ float g_sums[NGRP * DDIM];
__device__ float g_cnt[NGRP];
__device__ __nv_bfloat16 g_wthi[DDIM * DDIM];   // W^T hi, [N=256][K]
__device__ __nv_bfloat16 g_wtlo[DDIM * DDIM];   // W^T lo
#define NB_CSR ((N_NODES + 255) / 256)
__device__ int g_bsum[NB_CSR];
__device__ int g_boff[NB_CSR];

// ---------------- W prep: transpose + bf16 hi/lo split ----------------
__global__ void prep_wt_kernel(const float* __restrict__ W,
                               __nv_bfloat16* __restrict__ hi,
                               __nv_bfloat16* __restrict__ lo, int K) {
    int n = blockIdx.x;                    // 0..255
    for (int k = threadIdx.x; k < K; k += blockDim.x) {
        float v = W[(size_t)k * DDIM + n];
        __nv_bfloat16 h = __float2bfloat16(v);
        float r = v - __bfloat162float(h);
        hi[(size_t)n * K + k] = h;
        lo[(size_t)n * K + k] = __float2bfloat16(r);
    }
}

// ---------------- bf16x2 HMMA GEMM + fused attcoef + bf16 proj output ----------------
#define KCH 32
#define LDK 40          // padded smem row stride (bf16 elems); 80 B = 16B multiple
#define TILE_E (128 * LDK)          // bf16 elements per operand buffer (5120)
#define GEMM_SMEM (6 * TILE_E * 2)  // 2 buffers x 3 operands = 61440 bytes

__device__ __forceinline__ void mma_bf16(float* c, uint32_t a0, uint32_t a1,
                                         uint32_t a2, uint32_t a3,
                                         uint32_t b0, uint32_t b1) {
    asm volatile(
        "mma.sync.aligned.m16n8k16.row.col.f32.bf16.bf16.f32 "
        "{%0,%1,%2,%3}, {%4,%5,%6,%7}, {%8,%9}, {%0,%1,%2,%3};"
        : "+f"(c[0]), "+f"(c[1]), "+f"(c[2]), "+f"(c[3])
        : "r"(a0), "r"(a1), "r"(a2), "r"(a3), "r"(b0), "r"(b1));
}

__device__ __forceinline__ void cp_async16(uint32_t saddr, const void* gptr) {
    asm volatile("cp.async.cg.shared.global [%0], [%1], 16;"
                 :: "r"(saddr), "l"(gptr) : "memory");
}
#define CP_COMMIT() asm volatile("cp.async.commit_group;" ::: "memory")
#define CP_WAIT(n)  asm volatile("cp.async.wait_group %0;" :: "n"(n) : "memory")

__global__ __launch_bounds__(256) void gemm_mma_kernel(
    const __nv_bfloat16* __restrict__ A,
    const __nv_bfloat16* __restrict__ BH, const __nv_bfloat16* __restrict__ BL,
    const float* __restrict__ a_s, const float* __restrict__ a_d,
    __nv_bfloat16* __restrict__ Pb,
    float* __restrict__ als, float* __restrict__ ald,
    int M, int K) {
    extern __shared__ __align__(16) __nv_bfloat16 gsm[];
    __nv_bfloat16* sA  = gsm;                 // [2][128][LDK]
    __nv_bfloat16* sBh = gsm + 2 * TILE_E;
    __nv_bfloat16* sBl = gsm + 4 * TILE_E;
    uint32_t saA  = (uint32_t)__cvta_generic_to_shared(sA);
    uint32_t saBh = (uint32_t)__cvta_generic_to_shared(sBh);
    uint32_t saBl = (uint32_t)__cvta_generic_to_shared(sBl);

    int tid = threadIdx.x;
    int warp = tid >> 5, lane = tid & 31;
    int g = lane >> 2, tg = lane & 3;
    int warpM = warp & 3, warpN = warp >> 2;   // 4 x 2
    int bm0 = blockIdx.y * 128;
    int bn0 = blockIdx.x * 128;

    float acc[2][8][4];
#pragma unroll
    for (int i = 0; i < 2; i++)
#pragma unroll
        for (int j = 0; j < 8; j++)
#pragma unroll
            for (int q = 0; q < 4; q++) acc[i][j][q] = 0.f;

    int rowLoc = tid >> 1;
    int kq = (tid & 1) * 16;    // 16 bf16 = 32 bytes = 2 x cp.async per operand
    int grow = bm0 + rowLoc;
    int arow = grow < M ? grow : (M - 1);   // clamp: garbage rows feed discarded outputs only
    int nch = K / KCH;

    uint32_t dstOffBytes = (uint32_t)(rowLoc * LDK + kq) * 2;
    const __nv_bfloat16* apBase = A + (size_t)arow * K + kq;
    const __nv_bfloat16* bhBase = BH + (size_t)(bn0 + rowLoc) * K + kq;
    const __nv_bfloat16* blBase = BL + (size_t)(bn0 + rowLoc) * K + kq;

    // prologue: async-load chunk 0 into buffer 0
    {
        cp_async16(saA  + dstOffBytes,      apBase);
        cp_async16(saA  + dstOffBytes + 16, apBase + 8);
        cp_async16(saBh + dstOffBytes,      bhBase);
        cp_async16(saBh + dstOffBytes + 16, bhBase + 8);
        cp_async16(saBl + dstOffBytes,      blBase);
        cp_async16(saBl + dstOffBytes + 16, blBase + 8);
        CP_COMMIT();
    }

    for (int c = 0; c < nch; c++) {
        int buf = c & 1;
        if (c + 1 < nch) {
            int k0 = (c + 1) * KCH;
            uint32_t nb = ((c + 1) & 1) * (uint32_t)(TILE_E * 2) + dstOffBytes;
            cp_async16(saA  + nb,      apBase + k0);
            cp_async16(saA  + nb + 16, apBase + k0 + 8);
            cp_async16(saBh + nb,      bhBase + k0);
            cp_async16(saBh + nb + 16, bhBase + k0 + 8);
            cp_async16(saBl + nb,      blBase + k0);
            cp_async16(saBl + nb + 16, blBase + k0 + 8);
            CP_COMMIT();
            CP_WAIT(1);
        } else {
            CP_WAIT(0);
        }
        __syncthreads();

        const __nv_bfloat16* bA  = sA  + buf * TILE_E;
        const __nv_bfloat16* bBh = sBh + buf * TILE_E;
        const __nv_bfloat16* bBl = sBl + buf * TILE_E;
#pragma unroll
        for (int ks = 0; ks < 2; ks++) {
            int kb = ks * 16 + tg * 2;
            uint32_t ah[2][4];
#pragma unroll
            for (int mt = 0; mt < 2; mt++) {
                int r0 = warpM * 32 + mt * 16 + g;
                ah[mt][0] = *(const uint32_t*)&bA[r0 * LDK + kb];
                ah[mt][1] = *(const uint32_t*)&bA[(r0 + 8) * LDK + kb];
                ah[mt][2] = *(const uint32_t*)&bA[r0 * LDK + kb + 8];
                ah[mt][3] = *(const uint32_t*)&bA[(r0 + 8) * LDK + kb + 8];
            }
#pragma unroll
            for (int nt = 0; nt < 8; nt++) {
                int nc = warpN * 64 + nt * 8 + g;
                uint32_t bh0 = *(const uint32_t*)&bBh[nc * LDK + kb];
                uint32_t bh1 = *(const uint32_t*)&bBh[nc * LDK + kb + 8];
                uint32_t bl0 = *(const uint32_t*)&bBl[nc * LDK + kb];
                uint32_t bl1 = *(const uint32_t*)&bBl[nc * LDK + kb + 8];
#pragma unroll
                for (int mt = 0; mt < 2; mt++) {
                    mma_bf16(acc[mt][nt], ah[mt][0], ah[mt][1], ah[mt][2], ah[mt][3], bh0, bh1);
                    mma_bf16(acc[mt][nt], ah[mt][0], ah[mt][1], ah[mt][2], ah[mt][3], bl0, bl1);
                }
            }
        }
        __syncthreads();
    }

    // ---- epilogue: bf16 proj store + fused attention coefficients ----
    int head = (bn0 >> 6) + warpN;
    float asv[16], adv[16];
#pragma unroll
    for (int nt = 0; nt < 8; nt++) {
#pragma unroll
        for (int q = 0; q < 2; q++) {
            int gcol = bn0 + warpN * 64 + nt * 8 + tg * 2 + q;
            asv[nt * 2 + q] = a_s[gcol];
            adv[nt * 2 + q] = a_d[gcol];
        }
    }
#pragma unroll
    for (int mt = 0; mt < 2; mt++) {
        int r0 = bm0 + warpM * 32 + mt * 16 + g;
        float s_lo = 0.f, s_hi = 0.f, d_lo = 0.f, d_hi = 0.f;
#pragma unroll
        for (int nt = 0; nt < 8; nt++) {
            int col = bn0 + warpN * 64 + nt * 8 + tg * 2;
            __nv_bfloat162 p0 = __floats2bfloat162_rn(acc[mt][nt][0], acc[mt][nt][1]);
            __nv_bfloat162 p1 = __floats2bfloat162_rn(acc[mt][nt][2], acc[mt][nt][3]);
            if (r0 < M)     *(__nv_bfloat162*)(Pb + (size_t)r0 * DDIM + col) = p0;
            if (r0 + 8 < M) *(__nv_bfloat162*)(Pb + (size_t)(r0 + 8) * DDIM + col) = p1;
            s_lo += acc[mt][nt][0] * asv[nt * 2] + acc[mt][nt][1] * asv[nt * 2 + 1];
            s_hi += acc[mt][nt][2] * asv[nt * 2] + acc[mt][nt][3] * asv[nt * 2 + 1];
            d_lo += acc[mt][nt][0] * adv[nt * 2] + acc[mt][nt][1] * adv[nt * 2 + 1];
            d_hi += acc[mt][nt][2] * adv[nt * 2] + acc[mt][nt][3] * adv[nt * 2 + 1];
        }
#pragma unroll
        for (int o = 1; o < 4; o <<= 1) {
            s_lo += __shfl_xor_sync(0xFFFFFFFFu, s_lo, o);
            s_hi += __shfl_xor_sync(0xFFFFFFFFu, s_hi, o);
            d_lo += __shfl_xor_sync(0xFFFFFFFFu, d_lo, o);
            d_hi += __shfl_xor_sync(0xFFFFFFFFu, d_hi, o);
        }
        if (tg == 0) {
            if (r0 < M)     { als[r0 * HEADS + head] = s_lo; ald[r0 * HEADS + head] = d_lo; }
            if (r0 + 8 < M) { als[(r0 + 8) * HEADS + head] = s_hi; ald[(r0 + 8) * HEADS + head] = d_hi; }
        }
    }
}

// ---------------- encoder: 64-node tiles, weights cached in smem, bf16 out ----------------
#define ENC_SMEM ((8448 + 8192 + 4352) * 4)
__global__ __launch_bounds__(256) void encoder_kernel(
    const float* __restrict__ x,
    const float* __restrict__ w1, const float* __restrict__ b1,
    const float* __restrict__ gam, const float* __restrict__ bet,
    const float* __restrict__ w2, const float* __restrict__ b2,
    __nv_bfloat16* __restrict__ h0) {
    extern __shared__ float sm[];
    float* xs = sm;             // [64][132]
    float* ws = sm + 8448;      // [128][64] then [64][64]
    float* ys = sm + 16640;     // [64][68]
    int t = threadIdx.x;
    int n0 = blockIdx.x * 64;
    for (int i = t; i < 64 * 128; i += 256) {
        int nd = i >> 7, k = i & 127;
        int gn = n0 + nd;
        xs[nd * 132 + k] = (gn < N_NODES) ? x[(size_t)gn * 128 + k] : 0.f;
    }
    for (int i = t; i < 128 * 64; i += 256) ws[i] = w1[i];
    __syncthreads();
    int tx = t & 15, ty = t >> 4;
    float acc[4][4] = {};
#pragma unroll 4
    for (int k = 0; k < 128; k++) {
        float4 b4 = *(const float4*)&ws[k * 64 + tx * 4];
        float a0 = xs[(ty * 4 + 0) * 132 + k];
        float a1 = xs[(ty * 4 + 1) * 132 + k];
        float a2 = xs[(ty * 4 + 2) * 132 + k];
        float a3 = xs[(ty * 4 + 3) * 132 + k];
        acc[0][0] += a0 * b4.x; acc[0][1] += a0 * b4.y; acc[0][2] += a0 * b4.z; acc[0][3] += a0 * b4.w;
        acc[1][0] += a1 * b4.x; acc[1][1] += a1 * b4.y; acc[1][2] += a1 * b4.z; acc[1][3] += a1 * b4.w;
        acc[2][0] += a2 * b4.x; acc[2][1] += a2 * b4.y; acc[2][2] += a2 * b4.z; acc[2][3] += a2 * b4.w;
        acc[3][0] += a3 * b4.x; acc[3][1] += a3 * b4.y; acc[3][2] += a3 * b4.z; acc[3][3] += a3 * b4.w;
    }
    float4 b1v = *(const float4*)&b1[tx * 4];
#pragma unroll
    for (int i = 0; i < 4; i++)
        *(float4*)&ys[(ty * 4 + i) * 68 + tx * 4] = make_float4(
            acc[i][0] + b1v.x, acc[i][1] + b1v.y, acc[i][2] + b1v.z, acc[i][3] + b1v.w);
    __syncthreads();
    {
        int nd = t >> 2, q = t & 3;
        float s1 = 0.f, s2 = 0.f;
#pragma unroll
        for (int j = 0; j < 16; j++) {
            float v = ys[nd * 68 + q * 16 + j];
            s1 += v; s2 += v * v;
        }
        s1 += __shfl_xor_sync(0xFFFFFFFFu, s1, 1); s2 += __shfl_xor_sync(0xFFFFFFFFu, s2, 1);
        s1 += __shfl_xor_sync(0xFFFFFFFFu, s1, 2); s2 += __shfl_xor_sync(0xFFFFFFFFu, s2, 2);
        float m = s1 * (1.f / 64.f);
        float var = s2 * (1.f / 64.f) - m * m;
        float inv = rsqrtf(var + EPS_LN);
#pragma unroll
        for (int j = 0; j < 16; j++) {
            int col = q * 16 + j;
            float v = ys[nd * 68 + col];
            float z = gam[col] * (v - m) * inv + bet[col];
            ys[nd * 68 + col] = fmaxf(z, 0.f);
        }
    }
    __syncthreads();
    for (int i = t; i < 64 * 64; i += 256) ws[i] = w2[i];
    __syncthreads();
    float acc2[4][4] = {};
#pragma unroll 4
    for (int k = 0; k < 64; k++) {
        float4 b4 = *(const float4*)&ws[k * 64 + tx * 4];
        float a0 = ys[(ty * 4 + 0) * 68 + k];
        float a1 = ys[(ty * 4 + 1) * 68 + k];
        float a2 = ys[(ty * 4 + 2) * 68 + k];
        float a3 = ys[(ty * 4 + 3) * 68 + k];
        acc2[0][0] += a0 * b4.x; acc2[0][1] += a0 * b4.y; acc2[0][2] += a0 * b4.z; acc2[0][3] += a0 * b4.w;
        acc2[1][0] += a1 * b4.x; acc2[1][1] += a1 * b4.y; acc2[1][2] += a1 * b4.z; acc2[1][3] += a1 * b4.w;
        acc2[2][0] += a2 * b4.x; acc2[2][1] += a2 * b4.y; acc2[2][2] += a2 * b4.z; acc2[2][3] += a2 * b4.w;
        acc2[3][0] += a3 * b4.x; acc2[3][1] += a3 * b4.y; acc2[3][2] += a3 * b4.z; acc2[3][3] += a3 * b4.w;
    }
    float4 b2v = *(const float4*)&b2[tx * 4];
#pragma unroll
    for (int i = 0; i < 4; i++) {
        int gn = n0 + ty * 4 + i;
        if (gn < N_NODES) {
            __nv_bfloat162 q0 = __floats2bfloat162_rn(acc2[i][0] + b2v.x, acc2[i][1] + b2v.y);
            __nv_bfloat162 q1 = __floats2bfloat162_rn(acc2[i][2] + b2v.z, acc2[i][3] + b2v.w);
            *(__nv_bfloat162*)(h0 + (size_t)gn * 64 + tx * 4)     = q0;
            *(__nv_bfloat162*)(h0 + (size_t)gn * 64 + tx * 4 + 2) = q1;
        }
    }
}

// ---------------- CSR build (two-level scan) ----------------
__global__ void hist_kernel(const int* __restrict__ ei, int* __restrict__ deg) {
    int e = blockIdx.x * blockDim.x + threadIdx.x;
    if (e >= ETOT) return;
    int dst = (e < N_EDGES) ? ei[N_EDGES + e] : (e - N_EDGES);
    atomicAdd(&deg[dst], 1);
}

__global__ void degsum_kernel(const int* __restrict__ deg, int* __restrict__ bsum) {
    __shared__ int red[256];
    int b = blockIdx.x, t = threadIdx.x;
    int i = b * 256 + t;
    red[t] = (i < N_NODES) ? deg[i] : 0;
    __syncthreads();
    for (int o = 128; o; o >>= 1) { if (t < o) red[t] += red[t + o]; __syncthreads(); }
    if (t == 0) bsum[b] = red[0];
}

__global__ void scanb_kernel(const int* __restrict__ bsum, int* __restrict__ boff) {
    __shared__ int s[256];
    int t = threadIdx.x;
    int v0 = (t < NB_CSR) ? bsum[t] : 0;
    s[t] = v0;
    __syncthreads();
    for (int o = 1; o < 256; o <<= 1) {
        int v = (t >= o) ? s[t - o] : 0;
        __syncthreads();
        s[t] += v;
        __syncthreads();
    }
    if (t < NB_CSR) boff[t] = s[t] - v0;
}

__global__ void offsets_kernel(const int* __restrict__ deg, const int* __restrict__ boff,
                               int* __restrict__ off, int* __restrict__ cur) {
    __shared__ int s[256];
    int b = blockIdx.x, t = threadIdx.x;
    int i = b * 256 + t;
    int d = (i < N_NODES) ? deg[i] : 0;
    s[t] = d;
    __syncthreads();
    for (int o = 1; o < 256; o <<= 1) {
        int v = (t >= o) ? s[t - o] : 0;
        __syncthreads();
        s[t] += v;
        __syncthreads();
    }
    int excl = boff[b] + s[t] - d;
    if (i < N_NODES) { off[i] = excl; cur[i] = excl; }
    if (b == 0 && t == 0) off[N_NODES] = ETOT;
}

__global__ void scatter_kernel(const int* __restrict__ ei,
                               int* __restrict__ cur, int* __restrict__ adj) {
    int e = blockIdx.x * blockDim.x + threadIdx.x;
    if (e >= ETOT) return;
    int src, dst;
    if (e < N_EDGES) { src = ei[e]; dst = ei[N_EDGES + e]; }
    else             { src = dst = e - N_EDGES; }
    int pos = atomicAdd(&cur[dst], 1);
    adj[pos] = src;
}

// ---------------- fused GAT attention + aggregation + bias + ELU (warp per node) ----------------
__device__ __forceinline__ float lrelu(float v) { return v > 0.f ? v : 0.2f * v; }
__device__ __forceinline__ float pick4(float4 v, int h) {
    float lo = (h == 0) ? v.x : v.y;
    float hi = (h == 2) ? v.z : v.w;
    return (h < 2) ? lo : hi;
}

__global__ __launch_bounds__(256) void gat_fused_kernel(
    const int* __restrict__ off, const int* __restrict__ adj,
    const __nv_bfloat16* __restrict__ projb, const float* __restrict__ als,
    const float* __restrict__ ald, const float* __restrict__ bias,
    __nv_bfloat16* __restrict__ hout) {
    __shared__ float sE[8][CAP][4];
    __shared__ int   sS[8][CAP];
    int w = threadIdx.x >> 5, lane = threadIdx.x & 31;
    int n = blockIdx.x * 8 + w;
    if (n >= N_NODES) return;
    int e0 = off[n];
    int deg = off[n + 1] - e0;
    float4 aldn = ((const float4*)ald)[n];
    bool fits = (deg <= CAP);

    float4 mx = make_float4(-INFINITY, -INFINITY, -INFINITY, -INFINITY);
    for (int j = lane; j < deg; j += 32) {
        int s = adj[e0 + j];
        float4 a = ((const float4*)als)[s];
        float4 e;
        e.x = lrelu(a.x + aldn.x);
        e.y = lrelu(a.y + aldn.y);
        e.z = lrelu(a.z + aldn.z);
        e.w = lrelu(a.w + aldn.w);
        if (j < CAP) { sS[w][j] = s; *(float4*)sE[w][j] = e; }
        mx.x = fmaxf(mx.x, e.x); mx.y = fmaxf(mx.y, e.y);
        mx.z = fmaxf(mx.z, e.z); mx.w = fmaxf(mx.w, e.w);
    }
#pragma unroll
    for (int o = 16; o; o >>= 1) {
        mx.x = fmaxf(mx.x, __shfl_xor_sync(0xFFFFFFFFu, mx.x, o));
        mx.y = fmaxf(mx.y, __shfl_xor_sync(0xFFFFFFFFu, mx.y, o));
        mx.z = fmaxf(mx.z, __shfl_xor_sync(0xFFFFFFFFu, mx.z, o));
        mx.w = fmaxf(mx.w, __shfl_xor_sync(0xFFFFFFFFu, mx.w, o));
    }

    float4 sum = make_float4(0.f, 0.f, 0.f, 0.f);
    for (int j = lane; j < deg; j += 32) {
        float4 e;
        if (j < CAP) e = *(float4*)sE[w][j];
        else {
            int s = adj[e0 + j];
            float4 a = ((const float4*)als)[s];
            e.x = lrelu(a.x + aldn.x); e.y = lrelu(a.y + aldn.y);
            e.z = lrelu(a.z + aldn.z); e.w = lrelu(a.w + aldn.w);
        }
        float4 g;
        g.x = expf(e.x - mx.x); g.y = expf(e.y - mx.y);
        g.z = expf(e.z - mx.z); g.w = expf(e.w - mx.w);
        if (j < CAP) *(float4*)sE[w][j] = g;
        sum.x += g.x; sum.y += g.y; sum.z += g.z; sum.w += g.w;
    }
#pragma unroll
    for (int o = 16; o; o >>= 1) {
        sum.x += __shfl_xor_sync(0xFFFFFFFFu, sum.x, o);
        sum.y += __shfl_xor_sync(0xFFFFFFFFu, sum.y, o);
        sum.z += __shfl_xor_sync(0xFFFFFFFFu, sum.z, o);
        sum.w += __shfl_xor_sync(0xFFFFFFFFu, sum.w, o);
    }
    int hsel = lane >> 3;      // head for cols lane*8 .. lane*8+7
    float invh = 1.0f / (pick4(sum, hsel) + 1e-16f);
    float mxh  = pick4(mx, hsel);

    // pass 3: weighted aggregation
    float acc0 = 0.f, acc1 = 0.f, acc2 = 0.f, acc3 = 0.f;
    float acc4 = 0.f, acc5 = 0.f, acc6 = 0.f, acc7 = 0.f;

    if (fits) {
        // fast path: all edges cached in smem, no per-edge bounds checks
        int j = 0;
        for (; j + 4 <= deg; j += 4) {
            int s0 = sS[w][j], s1 = sS[w][j + 1], s2 = sS[w][j + 2], s3 = sS[w][j + 3];
            float g0 = sE[w][j][hsel], g1 = sE[w][j + 1][hsel];
            float g2 = sE[w][j + 2][hsel], g3 = sE[w][j + 3][hsel];
            uint4 p0 = ((const uint4*)(projb + (size_t)s0 * DDIM))[lane];
            uint4 p1 = ((const uint4*)(projb + (size_t)s1 * DDIM))[lane];
            uint4 p2 = ((const uint4*)(projb + (size_t)s2 * DDIM))[lane];
            uint4 p3 = ((const uint4*)(projb + (size_t)s3 * DDIM))[lane];
            float a0 = g0 * invh, a1 = g1 * invh, a2 = g2 * invh, a3 = g3 * invh;
            __nv_bfloat162 q;
            q = *(__nv_bfloat162*)&p0.x; acc0 += a0 * __bfloat162float(q.x); acc1 += a0 * __bfloat162float(q.y);
            q = *(__nv_bfloat162*)&p0.y; acc2 += a0 * __bfloat162float(q.x); acc3 += a0 * __bfloat162float(q.y);
            q = *(__nv_bfloat162*)&p0.z; acc4 += a0 * __bfloat162float(q.x); acc5 += a0 * __bfloat162float(q.y);
            q = *(__nv_bfloat162*)&p0.w; acc6 += a0 * __bfloat162float(q.x); acc7 += a0 * __bfloat162float(q.y);
            q = *(__nv_bfloat162*)&p1.x; acc0 += a1 * __bfloat162float(q.x); acc1 += a1 * __bfloat162float(q.y);
            q = *(__nv_bfloat162*)&p1.y; acc2 += a1 * __bfloat162float(q.x); acc3 += a1 * __bfloat162float(q.y);
            q = *(__nv_bfloat162*)&p1.z; acc4 += a1 * __bfloat162float(q.x); acc5 += a1 * __bfloat162float(q.y);
            q = *(__nv_bfloat162*)&p1.w; acc6 += a1 * __bfloat162float(q.x); acc7 += a1 * __bfloat162float(q.y);
            q = *(__nv_bfloat162*)&p2.x; acc0 += a2 * __bfloat162float(q.x); acc1 += a2 * __bfloat162float(q.y);
            q = *(__nv_bfloat162*)&p2.y; acc2 += a2 * __bfloat162float(q.x); acc3 += a2 * __bfloat162float(q.y);
            q = *(__nv_bfloat162*)&p2.z; acc4 += a2 * __bfloat162float(q.x); acc5 += a2 * __bfloat162float(q.y);
            q = *(__nv_bfloat162*)&p2.w; acc6 += a2 * __bfloat162float(q.x); acc7 += a2 * __bfloat162float(q.y);
            q = *(__nv_bfloat162*)&p3.x; acc0 += a3 * __bfloat162float(q.x); acc1 += a3 * __bfloat162float(q.y);
            q = *(__nv_bfloat162*)&p3.y; acc2 += a3 * __bfloat162float(q.x); acc3 += a3 * __bfloat162float(q.y);
            q = *(__nv_bfloat162*)&p3.z; acc4 += a3 * __bfloat162float(q.x); acc5 += a3 * __bfloat162float(q.y);
            q = *(__nv_bfloat162*)&p3.w; acc6 += a3 * __bfloat162float(q.x); acc7 += a3 * __bfloat162float(q.y);
        }
        for (; j < deg; j++) {
            int s0 = sS[w][j];
            float g0 = sE[w][j][hsel];
            uint4 p0 = ((const uint4*)(projb + (size_t)s0 * DDIM))[lane];
            float a0 = g0 * invh;
            __nv_bfloat162 q;
            q = *(__nv_bfloat162*)&p0.x; acc0 += a0 * __bfloat162float(q.x); acc1 += a0 * __bfloat162float(q.y);
            q = *(__nv_bfloat162*)&p0.y; acc2 += a0 * __bfloat162float(q.x); acc3 += a0 * __bfloat162float(q.y);
            q = *(__nv_bfloat162*)&p0.z; acc4 += a0 * __bfloat162float(q.x); acc5 += a0 * __bfloat162float(q.y);
            q = *(__nv_bfloat162*)&p0.w; acc6 += a0 * __bfloat162float(q.x); acc7 += a0 * __bfloat162float(q.y);
        }
    } else {
        // slow path (deg > CAP): recompute weights beyond the cache
        for (int j = 0; j < deg; j++) {
            int s0; float g0;
            if (j < CAP) { s0 = sS[w][j]; g0 = sE[w][j][hsel]; }
            else {
                s0 = adj[e0 + j];
                float4 a = ((const float4*)als)[s0];
                g0 = expf(lrelu(pick4(a, hsel) + pick4(aldn, hsel)) - mxh);
            }
            uint4 p0 = ((const uint4*)(projb + (size_t)s0 * DDIM))[lane];
            float a0 = g0 * invh;
            __nv_bfloat162 q;
            q = *(__nv_bfloat162*)&p0.x; acc0 += a0 * __bfloat162float(q.x); acc1 += a0 * __bfloat162float(q.y);
            q = *(__nv_bfloat162*)&p0.y; acc2 += a0 * __bfloat162float(q.x); acc3 += a0 * __bfloat162float(q.y);
            q = *(__nv_bfloat162*)&p0.z; acc4 += a0 * __bfloat162float(q.x); acc5 += a0 * __bfloat162float(q.y);
            q = *(__nv_bfloat162*)&p0.w; acc6 += a0 * __bfloat162float(q.x); acc7 += a0 * __bfloat162float(q.y);
        }
    }

    const float4* b4 = (const float4*)bias;
    float4 b0 = b4[lane * 2], b1 = b4[lane * 2 + 1];
    float v0 = acc0 + b0.x; v0 = v0 > 0.f ? v0 : expm1f(v0);
    float v1 = acc1 + b0.y; v1 = v1 > 0.f ? v1 : expm1f(v1);
    float v2 = acc2 + b0.z; v2 = v2 > 0.f ? v2 : expm1f(v2);
    float v3 = acc3 + b0.w; v3 = v3 > 0.f ? v3 : expm1f(v3);
    float v4 = acc4 + b1.x; v4 = v4 > 0.f ? v4 : expm1f(v4);
    float v5 = acc5 + b1.y; v5 = v5 > 0.f ? v5 : expm1f(v5);
    float v6 = acc6 + b1.z; v6 = v6 > 0.f ? v6 : expm1f(v6);
    float v7 = acc7 + b1.w; v7 = v7 > 0.f ? v7 : expm1f(v7);
    uint4 ov;
    *(__nv_bfloat162*)&ov.x = __floats2bfloat162_rn(v0, v1);
    *(__nv_bfloat162*)&ov.y = __floats2bfloat162_rn(v2, v3);
    *(__nv_bfloat162*)&ov.z = __floats2bfloat162_rn(v4, v5);
    *(__nv_bfloat162*)&ov.w = __floats2bfloat162_rn(v6, v7);
    ((uint4*)(hout + (size_t)n * DDIM))[lane] = ov;
}

// ---------------- mean pool over sorted batch (bf16 input) ----------------
#define PCHUNK 256
__global__ void pool_kernel(const __nv_bfloat16* __restrict__ h, const int* __restrict__ batch,
                            float* __restrict__ sums, float* __restrict__ cnt) {
    __shared__ int sb[PCHUNK];
    int n0 = blockIdx.x * PCHUNK;
    int n1 = min(N_NODES, n0 + PCHUNK);
    int cnt_local = n1 - n0;
    for (int i = threadIdx.x; i < cnt_local; i += blockDim.x) sb[i] = batch[n0 + i];
    __syncthreads();
    int t = threadIdx.x;
    float acc = 0.0f;
    int gp = sb[0];
    for (int i = 0; i < cnt_local; i++) {
        int g = sb[i];
        if (g != gp) { atomicAdd(&sums[gp * DDIM + t], acc); acc = 0.0f; gp = g; }
        acc += __bfloat162float(h[(size_t)(n0 + i) * DDIM + t]);
    }
    atomicAdd(&sums[gp * DDIM + t], acc);
    if (t == 0) {
        float c = 0.0f; gp = sb[0];
        for (int i = 0; i < cnt_local; i++) {
            int g = sb[i];
            if (g != gp) { atomicAdd(&cnt[gp], c); c = 0.0f; gp = g; }
            c += 1.0f;
        }
        atomicAdd(&cnt[gp], c);
    }
}

// ---------------- decoder ----------------
__global__ void decoder_kernel(const float* __restrict__ sums, const float* __restrict__ cnt,
                               const float* __restrict__ w1, const float* __restrict__ b1,
                               const float* __restrict__ gam, const float* __restrict__ bet,
                               const float* __restrict__ w2, const float* __restrict__ b2,
                               float* __restrict__ out) {
    __shared__ float p[DDIM];
    __shared__ float y[64];
    int t = threadIdx.x;
    for (int gr = 0; gr < NGRP; gr++) {
        float invc = 1.0f / fmaxf(cnt[gr], 1.0f);
        for (int i = t; i < DDIM; i += 64) p[i] = sums[gr * DDIM + i] * invc;
        __syncthreads();
        float acc = b1[t];
        for (int k = 0; k < DDIM; k++) acc += p[k] * w1[k * 64 + t];
        y[t] = acc;
        __syncthreads();
        float m = 0.0f;
        for (int k = 0; k < 64; k++) m += y[k];
        m *= (1.0f / 64.0f);
        float v = 0.0f;
        for (int k = 0; k < 64; k++) { float d = y[k] - m; v += d * d; }
        v *= (1.0f / 64.0f);
        float z = fmaxf(0.0f, gam[t] * (acc - m) * rsqrtf(v + EPS_LN) + bet[t]);
        __syncthreads();
        y[t] = z;
        __syncthreads();
        if (t < OUTF) {
            float o = b2[t];
            for (int k = 0; k < 64; k++) o += y[k] * w2[k * OUTF + t];
            out[gr * OUTF + t] = o;
        }
        __syncthreads();
    }
}

// ---------------- orchestration ----------------
extern "C" void kernel_launch(void* const* d_in, const int* in_sizes, int n_in,
                              void* d_out, int out_size) {
    const float* x      = (const float*)d_in[0];
    const int*   ei     = (const int*)d_in[1];
    const int*   batch  = (const int*)d_in[2];
    const float* enc_w1 = (const float*)d_in[3];
    const float* enc_b1 = (const float*)d_in[4];
    const float* enc_g  = (const float*)d_in[5];
    const float* enc_be = (const float*)d_in[6];
    const float* enc_w2 = (const float*)d_in[7];
    const float* enc_b2 = (const float*)d_in[8];
    const float* convW[3]  = { (const float*)d_in[9],  (const float*)d_in[13], (const float*)d_in[17] };
    const float* convAS[3] = { (const float*)d_in[10], (const float*)d_in[14], (const float*)d_in[18] };
    const float* convAD[3] = { (const float*)d_in[11], (const float*)d_in[15], (const float*)d_in[19] };
    const float* convB[3]  = { (const float*)d_in[12], (const float*)d_in[16], (const float*)d_in[20] };
    const float* dec_w1 = (const float*)d_in[21];
    const float* dec_b1 = (const float*)d_in[22];
    const float* dec_g  = (const float*)d_in[23];
    const float* dec_be = (const float*)d_in[24];
    const float* dec_w2 = (const float*)d_in[25];
    const float* dec_b2 = (const float*)d_in[26];

    float *als, *ald, *sums, *cnt;
    int *deg, *off, *cur, *adj, *bsum, *boff;
    __nv_bfloat16 *wthi, *wtlo, *projb, *bufA, *bufB;
    cudaGetSymbolAddress((void**)&bufA,  g_bufA);
    cudaGetSymbolAddress((void**)&bufB,  g_bufB);
    cudaGetSymbolAddress((void**)&projb, g_projb);
    cudaGetSymbolAddress((void**)&als,   g_als);
    cudaGetSymbolAddress((void**)&ald,   g_ald);
    cudaGetSymbolAddress((void**)&deg,   g_deg);
    cudaGetSymbolAddress((void**)&off,   g_off);
    cudaGetSymbolAddress((void**)&cur,   g_cur);
    cudaGetSymbolAddress((void**)&adj,   g_adj);
    cudaGetSymbolAddress((void**)&sums,  g_sums);
    cudaGetSymbolAddress((void**)&cnt,   g_cnt);
    cudaGetSymbolAddress((void**)&bsum,  g_bsum);
    cudaGetSymbolAddress((void**)&boff,  g_boff);
    cudaGetSymbolAddress((void**)&wthi,  g_wthi);
    cudaGetSymbolAddress((void**)&wtlo,  g_wtlo);

    cudaFuncSetAttribute(encoder_kernel, cudaFuncAttributeMaxDynamicSharedMemorySize, ENC_SMEM);
    cudaFuncSetAttribute(gemm_mma_kernel, cudaFuncAttributeMaxDynamicSharedMemorySize, GEMM_SMEM);

    // CSR build
    cudaMemsetAsync(deg, 0, N_NODES * sizeof(int));
    hist_kernel<<<(ETOT + 255) / 256, 256>>>(ei, deg);
    degsum_kernel<<<NB_CSR, 256>>>(deg, bsum);
    scanb_kernel<<<1, 256>>>(bsum, boff);
    offsets_kernel<<<NB_CSR, 256>>>(deg, boff, off, cur);
    scatter_kernel<<<(ETOT + 255) / 256, 256>>>(ei, cur, adj);

    // encoder -> bufA [N,64] bf16
    encoder_kernel<<<(N_NODES + 63) / 64, 256, ENC_SMEM>>>(
        x, enc_w1, enc_b1, enc_g, enc_be, enc_w2, enc_b2, bufA);

    __nv_bfloat16* hin = bufA;
    __nv_bfloat16* hout = bufB;
    int Fin = HID;
    for (int L = 0; L < 3; L++) {
        prep_wt_kernel<<<DDIM, 256>>>(convW[L], wthi, wtlo, Fin);
        dim3 ggrid(2, (N_NODES + 127) / 128);
        gemm_mma_kernel<<<ggrid, 256, GEMM_SMEM>>>(hin, wthi, wtlo, convAS[L], convAD[L],
                                                   projb, als, ald, N_NODES, Fin);
        gat_fused_kernel<<<(N_NODES + 7) / 8, 256>>>(off, adj, projb, als, ald, convB[L], hout);
        __nv_bfloat16* tmp = hin; hin = hout; hout = tmp;
        Fin = DDIM;
    }

    cudaMemsetAsync(sums, 0, NGRP * DDIM * sizeof(float));
    cudaMemsetAsync(cnt, 0, NGRP * sizeof(float));
    pool_kernel<<<(N_NODES + PCHUNK - 1) / PCHUNK, 256>>>(hin, batch, sums, cnt);
    decoder_kernel<<<1, 64>>>(sums, cnt, dec_w1, dec_b1, dec_g, dec_be, dec_w2, dec_b2,
                              (float*)d_out);
}

// round 13
// speedup vs baseline: 1.0041x; 1.0041x over previous
#include <cuda_runtime.h>
#include <cuda_bf16.h>
#include <math.h>
#include <stdint.h>

#define N_NODES 50000
#define N_EDGES 800000
#define ETOT    850000   // edges + self loops
#define HID     64
#define HEADS   4
#define DDIM    256      // HID*HEADS
#define OUTF    40
#define NGRP    8
#define EPS_LN  1e-5f
#define CAP     96

// ---------------- scratch (device globals; no dynamic alloc allowed) ----------------
__device__ __nv_bfloat16 g_bufA[(size_t)N_NODES * DDIM];
__device__ __nv_bfloat16 g_bufB[(size_t)N_NODES * DDIM];
__device__ __nv_bfloat16 g_projb[(size_t)N_NODES * DDIM];
__device__ float g_als[N_NODES * HEADS];
__device__ float g_ald[N_NODES * HEADS];
__device__ int   g_deg[N_NODES];
__device__ int   g_off[N_NODES + 1];
__device__ int   g_cur[N_NODES];
__device__ int   g_adj[ETOT];
__device__ float g_sums[NGRP * DDIM];
__device__ float g_cnt[NGRP];
__device__ __nv_bfloat16 g_wthi[DDIM * DDIM];   // W^T hi, [N=256][K]
__device__ __nv_bfloat16 g_wtlo[DDIM * DDIM];   // W^T lo
#define NB_CSR ((N_NODES + 255) / 256)
__device__ int g_bsum[NB_CSR];
__device__ int g_boff[NB_CSR];

// ---------------- W prep: transpose + bf16 hi/lo split ----------------
__global__ void prep_wt_kernel(const float* __restrict__ W,
                               __nv_bfloat16* __restrict__ hi,
                               __nv_bfloat16* __restrict__ lo, int K) {
    int n = blockIdx.x;                    // 0..255
    for (int k = threadIdx.x; k < K; k += blockDim.x) {
        float v = W[(size_t)k * DDIM + n];
        __nv_bfloat16 h = __float2bfloat16(v);
        float r = v - __bfloat162float(h);
        hi[(size_t)n * K + k] = h;
        lo[(size_t)n * K + k] = __float2bfloat16(r);
    }
}

// ---------------- bf16x2 HMMA GEMM + fused attcoef + bf16 proj output ----------------
#define KCH 32
#define LDK 40          // padded smem row stride (bf16 elems); 80 B = 16B multiple
#define TILE_E (128 * LDK)          // bf16 elements per operand buffer (5120)
#define GEMM_SMEM (6 * TILE_E * 2)  // 2 buffers x 3 operands = 61440 bytes

__device__ __forceinline__ void mma_bf16(float* c, uint32_t a0, uint32_t a1,
                                         uint32_t a2, uint32_t a3,
                                         uint32_t b0, uint32_t b1) {
    asm volatile(
        "mma.sync.aligned.m16n8k16.row.col.f32.bf16.bf16.f32 "
        "{%0,%1,%2,%3}, {%4,%5,%6,%7}, {%8,%9}, {%0,%1,%2,%3};"
        : "+f"(c[0]), "+f"(c[1]), "+f"(c[2]), "+f"(c[3])
        : "r"(a0), "r"(a1), "r"(a2), "r"(a3), "r"(b0), "r"(b1));
}

__device__ __forceinline__ void cp_async16(uint32_t saddr, const void* gptr) {
    asm volatile("cp.async.cg.shared.global [%0], [%1], 16;"
                 :: "r"(saddr), "l"(gptr) : "memory");
}
#define CP_COMMIT() asm volatile("cp.async.commit_group;" ::: "memory")
#define CP_WAIT(n)  asm volatile("cp.async.wait_group %0;" :: "n"(n) : "memory")

__global__ __launch_bounds__(256) void gemm_mma_kernel(
    const __nv_bfloat16* __restrict__ A,
    const __nv_bfloat16* __restrict__ BH, const __nv_bfloat16* __restrict__ BL,
    const float* __restrict__ a_s, const float* __restrict__ a_d,
    __nv_bfloat16* __restrict__ Pb,
    float* __restrict__ als, float* __restrict__ ald,
    int M, int K) {
    extern __shared__ __align__(16) __nv_bfloat16 gsm[];
    __nv_bfloat16* sA  = gsm;                 // [2][128][LDK]
    __nv_bfloat16* sBh = gsm + 2 * TILE_E;
    __nv_bfloat16* sBl = gsm + 4 * TILE_E;
    uint32_t saA  = (uint32_t)__cvta_generic_to_shared(sA);
    uint32_t saBh = (uint32_t)__cvta_generic_to_shared(sBh);
    uint32_t saBl = (uint32_t)__cvta_generic_to_shared(sBl);

    int tid = threadIdx.x;
    int warp = tid >> 5, lane = tid & 31;
    int g = lane >> 2, tg = lane & 3;
    int warpM = warp & 3, warpN = warp >> 2;   // 4 x 2
    int bm0 = blockIdx.y * 128;
    int bn0 = blockIdx.x * 128;

    float acc[2][8][4];
#pragma unroll
    for (int i = 0; i < 2; i++)
#pragma unroll
        for (int j = 0; j < 8; j++)
#pragma unroll
            for (int q = 0; q < 4; q++) acc[i][j][q] = 0.f;

    int rowLoc = tid >> 1;
    int kq = (tid & 1) * 16;    // 16 bf16 = 32 bytes = 2 x cp.async per operand
    int grow = bm0 + rowLoc;
    int arow = grow < M ? grow : (M - 1);   // clamp: garbage rows feed discarded outputs only
    int nch = K / KCH;

    uint32_t dstOffBytes = (uint32_t)(rowLoc * LDK + kq) * 2;
    const __nv_bfloat16* apBase = A + (size_t)arow * K + kq;
    const __nv_bfloat16* bhBase = BH + (size_t)(bn0 + rowLoc) * K + kq;
    const __nv_bfloat16* blBase = BL + (size_t)(bn0 + rowLoc) * K + kq;

    // prologue: async-load chunk 0 into buffer 0
    {
        cp_async16(saA  + dstOffBytes,      apBase);
        cp_async16(saA  + dstOffBytes + 16, apBase + 8);
        cp_async16(saBh + dstOffBytes,      bhBase);
        cp_async16(saBh + dstOffBytes + 16, bhBase + 8);
        cp_async16(saBl + dstOffBytes,      blBase);
        cp_async16(saBl + dstOffBytes + 16, blBase + 8);
        CP_COMMIT();
    }

    for (int c = 0; c < nch; c++) {
        int buf = c & 1;
        if (c + 1 < nch) {
            int k0 = (c + 1) * KCH;
            uint32_t nb = ((c + 1) & 1) * (uint32_t)(TILE_E * 2) + dstOffBytes;
            cp_async16(saA  + nb,      apBase + k0);
            cp_async16(saA  + nb + 16, apBase + k0 + 8);
            cp_async16(saBh + nb,      bhBase + k0);
            cp_async16(saBh + nb + 16, bhBase + k0 + 8);
            cp_async16(saBl + nb,      blBase + k0);
            cp_async16(saBl + nb + 16, blBase + k0 + 8);
            CP_COMMIT();
            CP_WAIT(1);
        } else {
            CP_WAIT(0);
        }
        __syncthreads();

        const __nv_bfloat16* bA  = sA  + buf * TILE_E;
        const __nv_bfloat16* bBh = sBh + buf * TILE_E;
        const __nv_bfloat16* bBl = sBl + buf * TILE_E;
#pragma unroll
        for (int ks = 0; ks < 2; ks++) {
            int kb = ks * 16 + tg * 2;
            uint32_t ah[2][4];
#pragma unroll
            for (int mt = 0; mt < 2; mt++) {
                int r0 = warpM * 32 + mt * 16 + g;
                ah[mt][0] = *(const uint32_t*)&bA[r0 * LDK + kb];
                ah[mt][1] = *(const uint32_t*)&bA[(r0 + 8) * LDK + kb];
                ah[mt][2] = *(const uint32_t*)&bA[r0 * LDK + kb + 8];
                ah[mt][3] = *(const uint32_t*)&bA[(r0 + 8) * LDK + kb + 8];
            }
#pragma unroll
            for (int nt = 0; nt < 8; nt++) {
                int nc = warpN * 64 + nt * 8 + g;
                uint32_t bh0 = *(const uint32_t*)&bBh[nc * LDK + kb];
                uint32_t bh1 = *(const uint32_t*)&bBh[nc * LDK + kb + 8];
                uint32_t bl0 = *(const uint32_t*)&bBl[nc * LDK + kb];
                uint32_t bl1 = *(const uint32_t*)&bBl[nc * LDK + kb + 8];
#pragma unroll
                for (int mt = 0; mt < 2; mt++) {
                    mma_bf16(acc[mt][nt], ah[mt][0], ah[mt][1], ah[mt][2], ah[mt][3], bh0, bh1);
                    mma_bf16(acc[mt][nt], ah[mt][0], ah[mt][1], ah[mt][2], ah[mt][3], bl0, bl1);
                }
            }
        }
        __syncthreads();
    }

    // ---- epilogue: bf16 proj store + fused attention coefficients ----
    int head = (bn0 >> 6) + warpN;
    float asv[16], adv[16];
#pragma unroll
    for (int nt = 0; nt < 8; nt++) {
#pragma unroll
        for (int q = 0; q < 2; q++) {
            int gcol = bn0 + warpN * 64 + nt * 8 + tg * 2 + q;
            asv[nt * 2 + q] = a_s[gcol];
            adv[nt * 2 + q] = a_d[gcol];
        }
    }
#pragma unroll
    for (int mt = 0; mt < 2; mt++) {
        int r0 = bm0 + warpM * 32 + mt * 16 + g;
        float s_lo = 0.f, s_hi = 0.f, d_lo = 0.f, d_hi = 0.f;
#pragma unroll
        for (int nt = 0; nt < 8; nt++) {
            int col = bn0 + warpN * 64 + nt * 8 + tg * 2;
            __nv_bfloat162 p0 = __floats2bfloat162_rn(acc[mt][nt][0], acc[mt][nt][1]);
            __nv_bfloat162 p1 = __floats2bfloat162_rn(acc[mt][nt][2], acc[mt][nt][3]);
            if (r0 < M)     *(__nv_bfloat162*)(Pb + (size_t)r0 * DDIM + col) = p0;
            if (r0 + 8 < M) *(__nv_bfloat162*)(Pb + (size_t)(r0 + 8) * DDIM + col) = p1;
            s_lo += acc[mt][nt][0] * asv[nt * 2] + acc[mt][nt][1] * asv[nt * 2 + 1];
            s_hi += acc[mt][nt][2] * asv[nt * 2] + acc[mt][nt][3] * asv[nt * 2 + 1];
            d_lo += acc[mt][nt][0] * adv[nt * 2] + acc[mt][nt][1] * adv[nt * 2 + 1];
            d_hi += acc[mt][nt][2] * adv[nt * 2] + acc[mt][nt][3] * adv[nt * 2 + 1];
        }
#pragma unroll
        for (int o = 1; o < 4; o <<= 1) {
            s_lo += __shfl_xor_sync(0xFFFFFFFFu, s_lo, o);
            s_hi += __shfl_xor_sync(0xFFFFFFFFu, s_hi, o);
            d_lo += __shfl_xor_sync(0xFFFFFFFFu, d_lo, o);
            d_hi += __shfl_xor_sync(0xFFFFFFFFu, d_hi, o);
        }
        if (tg == 0) {
            if (r0 < M)     { als[r0 * HEADS + head] = s_lo; ald[r0 * HEADS + head] = d_lo; }
            if (r0 + 8 < M) { als[(r0 + 8) * HEADS + head] = s_hi; ald[(r0 + 8) * HEADS + head] = d_hi; }
        }
    }
}

// ---------------- encoder: 64-node tiles, weights cached in smem, bf16 out ----------------
#define ENC_SMEM ((8448 + 8192 + 4352) * 4)
__global__ __launch_bounds__(256) void encoder_kernel(
    const float* __restrict__ x,
    const float* __restrict__ w1, const float* __restrict__ b1,
    const float* __restrict__ gam, const float* __restrict__ bet,
    const float* __restrict__ w2, const float* __restrict__ b2,
    __nv_bfloat16* __restrict__ h0) {
    extern __shared__ float sm[];
    float* xs = sm;             // [64][132]
    float* ws = sm + 8448;      // [128][64] then [64][64]
    float* ys = sm + 16640;     // [64][68]
    int t = threadIdx.x;
    int n0 = blockIdx.x * 64;
    for (int i = t; i < 64 * 128; i += 256) {
        int nd = i >> 7, k = i & 127;
        int gn = n0 + nd;
        xs[nd * 132 + k] = (gn < N_NODES) ? x[(size_t)gn * 128 + k] : 0.f;
    }
    for (int i = t; i < 128 * 64; i += 256) ws[i] = w1[i];
    __syncthreads();
    int tx = t & 15, ty = t >> 4;
    float acc[4][4] = {};
#pragma unroll 4
    for (int k = 0; k < 128; k++) {
        float4 b4 = *(const float4*)&ws[k * 64 + tx * 4];
        float a0 = xs[(ty * 4 + 0) * 132 + k];
        float a1 = xs[(ty * 4 + 1) * 132 + k];
        float a2 = xs[(ty * 4 + 2) * 132 + k];
        float a3 = xs[(ty * 4 + 3) * 132 + k];
        acc[0][0] += a0 * b4.x; acc[0][1] += a0 * b4.y; acc[0][2] += a0 * b4.z; acc[0][3] += a0 * b4.w;
        acc[1][0] += a1 * b4.x; acc[1][1] += a1 * b4.y; acc[1][2] += a1 * b4.z; acc[1][3] += a1 * b4.w;
        acc[2][0] += a2 * b4.x; acc[2][1] += a2 * b4.y; acc[2][2] += a2 * b4.z; acc[2][3] += a2 * b4.w;
        acc[3][0] += a3 * b4.x; acc[3][1] += a3 * b4.y; acc[3][2] += a3 * b4.z; acc[3][3] += a3 * b4.w;
    }
    float4 b1v = *(const float4*)&b1[tx * 4];
#pragma unroll
    for (int i = 0; i < 4; i++)
        *(float4*)&ys[(ty * 4 + i) * 68 + tx * 4] = make_float4(
            acc[i][0] + b1v.x, acc[i][1] + b1v.y, acc[i][2] + b1v.z, acc[i][3] + b1v.w);
    __syncthreads();
    {
        int nd = t >> 2, q = t & 3;
        float s1 = 0.f, s2 = 0.f;
#pragma unroll
        for (int j = 0; j < 16; j++) {
            float v = ys[nd * 68 + q * 16 + j];
            s1 += v; s2 += v * v;
        }
        s1 += __shfl_xor_sync(0xFFFFFFFFu, s1, 1); s2 += __shfl_xor_sync(0xFFFFFFFFu, s2, 1);
        s1 += __shfl_xor_sync(0xFFFFFFFFu, s1, 2); s2 += __shfl_xor_sync(0xFFFFFFFFu, s2, 2);
        float m = s1 * (1.f / 64.f);
        float var = s2 * (1.f / 64.f) - m * m;
        float inv = rsqrtf(var + EPS_LN);
#pragma unroll
        for (int j = 0; j < 16; j++) {
            int col = q * 16 + j;
            float v = ys[nd * 68 + col];
            float z = gam[col] * (v - m) * inv + bet[col];
            ys[nd * 68 + col] = fmaxf(z, 0.f);
        }
    }
    __syncthreads();
    for (int i = t; i < 64 * 64; i += 256) ws[i] = w2[i];
    __syncthreads();
    float acc2[4][4] = {};
#pragma unroll 4
    for (int k = 0; k < 64; k++) {
        float4 b4 = *(const float4*)&ws[k * 64 + tx * 4];
        float a0 = ys[(ty * 4 + 0) * 68 + k];
        float a1 = ys[(ty * 4 + 1) * 68 + k];
        float a2 = ys[(ty * 4 + 2) * 68 + k];
        float a3 = ys[(ty * 4 + 3) * 68 + k];
        acc2[0][0] += a0 * b4.x; acc2[0][1] += a0 * b4.y; acc2[0][2] += a0 * b4.z; acc2[0][3] += a0 * b4.w;
        acc2[1][0] += a1 * b4.x; acc2[1][1] += a1 * b4.y; acc2[1][2] += a1 * b4.z; acc2[1][3] += a1 * b4.w;
        acc2[2][0] += a2 * b4.x; acc2[2][1] += a2 * b4.y; acc2[2][2] += a2 * b4.z; acc2[2][3] += a2 * b4.w;
        acc2[3][0] += a3 * b4.x; acc2[3][1] += a3 * b4.y; acc2[3][2] += a3 * b4.z; acc2[3][3] += a3 * b4.w;
    }
    float4 b2v = *(const float4*)&b2[tx * 4];
#pragma unroll
    for (int i = 0; i < 4; i++) {
        int gn = n0 + ty * 4 + i;
        if (gn < N_NODES) {
            __nv_bfloat162 q0 = __floats2bfloat162_rn(acc2[i][0] + b2v.x, acc2[i][1] + b2v.y);
            __nv_bfloat162 q1 = __floats2bfloat162_rn(acc2[i][2] + b2v.z, acc2[i][3] + b2v.w);
            *(__nv_bfloat162*)(h0 + (size_t)gn * 64 + tx * 4)     = q0;
            *(__nv_bfloat162*)(h0 + (size_t)gn * 64 + tx * 4 + 2) = q1;
        }
    }
}

// ---------------- CSR build (two-level scan) ----------------
__global__ void hist_kernel(const int* __restrict__ ei, int* __restrict__ deg) {
    int e = blockIdx.x * blockDim.x + threadIdx.x;
    if (e >= ETOT) return;
    int dst = (e < N_EDGES) ? ei[N_EDGES + e] : (e - N_EDGES);
    atomicAdd(&deg[dst], 1);
}

__global__ void degsum_kernel(const int* __restrict__ deg, int* __restrict__ bsum) {
    __shared__ int red[256];
    int b = blockIdx.x, t = threadIdx.x;
    int i = b * 256 + t;
    red[t] = (i < N_NODES) ? deg[i] : 0;
    __syncthreads();
    for (int o = 128; o; o >>= 1) { if (t < o) red[t] += red[t + o]; __syncthreads(); }
    if (t == 0) bsum[b] = red[0];
}

__global__ void scanb_kernel(const int* __restrict__ bsum, int* __restrict__ boff) {
    __shared__ int s[256];
    int t = threadIdx.x;
    int v0 = (t < NB_CSR) ? bsum[t] : 0;
    s[t] = v0;
    __syncthreads();
    for (int o = 1; o < 256; o <<= 1) {
        int v = (t >= o) ? s[t - o] : 0;
        __syncthreads();
        s[t] += v;
        __syncthreads();
    }
    if (t < NB_CSR) boff[t] = s[t] - v0;
}

__global__ void offsets_kernel(const int* __restrict__ deg, const int* __restrict__ boff,
                               int* __restrict__ off, int* __restrict__ cur) {
    __shared__ int s[256];
    int b = blockIdx.x, t = threadIdx.x;
    int i = b * 256 + t;
    int d = (i < N_NODES) ? deg[i] : 0;
    s[t] = d;
    __syncthreads();
    for (int o = 1; o < 256; o <<= 1) {
        int v = (t >= o) ? s[t - o] : 0;
        __syncthreads();
        s[t] += v;
        __syncthreads();
    }
    int excl = boff[b] + s[t] - d;
    if (i < N_NODES) { off[i] = excl; cur[i] = excl; }
    if (b == 0 && t == 0) off[N_NODES] = ETOT;
}

__global__ void scatter_kernel(const int* __restrict__ ei,
                               int* __restrict__ cur, int* __restrict__ adj) {
    int e = blockIdx.x * blockDim.x + threadIdx.x;
    if (e >= ETOT) return;
    int src, dst;
    if (e < N_EDGES) { src = ei[e]; dst = ei[N_EDGES + e]; }
    else             { src = dst = e - N_EDGES; }
    int pos = atomicAdd(&cur[dst], 1);
    adj[pos] = src;
}

// ---------------- fused GAT attention + aggregation + bias + ELU (warp per node) ----------------
__device__ __forceinline__ float lrelu(float v) { return v > 0.f ? v : 0.2f * v; }
__device__ __forceinline__ float pick4(float4 v, int h) {
    float lo = (h == 0) ? v.x : v.y;
    float hi = (h == 2) ? v.z : v.w;
    return (h < 2) ? lo : hi;
}

__global__ __launch_bounds__(256) void gat_fused_kernel(
    const int* __restrict__ off, const int* __restrict__ adj,
    const __nv_bfloat16* __restrict__ projb, const float* __restrict__ als,
    const float* __restrict__ ald, const float* __restrict__ bias,
    __nv_bfloat16* __restrict__ hout) {
    __shared__ float sE[8][CAP][4];
    __shared__ int   sS[8][CAP];
    int w = threadIdx.x >> 5, lane = threadIdx.x & 31;
    int n = blockIdx.x * 8 + w;
    if (n >= N_NODES) return;
    int e0 = off[n];
    int deg = off[n + 1] - e0;
    float4 aldn = ((const float4*)ald)[n];

    float4 mx = make_float4(-INFINITY, -INFINITY, -INFINITY, -INFINITY);
    for (int j = lane; j < deg; j += 32) {
        int s = adj[e0 + j];
        float4 a = ((const float4*)als)[s];
        float4 e;
        e.x = lrelu(a.x + aldn.x);
        e.y = lrelu(a.y + aldn.y);
        e.z = lrelu(a.z + aldn.z);
        e.w = lrelu(a.w + aldn.w);
        if (j < CAP) { sS[w][j] = s; *(float4*)sE[w][j] = e; }
        mx.x = fmaxf(mx.x, e.x); mx.y = fmaxf(mx.y, e.y);
        mx.z = fmaxf(mx.z, e.z); mx.w = fmaxf(mx.w, e.w);
    }
#pragma unroll
    for (int o = 16; o; o >>= 1) {
        mx.x = fmaxf(mx.x, __shfl_xor_sync(0xFFFFFFFFu, mx.x, o));
        mx.y = fmaxf(mx.y, __shfl_xor_sync(0xFFFFFFFFu, mx.y, o));
        mx.z = fmaxf(mx.z, __shfl_xor_sync(0xFFFFFFFFu, mx.z, o));
        mx.w = fmaxf(mx.w, __shfl_xor_sync(0xFFFFFFFFu, mx.w, o));
    }

    float4 sum = make_float4(0.f, 0.f, 0.f, 0.f);
    for (int j = lane; j < deg; j += 32) {
        float4 e;
        if (j < CAP) e = *(float4*)sE[w][j];
        else {
            int s = adj[e0 + j];
            float4 a = ((const float4*)als)[s];
            e.x = lrelu(a.x + aldn.x); e.y = lrelu(a.y + aldn.y);
            e.z = lrelu(a.z + aldn.z); e.w = lrelu(a.w + aldn.w);
        }
        float4 g;
        g.x = expf(e.x - mx.x); g.y = expf(e.y - mx.y);
        g.z = expf(e.z - mx.z); g.w = expf(e.w - mx.w);
        if (j < CAP) *(float4*)sE[w][j] = g;
        sum.x += g.x; sum.y += g.y; sum.z += g.z; sum.w += g.w;
    }
#pragma unroll
    for (int o = 16; o; o >>= 1) {
        sum.x += __shfl_xor_sync(0xFFFFFFFFu, sum.x, o);
        sum.y += __shfl_xor_sync(0xFFFFFFFFu, sum.y, o);
        sum.z += __shfl_xor_sync(0xFFFFFFFFu, sum.z, o);
        sum.w += __shfl_xor_sync(0xFFFFFFFFu, sum.w, o);
    }
    int hsel = lane >> 3;      // head for cols lane*8 .. lane*8+7
    float invh = 1.0f / (pick4(sum, hsel) + 1e-16f);
    float mxh  = pick4(mx, hsel);

    // pass 3: weighted aggregation, unrolled x2 for MLP
    float acc0 = 0.f, acc1 = 0.f, acc2 = 0.f, acc3 = 0.f;
    float acc4 = 0.f, acc5 = 0.f, acc6 = 0.f, acc7 = 0.f;
    int j = 0;
    for (; j + 2 <= deg; j += 2) {
        int s0, s1; float g0, g1;
        if (j < CAP) { s0 = sS[w][j]; g0 = sE[w][j][hsel]; }
        else {
            s0 = adj[e0 + j];
            float4 a = ((const float4*)als)[s0];
            g0 = expf(lrelu(pick4(a, hsel) + pick4(aldn, hsel)) - mxh);
        }
        if (j + 1 < CAP) { s1 = sS[w][j + 1]; g1 = sE[w][j + 1][hsel]; }
        else {
            s1 = adj[e0 + j + 1];
            float4 a = ((const float4*)als)[s1];
            g1 = expf(lrelu(pick4(a, hsel) + pick4(aldn, hsel)) - mxh);
        }
        uint4 p0 = ((const uint4*)(projb + (size_t)s0 * DDIM))[lane];
        uint4 p1 = ((const uint4*)(projb + (size_t)s1 * DDIM))[lane];
        float a0 = g0 * invh, a1 = g1 * invh;
        __nv_bfloat162 q;
        q = *(__nv_bfloat162*)&p0.x; acc0 += a0 * __bfloat162float(q.x); acc1 += a0 * __bfloat162float(q.y);
        q = *(__nv_bfloat162*)&p0.y; acc2 += a0 * __bfloat162float(q.x); acc3 += a0 * __bfloat162float(q.y);
        q = *(__nv_bfloat162*)&p0.z; acc4 += a0 * __bfloat162float(q.x); acc5 += a0 * __bfloat162float(q.y);
        q = *(__nv_bfloat162*)&p0.w; acc6 += a0 * __bfloat162float(q.x); acc7 += a0 * __bfloat162float(q.y);
        q = *(__nv_bfloat162*)&p1.x; acc0 += a1 * __bfloat162float(q.x); acc1 += a1 * __bfloat162float(q.y);
        q = *(__nv_bfloat162*)&p1.y; acc2 += a1 * __bfloat162float(q.x); acc3 += a1 * __bfloat162float(q.y);
        q = *(__nv_bfloat162*)&p1.z; acc4 += a1 * __bfloat162float(q.x); acc5 += a1 * __bfloat162float(q.y);
        q = *(__nv_bfloat162*)&p1.w; acc6 += a1 * __bfloat162float(q.x); acc7 += a1 * __bfloat162float(q.y);
    }
    if (j < deg) {
        int s0; float g0;
        if (j < CAP) { s0 = sS[w][j]; g0 = sE[w][j][hsel]; }
        else {
            s0 = adj[e0 + j];
            float4 a = ((const float4*)als)[s0];
            g0 = expf(lrelu(pick4(a, hsel) + pick4(aldn, hsel)) - mxh);
        }
        uint4 p0 = ((const uint4*)(projb + (size_t)s0 * DDIM))[lane];
        float a0 = g0 * invh;
        __nv_bfloat162 q;
        q = *(__nv_bfloat162*)&p0.x; acc0 += a0 * __bfloat162float(q.x); acc1 += a0 * __bfloat162float(q.y);
        q = *(__nv_bfloat162*)&p0.y; acc2 += a0 * __bfloat162float(q.x); acc3 += a0 * __bfloat162float(q.y);
        q = *(__nv_bfloat162*)&p0.z; acc4 += a0 * __bfloat162float(q.x); acc5 += a0 * __bfloat162float(q.y);
        q = *(__nv_bfloat162*)&p0.w; acc6 += a0 * __bfloat162float(q.x); acc7 += a0 * __bfloat162float(q.y);
    }

    const float4* b4 = (const float4*)bias;
    float4 b0 = b4[lane * 2], b1 = b4[lane * 2 + 1];
    float v0 = acc0 + b0.x; v0 = v0 > 0.f ? v0 : expm1f(v0);
    float v1 = acc1 + b0.y; v1 = v1 > 0.f ? v1 : expm1f(v1);
    float v2 = acc2 + b0.z; v2 = v2 > 0.f ? v2 : expm1f(v2);
    float v3 = acc3 + b0.w; v3 = v3 > 0.f ? v3 : expm1f(v3);
    float v4 = acc4 + b1.x; v4 = v4 > 0.f ? v4 : expm1f(v4);
    float v5 = acc5 + b1.y; v5 = v5 > 0.f ? v5 : expm1f(v5);
    float v6 = acc6 + b1.z; v6 = v6 > 0.f ? v6 : expm1f(v6);
    float v7 = acc7 + b1.w; v7 = v7 > 0.f ? v7 : expm1f(v7);
    uint4 ov;
    *(__nv_bfloat162*)&ov.x = __floats2bfloat162_rn(v0, v1);
    *(__nv_bfloat162*)&ov.y = __floats2bfloat162_rn(v2, v3);
    *(__nv_bfloat162*)&ov.z = __floats2bfloat162_rn(v4, v5);
    *(__nv_bfloat162*)&ov.w = __floats2bfloat162_rn(v6, v7);
    ((uint4*)(hout + (size_t)n * DDIM))[lane] = ov;
}

// ---------------- mean pool over sorted batch (bf16 input) ----------------
#define PCHUNK 256
__global__ void pool_kernel(const __nv_bfloat16* __restrict__ h, const int* __restrict__ batch,
                            float* __restrict__ sums, float* __restrict__ cnt) {
    __shared__ int sb[PCHUNK];
    int n0 = blockIdx.x * PCHUNK;
    int n1 = min(N_NODES, n0 + PCHUNK);
    int cnt_local = n1 - n0;
    for (int i = threadIdx.x; i < cnt_local; i += blockDim.x) sb[i] = batch[n0 + i];
    __syncthreads();
    int t = threadIdx.x;
    float acc = 0.0f;
    int gp = sb[0];
    for (int i = 0; i < cnt_local; i++) {
        int g = sb[i];
        if (g != gp) { atomicAdd(&sums[gp * DDIM + t], acc); acc = 0.0f; gp = g; }
        acc += __bfloat162float(h[(size_t)(n0 + i) * DDIM + t]);
    }
    atomicAdd(&sums[gp * DDIM + t], acc);
    if (t == 0) {
        float c = 0.0f; gp = sb[0];
        for (int i = 0; i < cnt_local; i++) {
            int g = sb[i];
            if (g != gp) { atomicAdd(&cnt[gp], c); c = 0.0f; gp = g; }
            c += 1.0f;
        }
        atomicAdd(&cnt[gp], c);
    }
}

// ---------------- decoder ----------------
__global__ void decoder_kernel(const float* __restrict__ sums, const float* __restrict__ cnt,
                               const float* __restrict__ w1, const float* __restrict__ b1,
                               const float* __restrict__ gam, const float* __restrict__ bet,
                               const float* __restrict__ w2, const float* __restrict__ b2,
                               float* __restrict__ out) {
    __shared__ float p[DDIM];
    __shared__ float y[64];
    int t = threadIdx.x;
    for (int gr = 0; gr < NGRP; gr++) {
        float invc = 1.0f / fmaxf(cnt[gr], 1.0f);
        for (int i = t; i < DDIM; i += 64) p[i] = sums[gr * DDIM + i] * invc;
        __syncthreads();
        float acc = b1[t];
        for (int k = 0; k < DDIM; k++) acc += p[k] * w1[k * 64 + t];
        y[t] = acc;
        __syncthreads();
        float m = 0.0f;
        for (int k = 0; k < 64; k++) m += y[k];
        m *= (1.0f / 64.0f);
        float v = 0.0f;
        for (int k = 0; k < 64; k++) { float d = y[k] - m; v += d * d; }
        v *= (1.0f / 64.0f);
        float z = fmaxf(0.0f, gam[t] * (acc - m) * rsqrtf(v + EPS_LN) + bet[t]);
        __syncthreads();
        y[t] = z;
        __syncthreads();
        if (t < OUTF) {
            float o = b2[t];
            for (int k = 0; k < 64; k++) o += y[k] * w2[k * OUTF + t];
            out[gr * OUTF + t] = o;
        }
        __syncthreads();
    }
}

// ---------------- orchestration ----------------
extern "C" void kernel_launch(void* const* d_in, const int* in_sizes, int n_in,
                              void* d_out, int out_size) {
    const float* x      = (const float*)d_in[0];
    const int*   ei     = (const int*)d_in[1];
    const int*   batch  = (const int*)d_in[2];
    const float* enc_w1 = (const float*)d_in[3];
    const float* enc_b1 = (const float*)d_in[4];
    const float* enc_g  = (const float*)d_in[5];
    const float* enc_be = (const float*)d_in[6];
    const float* enc_w2 = (const float*)d_in[7];
    const float* enc_b2 = (const float*)d_in[8];
    const float* convW[3]  = { (const float*)d_in[9],  (const float*)d_in[13], (const float*)d_in[17] };
    const float* convAS[3] = { (const float*)d_in[10], (const float*)d_in[14], (const float*)d_in[18] };
    const float* convAD[3] = { (const float*)d_in[11], (const float*)d_in[15], (const float*)d_in[19] };
    const float* convB[3]  = { (const float*)d_in[12], (const float*)d_in[16], (const float*)d_in[20] };
    const float* dec_w1 = (const float*)d_in[21];
    const float* dec_b1 = (const float*)d_in[22];
    const float* dec_g  = (const float*)d_in[23];
    const float* dec_be = (const float*)d_in[24];
    const float* dec_w2 = (const float*)d_in[25];
    const float* dec_b2 = (const float*)d_in[26];

    float *als, *ald, *sums, *cnt;
    int *deg, *off, *cur, *adj, *bsum, *boff;
    __nv_bfloat16 *wthi, *wtlo, *projb, *bufA, *bufB;
    cudaGetSymbolAddress((void**)&bufA,  g_bufA);
    cudaGetSymbolAddress((void**)&bufB,  g_bufB);
    cudaGetSymbolAddress((void**)&projb, g_projb);
    cudaGetSymbolAddress((void**)&als,   g_als);
    cudaGetSymbolAddress((void**)&ald,   g_ald);
    cudaGetSymbolAddress((void**)&deg,   g_deg);
    cudaGetSymbolAddress((void**)&off,   g_off);
    cudaGetSymbolAddress((void**)&cur,   g_cur);
    cudaGetSymbolAddress((void**)&adj,   g_adj);
    cudaGetSymbolAddress((void**)&sums,  g_sums);
    cudaGetSymbolAddress((void**)&cnt,   g_cnt);
    cudaGetSymbolAddress((void**)&bsum,  g_bsum);
    cudaGetSymbolAddress((void**)&boff,  g_boff);
    cudaGetSymbolAddress((void**)&wthi,  g_wthi);
    cudaGetSymbolAddress((void**)&wtlo,  g_wtlo);

    cudaFuncSetAttribute(encoder_kernel, cudaFuncAttributeMaxDynamicSharedMemorySize, ENC_SMEM);
    cudaFuncSetAttribute(gemm_mma_kernel, cudaFuncAttributeMaxDynamicSharedMemorySize, GEMM_SMEM);

    // CSR build
    cudaMemsetAsync(deg, 0, N_NODES * sizeof(int));
    hist_kernel<<<(ETOT + 255) / 256, 256>>>(ei, deg);
    degsum_kernel<<<NB_CSR, 256>>>(deg, bsum);
    scanb_kernel<<<1, 256>>>(bsum, boff);
    offsets_kernel<<<NB_CSR, 256>>>(deg, boff, off, cur);
    scatter_kernel<<<(ETOT + 255) / 256, 256>>>(ei, cur, adj);

    // encoder -> bufA [N,64] bf16
    encoder_kernel<<<(N_NODES + 63) / 64, 256, ENC_SMEM>>>(
        x, enc_w1, enc_b1, enc_g, enc_be, enc_w2, enc_b2, bufA);

    __nv_bfloat16* hin = bufA;
    __nv_bfloat16* hout = bufB;
    int Fin = HID;
    for (int L = 0; L < 3; L++) {
        prep_wt_kernel<<<DDIM, 256>>>(convW[L], wthi, wtlo, Fin);
        dim3 ggrid(2, (N_NODES + 127) / 128);
        gemm_mma_kernel<<<ggrid, 256, GEMM_SMEM>>>(hin, wthi, wtlo, convAS[L], convAD[L],
                                                   projb, als, ald, N_NODES, Fin);
        gat_fused_kernel<<<(N_NODES + 7) / 8, 256>>>(off, adj, projb, als, ald, convB[L], hout);
        __nv_bfloat16* tmp = hin; hin = hout; hout = tmp;
        Fin = DDIM;
    }

    cudaMemsetAsync(sums, 0, NGRP * DDIM * sizeof(float));
    cudaMemsetAsync(cnt, 0, NGRP * sizeof(float));
    pool_kernel<<<(N_NODES + PCHUNK - 1) / PCHUNK, 256>>>(hin, batch, sums, cnt);
    decoder_kernel<<<1, 64>>>(sums, cnt, dec_w1, dec_b1, dec_g, dec_be, dec_w2, dec_b2,
                              (float*)d_out);
}

// round 14
// speedup vs baseline: 1.0120x; 1.0078x over previous
#include <cuda_runtime.h>
#include <cuda_bf16.h>
#include <math.h>
#include <stdint.h>

#define N_NODES 50000
#define N_EDGES 800000
#define ETOT    850000   // edges + self loops
#define HID     64
#define HEADS   4
#define DDIM    256      // HID*HEADS
#define OUTF    40
#define NGRP    8
#define EPS_LN  1e-5f
#define CAP     96

// ---------------- scratch (device globals; no dynamic alloc allowed) ----------------
__device__ __nv_bfloat16 g_bufA[(size_t)N_NODES * DDIM];
__device__ __nv_bfloat16 g_bufB[(size_t)N_NODES * DDIM];
__device__ __nv_bfloat16 g_projb[(size_t)N_NODES * DDIM];
__device__ float g_als[N_NODES * HEADS];
__device__ float g_ald[N_NODES * HEADS];
__device__ int   g_deg[N_NODES];
__device__ int   g_off[N_NODES + 1];
__device__ int   g_cur[N_NODES];
__device__ int   g_adj[ETOT];
__device__ float g_sums[NGRP * DDIM];
__device__ float g_cnt[NGRP];
__device__ __nv_bfloat16 g_wthi[DDIM * DDIM];   // W^T hi, [N=256][K]
__device__ __nv_bfloat16 g_wtlo[DDIM * DDIM];   // W^T lo
#define NB_CSR ((N_NODES + 255) / 256)
__device__ int g_bsum[NB_CSR];
__device__ int g_boff[NB_CSR];

// ---------------- W prep: transpose + bf16 hi/lo split ----------------
__global__ void prep_wt_kernel(const float* __restrict__ W,
                               __nv_bfloat16* __restrict__ hi,
                               __nv_bfloat16* __restrict__ lo, int K) {
    int n = blockIdx.x;                    // 0..255
    for (int k = threadIdx.x; k < K; k += blockDim.x) {
        float v = W[(size_t)k * DDIM + n];
        __nv_bfloat16 h = __float2bfloat16(v);
        float r = v - __bfloat162float(h);
        hi[(size_t)n * K + k] = h;
        lo[(size_t)n * K + k] = __float2bfloat16(r);
    }
}

// ---------------- bf16x2 HMMA GEMM + fused attcoef + bf16 proj output ----------------
#define KCH 32
#define LDK 40          // padded smem row stride (bf16 elems); 80 B = 16B multiple
#define TILE_E (128 * LDK)          // bf16 elements per operand buffer (5120)
#define GEMM_SMEM (6 * TILE_E * 2)  // 2 buffers x 3 operands = 61440 bytes

__device__ __forceinline__ void mma_bf16(float* c, uint32_t a0, uint32_t a1,
                                         uint32_t a2, uint32_t a3,
                                         uint32_t b0, uint32_t b1) {
    asm volatile(
        "mma.sync.aligned.m16n8k16.row.col.f32.bf16.bf16.f32 "
        "{%0,%1,%2,%3}, {%4,%5,%6,%7}, {%8,%9}, {%0,%1,%2,%3};"
        : "+f"(c[0]), "+f"(c[1]), "+f"(c[2]), "+f"(c[3])
        : "r"(a0), "r"(a1), "r"(a2), "r"(a3), "r"(b0), "r"(b1));
}

__device__ __forceinline__ void ldsm_x4(uint32_t& d0, uint32_t& d1,
                                        uint32_t& d2, uint32_t& d3, uint32_t saddr) {
    asm volatile("ldmatrix.sync.aligned.m8n8.x4.shared.b16 {%0,%1,%2,%3}, [%4];"
                 : "=r"(d0), "=r"(d1), "=r"(d2), "=r"(d3) : "r"(saddr));
}
__device__ __forceinline__ void ldsm_x2(uint32_t& d0, uint32_t& d1, uint32_t saddr) {
    asm volatile("ldmatrix.sync.aligned.m8n8.x2.shared.b16 {%0,%1}, [%2];"
                 : "=r"(d0), "=r"(d1) : "r"(saddr));
}

__device__ __forceinline__ void cp_async16(uint32_t saddr, const void* gptr) {
    asm volatile("cp.async.cg.shared.global [%0], [%1], 16;"
                 :: "r"(saddr), "l"(gptr) : "memory");
}
#define CP_COMMIT() asm volatile("cp.async.commit_group;" ::: "memory")
#define CP_WAIT(n)  asm volatile("cp.async.wait_group %0;" :: "n"(n) : "memory")

__global__ __launch_bounds__(256) void gemm_mma_kernel(
    const __nv_bfloat16* __restrict__ A,
    const __nv_bfloat16* __restrict__ BH, const __nv_bfloat16* __restrict__ BL,
    const float* __restrict__ a_s, const float* __restrict__ a_d,
    __nv_bfloat16* __restrict__ Pb,
    float* __restrict__ als, float* __restrict__ ald,
    int M, int K) {
    extern __shared__ __align__(16) __nv_bfloat16 gsm[];
    __nv_bfloat16* sA  = gsm;                 // [2][128][LDK]
    __nv_bfloat16* sBh = gsm + 2 * TILE_E;
    __nv_bfloat16* sBl = gsm + 4 * TILE_E;
    uint32_t saA  = (uint32_t)__cvta_generic_to_shared(sA);
    uint32_t saBh = (uint32_t)__cvta_generic_to_shared(sBh);
    uint32_t saBl = (uint32_t)__cvta_generic_to_shared(sBl);

    int tid = threadIdx.x;
    int warp = tid >> 5, lane = tid & 31;
    int g = lane >> 2, tg = lane & 3;
    int warpM = warp & 3, warpN = warp >> 2;   // 4 x 2
    int bm0 = blockIdx.y * 128;
    int bn0 = blockIdx.x * 128;

    float acc[2][8][4];
#pragma unroll
    for (int i = 0; i < 2; i++)
#pragma unroll
        for (int j = 0; j < 8; j++)
#pragma unroll
            for (int q = 0; q < 4; q++) acc[i][j][q] = 0.f;

    int rowLoc = tid >> 1;
    int kq = (tid & 1) * 16;    // 16 bf16 = 32 bytes = 2 x cp.async per operand
    int grow = bm0 + rowLoc;
    int arow = grow < M ? grow : (M - 1);   // clamp: garbage rows feed discarded outputs only
    int nch = K / KCH;

    // ldmatrix lane-geometry (constants per thread)
    int aRow = ((lane >> 3) & 1) * 8 + (lane & 7);   // row-in-16 for A tile t=lane>>3
    int aK   = (lane >> 4) * 8;                      // k-offset 0 or 8 (tiles 2,3)
    int bN   = lane & 7;                             // B row (n within 8-group)
    int bK   = ((lane >> 3) & 1) * 8;                // B k-offset (lanes 0-7:0, 8-15:8)

    uint32_t dstOffBytes = (uint32_t)(rowLoc * LDK + kq) * 2;
    const __nv_bfloat16* apBase = A + (size_t)arow * K + kq;
    const __nv_bfloat16* bhBase = BH + (size_t)(bn0 + rowLoc) * K + kq;
    const __nv_bfloat16* blBase = BL + (size_t)(bn0 + rowLoc) * K + kq;

    // prologue: async-load chunk 0 into buffer 0
    {
        cp_async16(saA  + dstOffBytes,      apBase);
        cp_async16(saA  + dstOffBytes + 16, apBase + 8);
        cp_async16(saBh + dstOffBytes,      bhBase);
        cp_async16(saBh + dstOffBytes + 16, bhBase + 8);
        cp_async16(saBl + dstOffBytes,      blBase);
        cp_async16(saBl + dstOffBytes + 16, blBase + 8);
        CP_COMMIT();
    }

    for (int c = 0; c < nch; c++) {
        int buf = c & 1;
        if (c + 1 < nch) {
            int k0 = (c + 1) * KCH;
            uint32_t nb = ((c + 1) & 1) * (uint32_t)(TILE_E * 2) + dstOffBytes;
            cp_async16(saA  + nb,      apBase + k0);
            cp_async16(saA  + nb + 16, apBase + k0 + 8);
            cp_async16(saBh + nb,      bhBase + k0);
            cp_async16(saBh + nb + 16, bhBase + k0 + 8);
            cp_async16(saBl + nb,      blBase + k0);
            cp_async16(saBl + nb + 16, blBase + k0 + 8);
            CP_COMMIT();
            CP_WAIT(1);
        } else {
            CP_WAIT(0);
        }
        __syncthreads();

        uint32_t aBase  = saA  + buf * (uint32_t)(TILE_E * 2);
        uint32_t bhBs   = saBh + buf * (uint32_t)(TILE_E * 2);
        uint32_t blBs   = saBl + buf * (uint32_t)(TILE_E * 2);
#pragma unroll
        for (int ks = 0; ks < 2; ks++) {
            uint32_t ah[2][4];
#pragma unroll
            for (int mt = 0; mt < 2; mt++) {
                int m = warpM * 32 + mt * 16 + aRow;
                uint32_t addr = aBase + (uint32_t)((m * LDK + ks * 16 + aK) * 2);
                ldsm_x4(ah[mt][0], ah[mt][1], ah[mt][2], ah[mt][3], addr);
            }
            uint32_t boff = (uint32_t)(((warpN * 64 + bN) * LDK + ks * 16 + bK) * 2);
#pragma unroll
            for (int nt = 0; nt < 8; nt++) {
                uint32_t bo = boff + (uint32_t)(nt * 8 * LDK * 2);
                uint32_t bh0, bh1, bl0, bl1;
                ldsm_x2(bh0, bh1, bhBs + bo);
                ldsm_x2(bl0, bl1, blBs + bo);
#pragma unroll
                for (int mt = 0; mt < 2; mt++) {
                    mma_bf16(acc[mt][nt], ah[mt][0], ah[mt][1], ah[mt][2], ah[mt][3], bh0, bh1);
                    mma_bf16(acc[mt][nt], ah[mt][0], ah[mt][1], ah[mt][2], ah[mt][3], bl0, bl1);
                }
            }
        }
        __syncthreads();
    }

    // ---- epilogue: bf16 proj store + fused attention coefficients ----
    int head = (bn0 >> 6) + warpN;
    float asv[16], adv[16];
#pragma unroll
    for (int nt = 0; nt < 8; nt++) {
#pragma unroll
        for (int q = 0; q < 2; q++) {
            int gcol = bn0 + warpN * 64 + nt * 8 + tg * 2 + q;
            asv[nt * 2 + q] = a_s[gcol];
            adv[nt * 2 + q] = a_d[gcol];
        }
    }
#pragma unroll
    for (int mt = 0; mt < 2; mt++) {
        int r0 = bm0 + warpM * 32 + mt * 16 + g;
        float s_lo = 0.f, s_hi = 0.f, d_lo = 0.f, d_hi = 0.f;
#pragma unroll
        for (int nt = 0; nt < 8; nt++) {
            int col = bn0 + warpN * 64 + nt * 8 + tg * 2;
            __nv_bfloat162 p0 = __floats2bfloat162_rn(acc[mt][nt][0], acc[mt][nt][1]);
            __nv_bfloat162 p1 = __floats2bfloat162_rn(acc[mt][nt][2], acc[mt][nt][3]);
            if (r0 < M)     *(__nv_bfloat162*)(Pb + (size_t)r0 * DDIM + col) = p0;
            if (r0 + 8 < M) *(__nv_bfloat162*)(Pb + (size_t)(r0 + 8) * DDIM + col) = p1;
            s_lo += acc[mt][nt][0] * asv[nt * 2] + acc[mt][nt][1] * asv[nt * 2 + 1];
            s_hi += acc[mt][nt][2] * asv[nt * 2] + acc[mt][nt][3] * asv[nt * 2 + 1];
            d_lo += acc[mt][nt][0] * adv[nt * 2] + acc[mt][nt][1] * adv[nt * 2 + 1];
            d_hi += acc[mt][nt][2] * adv[nt * 2] + acc[mt][nt][3] * adv[nt * 2 + 1];
        }
#pragma unroll
        for (int o = 1; o < 4; o <<= 1) {
            s_lo += __shfl_xor_sync(0xFFFFFFFFu, s_lo, o);
            s_hi += __shfl_xor_sync(0xFFFFFFFFu, s_hi, o);
            d_lo += __shfl_xor_sync(0xFFFFFFFFu, d_lo, o);
            d_hi += __shfl_xor_sync(0xFFFFFFFFu, d_hi, o);
        }
        if (tg == 0) {
            if (r0 < M)     { als[r0 * HEADS + head] = s_lo; ald[r0 * HEADS + head] = d_lo; }
            if (r0 + 8 < M) { als[(r0 + 8) * HEADS + head] = s_hi; ald[(r0 + 8) * HEADS + head] = d_hi; }
        }
    }
}

// ---------------- encoder: 64-node tiles, weights cached in smem, bf16 out ----------------
#define ENC_SMEM ((8448 + 8192 + 4352) * 4)
__global__ __launch_bounds__(256) void encoder_kernel(
    const float* __restrict__ x,
    const float* __restrict__ w1, const float* __restrict__ b1,
    const float* __restrict__ gam, const float* __restrict__ bet,
    const float* __restrict__ w2, const float* __restrict__ b2,
    __nv_bfloat16* __restrict__ h0) {
    extern __shared__ float sm[];
    float* xs = sm;             // [64][132]
    float* ws = sm + 8448;      // [128][64] then [64][64]
    float* ys = sm + 16640;     // [64][68]
    int t = threadIdx.x;
    int n0 = blockIdx.x * 64;
    for (int i = t; i < 64 * 128; i += 256) {
        int nd = i >> 7, k = i & 127;
        int gn = n0 + nd;
        xs[nd * 132 + k] = (gn < N_NODES) ? x[(size_t)gn * 128 + k] : 0.f;
    }
    for (int i = t; i < 128 * 64; i += 256) ws[i] = w1[i];
    __syncthreads();
    int tx = t & 15, ty = t >> 4;
    float acc[4][4] = {};
#pragma unroll 4
    for (int k = 0; k < 128; k++) {
        float4 b4 = *(const float4*)&ws[k * 64 + tx * 4];
        float a0 = xs[(ty * 4 + 0) * 132 + k];
        float a1 = xs[(ty * 4 + 1) * 132 + k];
        float a2 = xs[(ty * 4 + 2) * 132 + k];
        float a3 = xs[(ty * 4 + 3) * 132 + k];
        acc[0][0] += a0 * b4.x; acc[0][1] += a0 * b4.y; acc[0][2] += a0 * b4.z; acc[0][3] += a0 * b4.w;
        acc[1][0] += a1 * b4.x; acc[1][1] += a1 * b4.y; acc[1][2] += a1 * b4.z; acc[1][3] += a1 * b4.w;
        acc[2][0] += a2 * b4.x; acc[2][1] += a2 * b4.y; acc[2][2] += a2 * b4.z; acc[2][3] += a2 * b4.w;
        acc[3][0] += a3 * b4.x; acc[3][1] += a3 * b4.y; acc[3][2] += a3 * b4.z; acc[3][3] += a3 * b4.w;
    }
    float4 b1v = *(const float4*)&b1[tx * 4];
#pragma unroll
    for (int i = 0; i < 4; i++)
        *(float4*)&ys[(ty * 4 + i) * 68 + tx * 4] = make_float4(
            acc[i][0] + b1v.x, acc[i][1] + b1v.y, acc[i][2] + b1v.z, acc[i][3] + b1v.w);
    __syncthreads();
    {
        int nd = t >> 2, q = t & 3;
        float s1 = 0.f, s2 = 0.f;
#pragma unroll
        for (int j = 0; j < 16; j++) {
            float v = ys[nd * 68 + q * 16 + j];
            s1 += v; s2 += v * v;
        }
        s1 += __shfl_xor_sync(0xFFFFFFFFu, s1, 1); s2 += __shfl_xor_sync(0xFFFFFFFFu, s2, 1);
        s1 += __shfl_xor_sync(0xFFFFFFFFu, s1, 2); s2 += __shfl_xor_sync(0xFFFFFFFFu, s2, 2);
        float m = s1 * (1.f / 64.f);
        float var = s2 * (1.f / 64.f) - m * m;
        float inv = rsqrtf(var + EPS_LN);
#pragma unroll
        for (int j = 0; j < 16; j++) {
            int col = q * 16 + j;
            float v = ys[nd * 68 + col];
            float z = gam[col] * (v - m) * inv + bet[col];
            ys[nd * 68 + col] = fmaxf(z, 0.f);
        }
    }
    __syncthreads();
    for (int i = t; i < 64 * 64; i += 256) ws[i] = w2[i];
    __syncthreads();
    float acc2[4][4] = {};
#pragma unroll 4
    for (int k = 0; k < 64; k++) {
        float4 b4 = *(const float4*)&ws[k * 64 + tx * 4];
        float a0 = ys[(ty * 4 + 0) * 68 + k];
        float a1 = ys[(ty * 4 + 1) * 68 + k];
        float a2 = ys[(ty * 4 + 2) * 68 + k];
        float a3 = ys[(ty * 4 + 3) * 68 + k];
        acc2[0][0] += a0 * b4.x; acc2[0][1] += a0 * b4.y; acc2[0][2] += a0 * b4.z; acc2[0][3] += a0 * b4.w;
        acc2[1][0] += a1 * b4.x; acc2[1][1] += a1 * b4.y; acc2[1][2] += a1 * b4.z; acc2[1][3] += a1 * b4.w;
        acc2[2][0] += a2 * b4.x; acc2[2][1] += a2 * b4.y; acc2[2][2] += a2 * b4.z; acc2[2][3] += a2 * b4.w;
        acc2[3][0] += a3 * b4.x; acc2[3][1] += a3 * b4.y; acc2[3][2] += a3 * b4.z; acc2[3][3] += a3 * b4.w;
    }
    float4 b2v = *(const float4*)&b2[tx * 4];
#pragma unroll
    for (int i = 0; i < 4; i++) {
        int gn = n0 + ty * 4 + i;
        if (gn < N_NODES) {
            __nv_bfloat162 q0 = __floats2bfloat162_rn(acc2[i][0] + b2v.x, acc2[i][1] + b2v.y);
            __nv_bfloat162 q1 = __floats2bfloat162_rn(acc2[i][2] + b2v.z, acc2[i][3] + b2v.w);
            *(__nv_bfloat162*)(h0 + (size_t)gn * 64 + tx * 4)     = q0;
            *(__nv_bfloat162*)(h0 + (size_t)gn * 64 + tx * 4 + 2) = q1;
        }
    }
}

// ---------------- CSR build (two-level scan) ----------------
__global__ void hist_kernel(const int* __restrict__ ei, int* __restrict__ deg) {
    int e = blockIdx.x * blockDim.x + threadIdx.x;
    if (e >= ETOT) return;
    int dst = (e < N_EDGES) ? ei[N_EDGES + e] : (e - N_EDGES);
    atomicAdd(&deg[dst], 1);
}

__global__ void degsum_kernel(const int* __restrict__ deg, int* __restrict__ bsum) {
    __shared__ int red[256];
    int b = blockIdx.x, t = threadIdx.x;
    int i = b * 256 + t;
    red[t] = (i < N_NODES) ? deg[i] : 0;
    __syncthreads();
    for (int o = 128; o; o >>= 1) { if (t < o) red[t] += red[t + o]; __syncthreads(); }
    if (t == 0) bsum[b] = red[0];
}

__global__ void scanb_kernel(const int* __restrict__ bsum, int* __restrict__ boff) {
    __shared__ int s[256];
    int t = threadIdx.x;
    int v0 = (t < NB_CSR) ? bsum[t] : 0;
    s[t] = v0;
    __syncthreads();
    for (int o = 1; o < 256; o <<= 1) {
        int v = (t >= o) ? s[t - o] : 0;
        __syncthreads();
        s[t] += v;
        __syncthreads();
    }
    if (t < NB_CSR) boff[t] = s[t] - v0;
}

__global__ void offsets_kernel(const int* __restrict__ deg, const int* __restrict__ boff,
                               int* __restrict__ off, int* __restrict__ cur) {
    __shared__ int s[256];
    int b = blockIdx.x, t = threadIdx.x;
    int i = b * 256 + t;
    int d = (i < N_NODES) ? deg[i] : 0;
    s[t] = d;
    __syncthreads();
    for (int o = 1; o < 256; o <<= 1) {
        int v = (t >= o) ? s[t - o] : 0;
        __syncthreads();
        s[t] += v;
        __syncthreads();
    }
    int excl = boff[b] + s[t] - d;
    if (i < N_NODES) { off[i] = excl; cur[i] = excl; }
    if (b == 0 && t == 0) off[N_NODES] = ETOT;
}

__global__ void scatter_kernel(const int* __restrict__ ei,
                               int* __restrict__ cur, int* __restrict__ adj) {
    int e = blockIdx.x * blockDim.x + threadIdx.x;
    if (e >= ETOT) return;
    int src, dst;
    if (e < N_EDGES) { src = ei[e]; dst = ei[N_EDGES + e]; }
    else             { src = dst = e - N_EDGES; }
    int pos = atomicAdd(&cur[dst], 1);
    adj[pos] = src;
}

// ---------------- fused GAT attention + aggregation + bias + ELU (warp per node) ----------------
__device__ __forceinline__ float lrelu(float v) { return v > 0.f ? v : 0.2f * v; }
__device__ __forceinline__ float pick4(float4 v, int h) {
    float lo = (h == 0) ? v.x : v.y;
    float hi = (h == 2) ? v.z : v.w;
    return (h < 2) ? lo : hi;
}

__global__ __launch_bounds__(256) void gat_fused_kernel(
    const int* __restrict__ off, const int* __restrict__ adj,
    const __nv_bfloat16* __restrict__ projb, const float* __restrict__ als,
    const float* __restrict__ ald, const float* __restrict__ bias,
    __nv_bfloat16* __restrict__ hout) {
    __shared__ float sE[8][CAP][4];
    __shared__ int   sS[8][CAP];
    int w = threadIdx.x >> 5, lane = threadIdx.x & 31;
    int n = blockIdx.x * 8 + w;
    if (n >= N_NODES) return;
    int e0 = off[n];
    int deg = off[n + 1] - e0;
    float4 aldn = ((const float4*)ald)[n];

    float4 mx = make_float4(-INFINITY, -INFINITY, -INFINITY, -INFINITY);
    for (int j = lane; j < deg; j += 32) {
        int s = adj[e0 + j];
        float4 a = ((const float4*)als)[s];
        float4 e;
        e.x = lrelu(a.x + aldn.x);
        e.y = lrelu(a.y + aldn.y);
        e.z = lrelu(a.z + aldn.z);
        e.w = lrelu(a.w + aldn.w);
        if (j < CAP) { sS[w][j] = s; *(float4*)sE[w][j] = e; }
        mx.x = fmaxf(mx.x, e.x); mx.y = fmaxf(mx.y, e.y);
        mx.z = fmaxf(mx.z, e.z); mx.w = fmaxf(mx.w, e.w);
    }
#pragma unroll
    for (int o = 16; o; o >>= 1) {
        mx.x = fmaxf(mx.x, __shfl_xor_sync(0xFFFFFFFFu, mx.x, o));
        mx.y = fmaxf(mx.y, __shfl_xor_sync(0xFFFFFFFFu, mx.y, o));
        mx.z = fmaxf(mx.z, __shfl_xor_sync(0xFFFFFFFFu, mx.z, o));
        mx.w = fmaxf(mx.w, __shfl_xor_sync(0xFFFFFFFFu, mx.w, o));
    }

    float4 sum = make_float4(0.f, 0.f, 0.f, 0.f);
    for (int j = lane; j < deg; j += 32) {
        float4 e;
        if (j < CAP) e = *(float4*)sE[w][j];
        else {
            int s = adj[e0 + j];
            float4 a = ((const float4*)als)[s];
            e.x = lrelu(a.x + aldn.x); e.y = lrelu(a.y + aldn.y);
            e.z = lrelu(a.z + aldn.z); e.w = lrelu(a.w + aldn.w);
        }
        float4 g;
        g.x = expf(e.x - mx.x); g.y = expf(e.y - mx.y);
        g.z = expf(e.z - mx.z); g.w = expf(e.w - mx.w);
        if (j < CAP) *(float4*)sE[w][j] = g;
        sum.x += g.x; sum.y += g.y; sum.z += g.z; sum.w += g.w;
    }
#pragma unroll
    for (int o = 16; o; o >>= 1) {
        sum.x += __shfl_xor_sync(0xFFFFFFFFu, sum.x, o);
        sum.y += __shfl_xor_sync(0xFFFFFFFFu, sum.y, o);
        sum.z += __shfl_xor_sync(0xFFFFFFFFu, sum.z, o);
        sum.w += __shfl_xor_sync(0xFFFFFFFFu, sum.w, o);
    }
    int hsel = lane >> 3;      // head for cols lane*8 .. lane*8+7
    float invh = 1.0f / (pick4(sum, hsel) + 1e-16f);
    float mxh  = pick4(mx, hsel);

    // pass 3: weighted aggregation, unrolled x2 for MLP
    float acc0 = 0.f, acc1 = 0.f, acc2 = 0.f, acc3 = 0.f;
    float acc4 = 0.f, acc5 = 0.f, acc6 = 0.f, acc7 = 0.f;
    int j = 0;
    for (; j + 2 <= deg; j += 2) {
        int s0, s1; float g0, g1;
        if (j < CAP) { s0 = sS[w][j]; g0 = sE[w][j][hsel]; }
        else {
            s0 = adj[e0 + j];
            float4 a = ((const float4*)als)[s0];
            g0 = expf(lrelu(pick4(a, hsel) + pick4(aldn, hsel)) - mxh);
        }
        if (j + 1 < CAP) { s1 = sS[w][j + 1]; g1 = sE[w][j + 1][hsel]; }
        else {
            s1 = adj[e0 + j + 1];
            float4 a = ((const float4*)als)[s1];
            g1 = expf(lrelu(pick4(a, hsel) + pick4(aldn, hsel)) - mxh);
        }
        uint4 p0 = ((const uint4*)(projb + (size_t)s0 * DDIM))[lane];
        uint4 p1 = ((const uint4*)(projb + (size_t)s1 * DDIM))[lane];
        float a0 = g0 * invh, a1 = g1 * invh;
        __nv_bfloat162 q;
        q = *(__nv_bfloat162*)&p0.x; acc0 += a0 * __bfloat162float(q.x); acc1 += a0 * __bfloat162float(q.y);
        q = *(__nv_bfloat162*)&p0.y; acc2 += a0 * __bfloat162float(q.x); acc3 += a0 * __bfloat162float(q.y);
        q = *(__nv_bfloat162*)&p0.z; acc4 += a0 * __bfloat162float(q.x); acc5 += a0 * __bfloat162float(q.y);
        q = *(__nv_bfloat162*)&p0.w; acc6 += a0 * __bfloat162float(q.x); acc7 += a0 * __bfloat162float(q.y);
        q = *(__nv_bfloat162*)&p1.x; acc0 += a1 * __bfloat162float(q.x); acc1 += a1 * __bfloat162float(q.y);
        q = *(__nv_bfloat162*)&p1.y; acc2 += a1 * __bfloat162float(q.x); acc3 += a1 * __bfloat162float(q.y);
        q = *(__nv_bfloat162*)&p1.z; acc4 += a1 * __bfloat162float(q.x); acc5 += a1 * __bfloat162float(q.y);
        q = *(__nv_bfloat162*)&p1.w; acc6 += a1 * __bfloat162float(q.x); acc7 += a1 * __bfloat162float(q.y);
    }
    if (j < deg) {
        int s0; float g0;
        if (j < CAP) { s0 = sS[w][j]; g0 = sE[w][j][hsel]; }
        else {
            s0 = adj[e0 + j];
            float4 a = ((const float4*)als)[s0];
            g0 = expf(lrelu(pick4(a, hsel) + pick4(aldn, hsel)) - mxh);
        }
        uint4 p0 = ((const uint4*)(projb + (size_t)s0 * DDIM))[lane];
        float a0 = g0 * invh;
        __nv_bfloat162 q;
        q = *(__nv_bfloat162*)&p0.x; acc0 += a0 * __bfloat162float(q.x); acc1 += a0 * __bfloat162float(q.y);
        q = *(__nv_bfloat162*)&p0.y; acc2 += a0 * __bfloat162float(q.x); acc3 += a0 * __bfloat162float(q.y);
        q = *(__nv_bfloat162*)&p0.z; acc4 += a0 * __bfloat162float(q.x); acc5 += a0 * __bfloat162float(q.y);
        q = *(__nv_bfloat162*)&p0.w; acc6 += a0 * __bfloat162float(q.x); acc7 += a0 * __bfloat162float(q.y);
    }

    const float4* b4 = (const float4*)bias;
    float4 b0 = b4[lane * 2], b1 = b4[lane * 2 + 1];
    float v0 = acc0 + b0.x; v0 = v0 > 0.f ? v0 : expm1f(v0);
    float v1 = acc1 + b0.y; v1 = v1 > 0.f ? v1 : expm1f(v1);
    float v2 = acc2 + b0.z; v2 = v2 > 0.f ? v2 : expm1f(v2);
    float v3 = acc3 + b0.w; v3 = v3 > 0.f ? v3 : expm1f(v3);
    float v4 = acc4 + b1.x; v4 = v4 > 0.f ? v4 : expm1f(v4);
    float v5 = acc5 + b1.y; v5 = v5 > 0.f ? v5 : expm1f(v5);
    float v6 = acc6 + b1.z; v6 = v6 > 0.f ? v6 : expm1f(v6);
    float v7 = acc7 + b1.w; v7 = v7 > 0.f ? v7 : expm1f(v7);
    uint4 ov;
    *(__nv_bfloat162*)&ov.x = __floats2bfloat162_rn(v0, v1);
    *(__nv_bfloat162*)&ov.y = __floats2bfloat162_rn(v2, v3);
    *(__nv_bfloat162*)&ov.z = __floats2bfloat162_rn(v4, v5);
    *(__nv_bfloat162*)&ov.w = __floats2bfloat162_rn(v6, v7);
    ((uint4*)(hout + (size_t)n * DDIM))[lane] = ov;
}

// ---------------- mean pool over sorted batch (bf16 input) ----------------
#define PCHUNK 256
__global__ void pool_kernel(const __nv_bfloat16* __restrict__ h, const int* __restrict__ batch,
                            float* __restrict__ sums, float* __restrict__ cnt) {
    __shared__ int sb[PCHUNK];
    int n0 = blockIdx.x * PCHUNK;
    int n1 = min(N_NODES, n0 + PCHUNK);
    int cnt_local = n1 - n0;
    for (int i = threadIdx.x; i < cnt_local; i += blockDim.x) sb[i] = batch[n0 + i];
    __syncthreads();
    int t = threadIdx.x;
    float acc = 0.0f;
    int gp = sb[0];
    for (int i = 0; i < cnt_local; i++) {
        int g = sb[i];
        if (g != gp) { atomicAdd(&sums[gp * DDIM + t], acc); acc = 0.0f; gp = g; }
        acc += __bfloat162float(h[(size_t)(n0 + i) * DDIM + t]);
    }
    atomicAdd(&sums[gp * DDIM + t], acc);
    if (t == 0) {
        float c = 0.0f; gp = sb[0];
        for (int i = 0; i < cnt_local; i++) {
            int g = sb[i];
            if (g != gp) { atomicAdd(&cnt[gp], c); c = 0.0f; gp = g; }
            c += 1.0f;
        }
        atomicAdd(&cnt[gp], c);
    }
}

// ---------------- decoder ----------------
__global__ void decoder_kernel(const float* __restrict__ sums, const float* __restrict__ cnt,
                               const float* __restrict__ w1, const float* __restrict__ b1,
                               const float* __restrict__ gam, const float* __restrict__ bet,
                               const float* __restrict__ w2, const float* __restrict__ b2,
                               float* __restrict__ out) {
    __shared__ float p[DDIM];
    __shared__ float y[64];
    int t = threadIdx.x;
    for (int gr = 0; gr < NGRP; gr++) {
        float invc = 1.0f / fmaxf(cnt[gr], 1.0f);
        for (int i = t; i < DDIM; i += 64) p[i] = sums[gr * DDIM + i] * invc;
        __syncthreads();
        float acc = b1[t];
        for (int k = 0; k < DDIM; k++) acc += p[k] * w1[k * 64 + t];
        y[t] = acc;
        __syncthreads();
        float m = 0.0f;
        for (int k = 0; k < 64; k++) m += y[k];
        m *= (1.0f / 64.0f);
        float v = 0.0f;
        for (int k = 0; k < 64; k++) { float d = y[k] - m; v += d * d; }
        v *= (1.0f / 64.0f);
        float z = fmaxf(0.0f, gam[t] * (acc - m) * rsqrtf(v + EPS_LN) + bet[t]);
        __syncthreads();
        y[t] = z;
        __syncthreads();
        if (t < OUTF) {
            float o = b2[t];
            for (int k = 0; k < 64; k++) o += y[k] * w2[k * OUTF + t];
            out[gr * OUTF + t] = o;
        }
        __syncthreads();
    }
}

// ---------------- orchestration ----------------
extern "C" void kernel_launch(void* const* d_in, const int* in_sizes, int n_in,
                              void* d_out, int out_size) {
    const float* x      = (const float*)d_in[0];
    const int*   ei     = (const int*)d_in[1];
    const int*   batch  = (const int*)d_in[2];
    const float* enc_w1 = (const float*)d_in[3];
    const float* enc_b1 = (const float*)d_in[4];
    const float* enc_g  = (const float*)d_in[5];
    const float* enc_be = (const float*)d_in[6];
    const float* enc_w2 = (const float*)d_in[7];
    const float* enc_b2 = (const float*)d_in[8];
    const float* convW[3]  = { (const float*)d_in[9],  (const float*)d_in[13], (const float*)d_in[17] };
    const float* convAS[3] = { (const float*)d_in[10], (const float*)d_in[14], (const float*)d_in[18] };
    const float* convAD[3] = { (const float*)d_in[11], (const float*)d_in[15], (const float*)d_in[19] };
    const float* convB[3]  = { (const float*)d_in[12], (const float*)d_in[16], (const float*)d_in[20] };
    const float* dec_w1 = (const float*)d_in[21];
    const float* dec_b1 = (const float*)d_in[22];
    const float* dec_g  = (const float*)d_in[23];
    const float* dec_be = (const float*)d_in[24];
    const float* dec_w2 = (const float*)d_in[25];
    const float* dec_b2 = (const float*)d_in[26];

    float *als, *ald, *sums, *cnt;
    int *deg, *off, *cur, *adj, *bsum, *boff;
    __nv_bfloat16 *wthi, *wtlo, *projb, *bufA, *bufB;
    cudaGetSymbolAddress((void**)&bufA,  g_bufA);
    cudaGetSymbolAddress((void**)&bufB,  g_bufB);
    cudaGetSymbolAddress((void**)&projb, g_projb);
    cudaGetSymbolAddress((void**)&als,   g_als);
    cudaGetSymbolAddress((void**)&ald,   g_ald);
    cudaGetSymbolAddress((void**)&deg,   g_deg);
    cudaGetSymbolAddress((void**)&off,   g_off);
    cudaGetSymbolAddress((void**)&cur,   g_cur);
    cudaGetSymbolAddress((void**)&adj,   g_adj);
    cudaGetSymbolAddress((void**)&sums,  g_sums);
    cudaGetSymbolAddress((void**)&cnt,   g_cnt);
    cudaGetSymbolAddress((void**)&bsum,  g_bsum);
    cudaGetSymbolAddress((void**)&boff,  g_boff);
    cudaGetSymbolAddress((void**)&wthi,  g_wthi);
    cudaGetSymbolAddress((void**)&wtlo,  g_wtlo);

    cudaFuncSetAttribute(encoder_kernel, cudaFuncAttributeMaxDynamicSharedMemorySize, ENC_SMEM);
    cudaFuncSetAttribute(gemm_mma_kernel, cudaFuncAttributeMaxDynamicSharedMemorySize, GEMM_SMEM);

    // CSR build
    cudaMemsetAsync(deg, 0, N_NODES * sizeof(int));
    hist_kernel<<<(ETOT + 255) / 256, 256>>>(ei, deg);
    degsum_kernel<<<NB_CSR, 256>>>(deg, bsum);
    scanb_kernel<<<1, 256>>>(bsum, boff);
    offsets_kernel<<<NB_CSR, 256>>>(deg, boff, off, cur);
    scatter_kernel<<<(ETOT + 255) / 256, 256>>>(ei, cur, adj);

    // encoder -> bufA [N,64] bf16
    encoder_kernel<<<(N_NODES + 63) / 64, 256, ENC_SMEM>>>(
        x, enc_w1, enc_b1, enc_g, enc_be, enc_w2, enc_b2, bufA);

    __nv_bfloat16* hin = bufA;
    __nv_bfloat16* hout = bufB;
    int Fin = HID;
    for (int L = 0; L < 3; L++) {
        prep_wt_kernel<<<DDIM, 256>>>(convW[L], wthi, wtlo, Fin);
        dim3 ggrid(2, (N_NODES + 127) / 128);
        gemm_mma_kernel<<<ggrid, 256, GEMM_SMEM>>>(hin, wthi, wtlo, convAS[L], convAD[L],
                                                   projb, als, ald, N_NODES, Fin);
        gat_fused_kernel<<<(N_NODES + 7) / 8, 256>>>(off, adj, projb, als, ald, convB[L], hout);
        __nv_bfloat16* tmp = hin; hin = hout; hout = tmp;
        Fin = DDIM;
    }

    cudaMemsetAsync(sums, 0, NGRP * DDIM * sizeof(float));
    cudaMemsetAsync(cnt, 0, NGRP * sizeof(float));
    pool_kernel<<<(N_NODES + PCHUNK - 1) / PCHUNK, 256>>>(hin, batch, sums, cnt);
    decoder_kernel<<<1, 64>>>(sums, cnt, dec_w1, dec_b1, dec_g, dec_be, dec_w2, dec_b2,
                              (float*)d_out);
}

// round 15
// speedup vs baseline: 1.0437x; 1.0314x over previous
#include <cuda_runtime.h>
#include <cuda_bf16.h>
#include <math.h>
#include <stdint.h>

#define N_NODES 50000
#define N_EDGES 800000
#define ETOT    850000   // edges + self loops
#define HID     64
#define HEADS   4
#define DDIM    256      // HID*HEADS
#define OUTF    40
#define NGRP    8
#define EPS_LN  1e-5f
#define CAP     96

// ---------------- scratch (device globals; no dynamic alloc allowed) ----------------
__device__ __nv_bfloat16 g_bufA[(size_t)N_NODES * DDIM];
__device__ __nv_bfloat16 g_bufB[(size_t)N_NODES * DDIM];
__device__ __nv_bfloat16 g_projb[(size_t)N_NODES * DDIM];
__device__ float g_als[N_NODES * HEADS];
__device__ float g_ald[N_NODES * HEADS];
__device__ int   g_deg[N_NODES];
__device__ int   g_off[N_NODES + 1];
__device__ int   g_cur[N_NODES];
__device__ int   g_adj[ETOT];
__device__ float g_sums[NGRP * DDIM];
__device__ float g_cnt[NGRP];
__device__ __nv_bfloat16 g_wthi[DDIM * DDIM];   // W^T hi, [N=256][K]
__device__ __nv_bfloat16 g_wtlo[DDIM * DDIM];   // W^T lo
#define NB_CSR ((N_NODES + 255) / 256)
__device__ int g_bsum[NB_CSR];
__device__ int g_boff[NB_CSR];

// ---------------- W prep: transpose + bf16 hi/lo split ----------------
__global__ void prep_wt_kernel(const float* __restrict__ W,
                               __nv_bfloat16* __restrict__ hi,
                               __nv_bfloat16* __restrict__ lo, int K) {
    int n = blockIdx.x;                    // 0..255
    for (int k = threadIdx.x; k < K; k += blockDim.x) {
        float v = W[(size_t)k * DDIM + n];
        __nv_bfloat16 h = __float2bfloat16(v);
        float r = v - __bfloat162float(h);
        hi[(size_t)n * K + k] = h;
        lo[(size_t)n * K + k] = __float2bfloat16(r);
    }
}

// ---------------- bf16x2 HMMA GEMM + fused attcoef + bf16 proj output ----------------
#define KCH 32
#define LDK 40          // padded smem row stride (bf16 elems); 80 B = 16B multiple
#define TILE_E (128 * LDK)          // bf16 elements per operand buffer (5120)
#define GEMM_SMEM (6 * TILE_E * 2)  // 2 buffers x 3 operands = 61440 bytes

__device__ __forceinline__ void mma_bf16(float* c, uint32_t a0, uint32_t a1,
                                         uint32_t a2, uint32_t a3,
                                         uint32_t b0, uint32_t b1) {
    asm volatile(
        "mma.sync.aligned.m16n8k16.row.col.f32.bf16.bf16.f32 "
        "{%0,%1,%2,%3}, {%4,%5,%6,%7}, {%8,%9}, {%0,%1,%2,%3};"
        : "+f"(c[0]), "+f"(c[1]), "+f"(c[2]), "+f"(c[3])
        : "r"(a0), "r"(a1), "r"(a2), "r"(a3), "r"(b0), "r"(b1));
}

__device__ __forceinline__ void ldsm_x4(uint32_t& d0, uint32_t& d1,
                                        uint32_t& d2, uint32_t& d3, uint32_t saddr) {
    asm volatile("ldmatrix.sync.aligned.m8n8.x4.shared.b16 {%0,%1,%2,%3}, [%4];"
                 : "=r"(d0), "=r"(d1), "=r"(d2), "=r"(d3) : "r"(saddr));
}
__device__ __forceinline__ void ldsm_x2(uint32_t& d0, uint32_t& d1, uint32_t saddr) {
    asm volatile("ldmatrix.sync.aligned.m8n8.x2.shared.b16 {%0,%1}, [%2];"
                 : "=r"(d0), "=r"(d1) : "r"(saddr));
}

__device__ __forceinline__ void cp_async16(uint32_t saddr, const void* gptr) {
    asm volatile("cp.async.cg.shared.global [%0], [%1], 16;"
                 :: "r"(saddr), "l"(gptr) : "memory");
}
#define CP_COMMIT() asm volatile("cp.async.commit_group;" ::: "memory")
#define CP_WAIT(n)  asm volatile("cp.async.wait_group %0;" :: "n"(n) : "memory")

__global__ __launch_bounds__(256) void gemm_mma_kernel(
    const __nv_bfloat16* __restrict__ A,
    const __nv_bfloat16* __restrict__ BH, const __nv_bfloat16* __restrict__ BL,
    const float* __restrict__ a_s, const float* __restrict__ a_d,
    __nv_bfloat16* __restrict__ Pb,
    float* __restrict__ als, float* __restrict__ ald,
    int M, int K) {
    extern __shared__ __align__(16) __nv_bfloat16 gsm[];
    __nv_bfloat16* sA  = gsm;                 // [2][128][LDK]
    __nv_bfloat16* sBh = gsm + 2 * TILE_E;
    __nv_bfloat16* sBl = gsm + 4 * TILE_E;
    uint32_t saA  = (uint32_t)__cvta_generic_to_shared(sA);
    uint32_t saBh = (uint32_t)__cvta_generic_to_shared(sBh);
    uint32_t saBl = (uint32_t)__cvta_generic_to_shared(sBl);

    int tid = threadIdx.x;
    int warp = tid >> 5, lane = tid & 31;
    int g = lane >> 2, tg = lane & 3;
    int warpM = warp & 3, warpN = warp >> 2;   // 4 x 2
    int bm0 = blockIdx.y * 128;
    int bn0 = blockIdx.x * 128;

    float acc[2][8][4];
#pragma unroll
    for (int i = 0; i < 2; i++)
#pragma unroll
        for (int j = 0; j < 8; j++)
#pragma unroll
            for (int q = 0; q < 4; q++) acc[i][j][q] = 0.f;

    int rowLoc = tid >> 1;
    int kq = (tid & 1) * 16;    // 16 bf16 = 32 bytes = 2 x cp.async per operand
    int grow = bm0 + rowLoc;
    int arow = grow < M ? grow : (M - 1);   // clamp: garbage rows feed discarded outputs only
    int nch = K / KCH;

    // ldmatrix lane-geometry (constants per thread)
    int aRow = ((lane >> 3) & 1) * 8 + (lane & 7);   // row-in-16 for A tile t=lane>>3
    int aK   = (lane >> 4) * 8;                      // k-offset 0 or 8 (tiles 2,3)
    int bN   = lane & 7;                             // B row (n within 8-group)
    int bK   = ((lane >> 3) & 1) * 8;                // B k-offset (lanes 0-7:0, 8-15:8)

    uint32_t dstOffBytes = (uint32_t)(rowLoc * LDK + kq) * 2;
    const __nv_bfloat16* apBase = A + (size_t)arow * K + kq;
    const __nv_bfloat16* bhBase = BH + (size_t)(bn0 + rowLoc) * K + kq;
    const __nv_bfloat16* blBase = BL + (size_t)(bn0 + rowLoc) * K + kq;

    // prologue: async-load chunk 0 into buffer 0
    {
        cp_async16(saA  + dstOffBytes,      apBase);
        cp_async16(saA  + dstOffBytes + 16, apBase + 8);
        cp_async16(saBh + dstOffBytes,      bhBase);
        cp_async16(saBh + dstOffBytes + 16, bhBase + 8);
        cp_async16(saBl + dstOffBytes,      blBase);
        cp_async16(saBl + dstOffBytes + 16, blBase + 8);
        CP_COMMIT();
    }

    for (int c = 0; c < nch; c++) {
        int buf = c & 1;
        if (c + 1 < nch) {
            int k0 = (c + 1) * KCH;
            uint32_t nb = ((c + 1) & 1) * (uint32_t)(TILE_E * 2) + dstOffBytes;
            cp_async16(saA  + nb,      apBase + k0);
            cp_async16(saA  + nb + 16, apBase + k0 + 8);
            cp_async16(saBh + nb,      bhBase + k0);
            cp_async16(saBh + nb + 16, bhBase + k0 + 8);
            cp_async16(saBl + nb,      blBase + k0);
            cp_async16(saBl + nb + 16, blBase + k0 + 8);
            CP_COMMIT();
            CP_WAIT(1);
        } else {
            CP_WAIT(0);
        }
        __syncthreads();

        uint32_t aBase  = saA  + buf * (uint32_t)(TILE_E * 2);
        uint32_t bhBs   = saBh + buf * (uint32_t)(TILE_E * 2);
        uint32_t blBs   = saBl + buf * (uint32_t)(TILE_E * 2);
#pragma unroll
        for (int ks = 0; ks < 2; ks++) {
            uint32_t ah[2][4];
#pragma unroll
            for (int mt = 0; mt < 2; mt++) {
                int m = warpM * 32 + mt * 16 + aRow;
                uint32_t addr = aBase + (uint32_t)((m * LDK + ks * 16 + aK) * 2);
                ldsm_x4(ah[mt][0], ah[mt][1], ah[mt][2], ah[mt][3], addr);
            }
            uint32_t boff = (uint32_t)(((warpN * 64 + bN) * LDK + ks * 16 + bK) * 2);
#pragma unroll
            for (int nt = 0; nt < 8; nt++) {
                uint32_t bo = boff + (uint32_t)(nt * 8 * LDK * 2);
                uint32_t bh0, bh1, bl0, bl1;
                ldsm_x2(bh0, bh1, bhBs + bo);
                ldsm_x2(bl0, bl1, blBs + bo);
#pragma unroll
                for (int mt = 0; mt < 2; mt++) {
                    mma_bf16(acc[mt][nt], ah[mt][0], ah[mt][1], ah[mt][2], ah[mt][3], bh0, bh1);
                    mma_bf16(acc[mt][nt], ah[mt][0], ah[mt][1], ah[mt][2], ah[mt][3], bl0, bl1);
                }
            }
        }
        __syncthreads();
    }

    // ---- epilogue: bf16 proj store + fused attention coefficients ----
    int head = (bn0 >> 6) + warpN;
    float asv[16], adv[16];
#pragma unroll
    for (int nt = 0; nt < 8; nt++) {
#pragma unroll
        for (int q = 0; q < 2; q++) {
            int gcol = bn0 + warpN * 64 + nt * 8 + tg * 2 + q;
            asv[nt * 2 + q] = a_s[gcol];
            adv[nt * 2 + q] = a_d[gcol];
        }
    }
#pragma unroll
    for (int mt = 0; mt < 2; mt++) {
        int r0 = bm0 + warpM * 32 + mt * 16 + g;
        float s_lo = 0.f, s_hi = 0.f, d_lo = 0.f, d_hi = 0.f;
#pragma unroll
        for (int nt = 0; nt < 8; nt++) {
            int col = bn0 + warpN * 64 + nt * 8 + tg * 2;
            __nv_bfloat162 p0 = __floats2bfloat162_rn(acc[mt][nt][0], acc[mt][nt][1]);
            __nv_bfloat162 p1 = __floats2bfloat162_rn(acc[mt][nt][2], acc[mt][nt][3]);
            if (r0 < M)     *(__nv_bfloat162*)(Pb + (size_t)r0 * DDIM + col) = p0;
            if (r0 + 8 < M) *(__nv_bfloat162*)(Pb + (size_t)(r0 + 8) * DDIM + col) = p1;
            s_lo += acc[mt][nt][0] * asv[nt * 2] + acc[mt][nt][1] * asv[nt * 2 + 1];
            s_hi += acc[mt][nt][2] * asv[nt * 2] + acc[mt][nt][3] * asv[nt * 2 + 1];
            d_lo += acc[mt][nt][0] * adv[nt * 2] + acc[mt][nt][1] * adv[nt * 2 + 1];
            d_hi += acc[mt][nt][2] * adv[nt * 2] + acc[mt][nt][3] * adv[nt * 2 + 1];
        }
#pragma unroll
        for (int o = 1; o < 4; o <<= 1) {
            s_lo += __shfl_xor_sync(0xFFFFFFFFu, s_lo, o);
            s_hi += __shfl_xor_sync(0xFFFFFFFFu, s_hi, o);
            d_lo += __shfl_xor_sync(0xFFFFFFFFu, d_lo, o);
            d_hi += __shfl_xor_sync(0xFFFFFFFFu, d_hi, o);
        }
        if (tg == 0) {
            if (r0 < M)     { als[r0 * HEADS + head] = s_lo; ald[r0 * HEADS + head] = d_lo; }
            if (r0 + 8 < M) { als[(r0 + 8) * HEADS + head] = s_hi; ald[(r0 + 8) * HEADS + head] = d_hi; }
        }
    }
}

// ---------------- encoder: 64-node tiles, weights cached in smem, bf16 out ----------------
#define ENC_SMEM ((8448 + 8192 + 4352) * 4)
__global__ __launch_bounds__(256) void encoder_kernel(
    const float* __restrict__ x,
    const float* __restrict__ w1, const float* __restrict__ b1,
    const float* __restrict__ gam, const float* __restrict__ bet,
    const float* __restrict__ w2, const float* __restrict__ b2,
    __nv_bfloat16* __restrict__ h0) {
    extern __shared__ float sm[];
    float* xs = sm;             // [64][132]
    float* ws = sm + 8448;      // [128][64] then [64][64]
    float* ys = sm + 16640;     // [64][68]
    int t = threadIdx.x;
    int n0 = blockIdx.x * 64;
    for (int i = t; i < 64 * 128; i += 256) {
        int nd = i >> 7, k = i & 127;
        int gn = n0 + nd;
        xs[nd * 132 + k] = (gn < N_NODES) ? x[(size_t)gn * 128 + k] : 0.f;
    }
    for (int i = t; i < 128 * 64; i += 256) ws[i] = w1[i];
    __syncthreads();
    int tx = t & 15, ty = t >> 4;
    float acc[4][4] = {};
#pragma unroll 4
    for (int k = 0; k < 128; k++) {
        float4 b4 = *(const float4*)&ws[k * 64 + tx * 4];
        float a0 = xs[(ty * 4 + 0) * 132 + k];
        float a1 = xs[(ty * 4 + 1) * 132 + k];
        float a2 = xs[(ty * 4 + 2) * 132 + k];
        float a3 = xs[(ty * 4 + 3) * 132 + k];
        acc[0][0] += a0 * b4.x; acc[0][1] += a0 * b4.y; acc[0][2] += a0 * b4.z; acc[0][3] += a0 * b4.w;
        acc[1][0] += a1 * b4.x; acc[1][1] += a1 * b4.y; acc[1][2] += a1 * b4.z; acc[1][3] += a1 * b4.w;
        acc[2][0] += a2 * b4.x; acc[2][1] += a2 * b4.y; acc[2][2] += a2 * b4.z; acc[2][3] += a2 * b4.w;
        acc[3][0] += a3 * b4.x; acc[3][1] += a3 * b4.y; acc[3][2] += a3 * b4.z; acc[3][3] += a3 * b4.w;
    }
    float4 b1v = *(const float4*)&b1[tx * 4];
#pragma unroll
    for (int i = 0; i < 4; i++)
        *(float4*)&ys[(ty * 4 + i) * 68 + tx * 4] = make_float4(
            acc[i][0] + b1v.x, acc[i][1] + b1v.y, acc[i][2] + b1v.z, acc[i][3] + b1v.w);
    __syncthreads();
    {
        int nd = t >> 2, q = t & 3;
        float s1 = 0.f, s2 = 0.f;
#pragma unroll
        for (int j = 0; j < 16; j++) {
            float v = ys[nd * 68 + q * 16 + j];
            s1 += v; s2 += v * v;
        }
        s1 += __shfl_xor_sync(0xFFFFFFFFu, s1, 1); s2 += __shfl_xor_sync(0xFFFFFFFFu, s2, 1);
        s1 += __shfl_xor_sync(0xFFFFFFFFu, s1, 2); s2 += __shfl_xor_sync(0xFFFFFFFFu, s2, 2);
        float m = s1 * (1.f / 64.f);
        float var = s2 * (1.f / 64.f) - m * m;
        float inv = rsqrtf(var + EPS_LN);
#pragma unroll
        for (int j = 0; j < 16; j++) {
            int col = q * 16 + j;
            float v = ys[nd * 68 + col];
            float z = gam[col] * (v - m) * inv + bet[col];
            ys[nd * 68 + col] = fmaxf(z, 0.f);
        }
    }
    __syncthreads();
    for (int i = t; i < 64 * 64; i += 256) ws[i] = w2[i];
    __syncthreads();
    float acc2[4][4] = {};
#pragma unroll 4
    for (int k = 0; k < 64; k++) {
        float4 b4 = *(const float4*)&ws[k * 64 + tx * 4];
        float a0 = ys[(ty * 4 + 0) * 68 + k];
        float a1 = ys[(ty * 4 + 1) * 68 + k];
        float a2 = ys[(ty * 4 + 2) * 68 + k];
        float a3 = ys[(ty * 4 + 3) * 68 + k];
        acc2[0][0] += a0 * b4.x; acc2[0][1] += a0 * b4.y; acc2[0][2] += a0 * b4.z; acc2[0][3] += a0 * b4.w;
        acc2[1][0] += a1 * b4.x; acc2[1][1] += a1 * b4.y; acc2[1][2] += a1 * b4.z; acc2[1][3] += a1 * b4.w;
        acc2[2][0] += a2 * b4.x; acc2[2][1] += a2 * b4.y; acc2[2][2] += a2 * b4.z; acc2[2][3] += a2 * b4.w;
        acc2[3][0] += a3 * b4.x; acc2[3][1] += a3 * b4.y; acc2[3][2] += a3 * b4.z; acc2[3][3] += a3 * b4.w;
    }
    float4 b2v = *(const float4*)&b2[tx * 4];
#pragma unroll
    for (int i = 0; i < 4; i++) {
        int gn = n0 + ty * 4 + i;
        if (gn < N_NODES) {
            __nv_bfloat162 q0 = __floats2bfloat162_rn(acc2[i][0] + b2v.x, acc2[i][1] + b2v.y);
            __nv_bfloat162 q1 = __floats2bfloat162_rn(acc2[i][2] + b2v.z, acc2[i][3] + b2v.w);
            *(__nv_bfloat162*)(h0 + (size_t)gn * 64 + tx * 4)     = q0;
            *(__nv_bfloat162*)(h0 + (size_t)gn * 64 + tx * 4 + 2) = q1;
        }
    }
}

// ---------------- CSR build (two-level scan) ----------------
__global__ void hist_kernel(const int* __restrict__ ei, int* __restrict__ deg) {
    int e = blockIdx.x * blockDim.x + threadIdx.x;
    if (e >= ETOT) return;
    int dst = (e < N_EDGES) ? ei[N_EDGES + e] : (e - N_EDGES);
    atomicAdd(&deg[dst], 1);
}

__global__ void degsum_kernel(const int* __restrict__ deg, int* __restrict__ bsum) {
    __shared__ int red[256];
    int b = blockIdx.x, t = threadIdx.x;
    int i = b * 256 + t;
    red[t] = (i < N_NODES) ? deg[i] : 0;
    __syncthreads();
    for (int o = 128; o; o >>= 1) { if (t < o) red[t] += red[t + o]; __syncthreads(); }
    if (t == 0) bsum[b] = red[0];
}

__global__ void scanb_kernel(const int* __restrict__ bsum, int* __restrict__ boff) {
    __shared__ int s[256];
    int t = threadIdx.x;
    int v0 = (t < NB_CSR) ? bsum[t] : 0;
    s[t] = v0;
    __syncthreads();
    for (int o = 1; o < 256; o <<= 1) {
        int v = (t >= o) ? s[t - o] : 0;
        __syncthreads();
        s[t] += v;
        __syncthreads();
    }
    if (t < NB_CSR) boff[t] = s[t] - v0;
}

__global__ void offsets_kernel(const int* __restrict__ deg, const int* __restrict__ boff,
                               int* __restrict__ off, int* __restrict__ cur) {
    __shared__ int s[256];
    int b = blockIdx.x, t = threadIdx.x;
    int i = b * 256 + t;
    int d = (i < N_NODES) ? deg[i] : 0;
    s[t] = d;
    __syncthreads();
    for (int o = 1; o < 256; o <<= 1) {
        int v = (t >= o) ? s[t - o] : 0;
        __syncthreads();
        s[t] += v;
        __syncthreads();
    }
    int excl = boff[b] + s[t] - d;
    if (i < N_NODES) { off[i] = excl; cur[i] = excl; }
    if (b == 0 && t == 0) off[N_NODES] = ETOT;
}

__global__ void scatter_kernel(const int* __restrict__ ei,
                               int* __restrict__ cur, int* __restrict__ adj) {
    int e = blockIdx.x * blockDim.x + threadIdx.x;
    if (e >= ETOT) return;
    int src, dst;
    if (e < N_EDGES) { src = ei[e]; dst = ei[N_EDGES + e]; }
    else             { src = dst = e - N_EDGES; }
    int pos = atomicAdd(&cur[dst], 1);
    adj[pos] = src;
}

// ---------------- fused GAT attention + aggregation + bias + ELU (warp per node) ----------------
__device__ __forceinline__ float lrelu(float v) { return v > 0.f ? v : 0.2f * v; }
__device__ __forceinline__ float pick4(float4 v, int h) {
    float lo = (h == 0) ? v.x : v.y;
    float hi = (h == 2) ? v.z : v.w;
    return (h < 2) ? lo : hi;
}

__global__ __launch_bounds__(256) void gat_fused_kernel(
    const int* __restrict__ off, const int* __restrict__ adj,
    const __nv_bfloat16* __restrict__ projb, const float* __restrict__ als,
    const float* __restrict__ ald, const float* __restrict__ bias,
    __nv_bfloat16* __restrict__ hout) {
    __shared__ float sE[8][CAP][4];
    __shared__ int   sS[8][CAP];
    int w = threadIdx.x >> 5, lane = threadIdx.x & 31;
    int n = blockIdx.x * 8 + w;
    if (n >= N_NODES) return;
    int e0 = off[n];
    int deg = off[n + 1] - e0;
    float4 aldn = ((const float4*)ald)[n];

    float4 mx = make_float4(-INFINITY, -INFINITY, -INFINITY, -INFINITY);
    for (int j = lane; j < deg; j += 32) {
        int s = adj[e0 + j];
        float4 a = ((const float4*)als)[s];
        float4 e;
        e.x = lrelu(a.x + aldn.x);
        e.y = lrelu(a.y + aldn.y);
        e.z = lrelu(a.z + aldn.z);
        e.w = lrelu(a.w + aldn.w);
        if (j < CAP) { sS[w][j] = s; *(float4*)sE[w][j] = e; }
        mx.x = fmaxf(mx.x, e.x); mx.y = fmaxf(mx.y, e.y);
        mx.z = fmaxf(mx.z, e.z); mx.w = fmaxf(mx.w, e.w);
    }
#pragma unroll
    for (int o = 16; o; o >>= 1) {
        mx.x = fmaxf(mx.x, __shfl_xor_sync(0xFFFFFFFFu, mx.x, o));
        mx.y = fmaxf(mx.y, __shfl_xor_sync(0xFFFFFFFFu, mx.y, o));
        mx.z = fmaxf(mx.z, __shfl_xor_sync(0xFFFFFFFFu, mx.z, o));
        mx.w = fmaxf(mx.w, __shfl_xor_sync(0xFFFFFFFFu, mx.w, o));
    }

    float4 sum = make_float4(0.f, 0.f, 0.f, 0.f);
    for (int j = lane; j < deg; j += 32) {
        float4 e;
        if (j < CAP) e = *(float4*)sE[w][j];
        else {
            int s = adj[e0 + j];
            float4 a = ((const float4*)als)[s];
            e.x = lrelu(a.x + aldn.x); e.y = lrelu(a.y + aldn.y);
            e.z = lrelu(a.z + aldn.z); e.w = lrelu(a.w + aldn.w);
        }
        float4 g;
        g.x = expf(e.x - mx.x); g.y = expf(e.y - mx.y);
        g.z = expf(e.z - mx.z); g.w = expf(e.w - mx.w);
        if (j < CAP) *(float4*)sE[w][j] = g;
        sum.x += g.x; sum.y += g.y; sum.z += g.z; sum.w += g.w;
    }
#pragma unroll
    for (int o = 16; o; o >>= 1) {
        sum.x += __shfl_xor_sync(0xFFFFFFFFu, sum.x, o);
        sum.y += __shfl_xor_sync(0xFFFFFFFFu, sum.y, o);
        sum.z += __shfl_xor_sync(0xFFFFFFFFu, sum.z, o);
        sum.w += __shfl_xor_sync(0xFFFFFFFFu, sum.w, o);
    }
    int hsel = lane >> 3;      // head for cols lane*8 .. lane*8+7
    float invh = 1.0f / (pick4(sum, hsel) + 1e-16f);
    float mxh  = pick4(mx, hsel);

    // pass 3: weighted aggregation, unrolled x2 for MLP
    float acc0 = 0.f, acc1 = 0.f, acc2 = 0.f, acc3 = 0.f;
    float acc4 = 0.f, acc5 = 0.f, acc6 = 0.f, acc7 = 0.f;
    int j = 0;
    for (; j + 2 <= deg; j += 2) {
        int s0, s1; float g0, g1;
        if (j < CAP) { s0 = sS[w][j]; g0 = sE[w][j][hsel]; }
        else {
            s0 = adj[e0 + j];
            float4 a = ((const float4*)als)[s0];
            g0 = expf(lrelu(pick4(a, hsel) + pick4(aldn, hsel)) - mxh);
        }
        if (j + 1 < CAP) { s1 = sS[w][j + 1]; g1 = sE[w][j + 1][hsel]; }
        else {
            s1 = adj[e0 + j + 1];
            float4 a = ((const float4*)als)[s1];
            g1 = expf(lrelu(pick4(a, hsel) + pick4(aldn, hsel)) - mxh);
        }
        uint4 p0 = ((const uint4*)(projb + (size_t)s0 * DDIM))[lane];
        uint4 p1 = ((const uint4*)(projb + (size_t)s1 * DDIM))[lane];
        float a0 = g0 * invh, a1 = g1 * invh;
        __nv_bfloat162 q;
        q = *(__nv_bfloat162*)&p0.x; acc0 += a0 * __bfloat162float(q.x); acc1 += a0 * __bfloat162float(q.y);
        q = *(__nv_bfloat162*)&p0.y; acc2 += a0 * __bfloat162float(q.x); acc3 += a0 * __bfloat162float(q.y);
        q = *(__nv_bfloat162*)&p0.z; acc4 += a0 * __bfloat162float(q.x); acc5 += a0 * __bfloat162float(q.y);
        q = *(__nv_bfloat162*)&p0.w; acc6 += a0 * __bfloat162float(q.x); acc7 += a0 * __bfloat162float(q.y);
        q = *(__nv_bfloat162*)&p1.x; acc0 += a1 * __bfloat162float(q.x); acc1 += a1 * __bfloat162float(q.y);
        q = *(__nv_bfloat162*)&p1.y; acc2 += a1 * __bfloat162float(q.x); acc3 += a1 * __bfloat162float(q.y);
        q = *(__nv_bfloat162*)&p1.z; acc4 += a1 * __bfloat162float(q.x); acc5 += a1 * __bfloat162float(q.y);
        q = *(__nv_bfloat162*)&p1.w; acc6 += a1 * __bfloat162float(q.x); acc7 += a1 * __bfloat162float(q.y);
    }
    if (j < deg) {
        int s0; float g0;
        if (j < CAP) { s0 = sS[w][j]; g0 = sE[w][j][hsel]; }
        else {
            s0 = adj[e0 + j];
            float4 a = ((const float4*)als)[s0];
            g0 = expf(lrelu(pick4(a, hsel) + pick4(aldn, hsel)) - mxh);
        }
        uint4 p0 = ((const uint4*)(projb + (size_t)s0 * DDIM))[lane];
        float a0 = g0 * invh;
        __nv_bfloat162 q;
        q = *(__nv_bfloat162*)&p0.x; acc0 += a0 * __bfloat162float(q.x); acc1 += a0 * __bfloat162float(q.y);
        q = *(__nv_bfloat162*)&p0.y; acc2 += a0 * __bfloat162float(q.x); acc3 += a0 * __bfloat162float(q.y);
        q = *(__nv_bfloat162*)&p0.z; acc4 += a0 * __bfloat162float(q.x); acc5 += a0 * __bfloat162float(q.y);
        q = *(__nv_bfloat162*)&p0.w; acc6 += a0 * __bfloat162float(q.x); acc7 += a0 * __bfloat162float(q.y);
    }

    const float4* b4 = (const float4*)bias;
    float4 b0 = b4[lane * 2], b1 = b4[lane * 2 + 1];
    float v0 = acc0 + b0.x; v0 = v0 > 0.f ? v0 : expm1f(v0);
    float v1 = acc1 + b0.y; v1 = v1 > 0.f ? v1 : expm1f(v1);
    float v2 = acc2 + b0.z; v2 = v2 > 0.f ? v2 : expm1f(v2);
    float v3 = acc3 + b0.w; v3 = v3 > 0.f ? v3 : expm1f(v3);
    float v4 = acc4 + b1.x; v4 = v4 > 0.f ? v4 : expm1f(v4);
    float v5 = acc5 + b1.y; v5 = v5 > 0.f ? v5 : expm1f(v5);
    float v6 = acc6 + b1.z; v6 = v6 > 0.f ? v6 : expm1f(v6);
    float v7 = acc7 + b1.w; v7 = v7 > 0.f ? v7 : expm1f(v7);
    uint4 ov;
    *(__nv_bfloat162*)&ov.x = __floats2bfloat162_rn(v0, v1);
    *(__nv_bfloat162*)&ov.y = __floats2bfloat162_rn(v2, v3);
    *(__nv_bfloat162*)&ov.z = __floats2bfloat162_rn(v4, v5);
    *(__nv_bfloat162*)&ov.w = __floats2bfloat162_rn(v6, v7);
    ((uint4*)(hout + (size_t)n * DDIM))[lane] = ov;
}

// ---------------- mean pool over sorted batch (bf16 input) ----------------
#define PCHUNK 256
__global__ void pool_kernel(const __nv_bfloat16* __restrict__ h, const int* __restrict__ batch,
                            float* __restrict__ sums, float* __restrict__ cnt) {
    __shared__ int sb[PCHUNK];
    int n0 = blockIdx.x * PCHUNK;
    int n1 = min(N_NODES, n0 + PCHUNK);
    int cnt_local = n1 - n0;
    for (int i = threadIdx.x; i < cnt_local; i += blockDim.x) sb[i] = batch[n0 + i];
    __syncthreads();
    int t = threadIdx.x;
    float acc = 0.0f;
    int gp = sb[0];
    for (int i = 0; i < cnt_local; i++) {
        int g = sb[i];
        if (g != gp) { atomicAdd(&sums[gp * DDIM + t], acc); acc = 0.0f; gp = g; }
        acc += __bfloat162float(h[(size_t)(n0 + i) * DDIM + t]);
    }
    atomicAdd(&sums[gp * DDIM + t], acc);
    if (t == 0) {
        float c = 0.0f; gp = sb[0];
        for (int i = 0; i < cnt_local; i++) {
            int g = sb[i];
            if (g != gp) { atomicAdd(&cnt[gp], c); c = 0.0f; gp = g; }
            c += 1.0f;
        }
        atomicAdd(&cnt[gp], c);
    }
}

// ---------------- decoder ----------------
__global__ void decoder_kernel(const float* __restrict__ sums, const float* __restrict__ cnt,
                               const float* __restrict__ w1, const float* __restrict__ b1,
                               const float* __restrict__ gam, const float* __restrict__ bet,
                               const float* __restrict__ w2, const float* __restrict__ b2,
                               float* __restrict__ out) {
    __shared__ float p[DDIM];
    __shared__ float y[64];
    int t = threadIdx.x;
    for (int gr = 0; gr < NGRP; gr++) {
        float invc = 1.0f / fmaxf(cnt[gr], 1.0f);
        for (int i = t; i < DDIM; i += 64) p[i] = sums[gr * DDIM + i] * invc;
        __syncthreads();
        float acc = b1[t];
        for (int k = 0; k < DDIM; k++) acc += p[k] * w1[k * 64 + t];
        y[t] = acc;
        __syncthreads();
        float m = 0.0f;
        for (int k = 0; k < 64; k++) m += y[k];
        m *= (1.0f / 64.0f);
        float v = 0.0f;
        for (int k = 0; k < 64; k++) { float d = y[k] - m; v += d * d; }
        v *= (1.0f / 64.0f);
        float z = fmaxf(0.0f, gam[t] * (acc - m) * rsqrtf(v + EPS_LN) + bet[t]);
        __syncthreads();
        y[t] = z;
        __syncthreads();
        if (t < OUTF) {
            float o = b2[t];
            for (int k = 0; k < 64; k++) o += y[k] * w2[k * OUTF + t];
            out[gr * OUTF + t] = o;
        }
        __syncthreads();
    }
}

// ---------------- orchestration (forked-stream graph) ----------------
extern "C" void kernel_launch(void* const* d_in, const int* in_sizes, int n_in,
                              void* d_out, int out_size) {
    const float* x      = (const float*)d_in[0];
    const int*   ei     = (const int*)d_in[1];
    const int*   batch  = (const int*)d_in[2];
    const float* enc_w1 = (const float*)d_in[3];
    const float* enc_b1 = (const float*)d_in[4];
    const float* enc_g  = (const float*)d_in[5];
    const float* enc_be = (const float*)d_in[6];
    const float* enc_w2 = (const float*)d_in[7];
    const float* enc_b2 = (const float*)d_in[8];
    const float* convW[3]  = { (const float*)d_in[9],  (const float*)d_in[13], (const float*)d_in[17] };
    const float* convAS[3] = { (const float*)d_in[10], (const float*)d_in[14], (const float*)d_in[18] };
    const float* convAD[3] = { (const float*)d_in[11], (const float*)d_in[15], (const float*)d_in[19] };
    const float* convB[3]  = { (const float*)d_in[12], (const float*)d_in[16], (const float*)d_in[20] };
    const float* dec_w1 = (const float*)d_in[21];
    const float* dec_b1 = (const float*)d_in[22];
    const float* dec_g  = (const float*)d_in[23];
    const float* dec_be = (const float*)d_in[24];
    const float* dec_w2 = (const float*)d_in[25];
    const float* dec_b2 = (const float*)d_in[26];

    float *als, *ald, *sums, *cnt;
    int *deg, *off, *cur, *adj, *bsum, *boff;
    __nv_bfloat16 *wthi, *wtlo, *projb, *bufA, *bufB;
    cudaGetSymbolAddress((void**)&bufA,  g_bufA);
    cudaGetSymbolAddress((void**)&bufB,  g_bufB);
    cudaGetSymbolAddress((void**)&projb, g_projb);
    cudaGetSymbolAddress((void**)&als,   g_als);
    cudaGetSymbolAddress((void**)&ald,   g_ald);
    cudaGetSymbolAddress((void**)&deg,   g_deg);
    cudaGetSymbolAddress((void**)&off,   g_off);
    cudaGetSymbolAddress((void**)&cur,   g_cur);
    cudaGetSymbolAddress((void**)&adj,   g_adj);
    cudaGetSymbolAddress((void**)&sums,  g_sums);
    cudaGetSymbolAddress((void**)&cnt,   g_cnt);
    cudaGetSymbolAddress((void**)&bsum,  g_bsum);
    cudaGetSymbolAddress((void**)&boff,  g_boff);
    cudaGetSymbolAddress((void**)&wthi,  g_wthi);
    cudaGetSymbolAddress((void**)&wtlo,  g_wtlo);

    cudaFuncSetAttribute(encoder_kernel, cudaFuncAttributeMaxDynamicSharedMemorySize, ENC_SMEM);
    cudaFuncSetAttribute(gemm_mma_kernel, cudaFuncAttributeMaxDynamicSharedMemorySize, GEMM_SMEM);

    // one-time side-stream + events (created on the first, uncaptured, call;
    // reused under capture so no stream/event creation happens while capturing)
    static cudaStream_t s2 = 0;
    static cudaEvent_t evFork = 0, evJoin = 0;
    if (s2 == 0) {
        cudaStreamCreateWithFlags(&s2, cudaStreamNonBlocking);
        cudaEventCreateWithFlags(&evFork, cudaEventDisableTiming);
        cudaEventCreateWithFlags(&evJoin, cudaEventDisableTiming);
    }

    // ---- fork: CSR build + pool-buffer clears on side stream ----
    cudaEventRecord(evFork, 0);
    cudaStreamWaitEvent(s2, evFork, 0);
    cudaMemsetAsync(deg, 0, N_NODES * sizeof(int), s2);
    hist_kernel<<<(ETOT + 255) / 256, 256, 0, s2>>>(ei, deg);
    degsum_kernel<<<NB_CSR, 256, 0, s2>>>(deg, bsum);
    scanb_kernel<<<1, 256, 0, s2>>>(bsum, boff);
    offsets_kernel<<<NB_CSR, 256, 0, s2>>>(deg, boff, off, cur);
    scatter_kernel<<<(ETOT + 255) / 256, 256, 0, s2>>>(ei, cur, adj);
    cudaMemsetAsync(sums, 0, NGRP * DDIM * sizeof(float), s2);
    cudaMemsetAsync(cnt, 0, NGRP * sizeof(float), s2);
    cudaEventRecord(evJoin, s2);

    // ---- main stream: encoder + layer-0 projection (independent of CSR) ----
    encoder_kernel<<<(N_NODES + 63) / 64, 256, ENC_SMEM>>>(
        x, enc_w1, enc_b1, enc_g, enc_be, enc_w2, enc_b2, bufA);

    __nv_bfloat16* hin = bufA;
    __nv_bfloat16* hout = bufB;
    int Fin = HID;
    for (int L = 0; L < 3; L++) {
        prep_wt_kernel<<<DDIM, 256>>>(convW[L], wthi, wtlo, Fin);
        dim3 ggrid(2, (N_NODES + 127) / 128);
        gemm_mma_kernel<<<ggrid, 256, GEMM_SMEM>>>(hin, wthi, wtlo, convAS[L], convAD[L],
                                                   projb, als, ald, N_NODES, Fin);
        if (L == 0) cudaStreamWaitEvent(0, evJoin, 0);   // join: gat needs CSR
        gat_fused_kernel<<<(N_NODES + 7) / 8, 256>>>(off, adj, projb, als, ald, convB[L], hout);
        __nv_bfloat16* tmp = hin; hin = hout; hout = tmp;
        Fin = DDIM;
    }

    pool_kernel<<<(N_NODES + PCHUNK - 1) / PCHUNK, 256>>>(hin, batch, sums, cnt);
    decoder_kernel<<<1, 64>>>(sums, cnt, dec_w1, dec_b1, dec_g, dec_be, dec_w2, dec_b2,
                              (float*)d_out);
}

// round 16
// speedup vs baseline: 1.0474x; 1.0036x over previous
#include <cuda_runtime.h>
#include <cuda_bf16.h>
#include <math.h>
#include <stdint.h>

#define N_NODES 50000
#define N_EDGES 800000
#define ETOT    850000   // edges + self loops
#define HID     64
#define HEADS   4
#define DDIM    256      // HID*HEADS
#define OUTF    40
#define NGRP    8
#define EPS_LN  1e-5f
#define CAP     96

// ---------------- scratch (device globals; no dynamic alloc allowed) ----------------
__device__ __nv_bfloat16 g_bufA[(size_t)N_NODES * DDIM];
__device__ __nv_bfloat16 g_bufB[(size_t)N_NODES * DDIM];
__device__ __nv_bfloat16 g_projb[(size_t)N_NODES * DDIM];
__device__ float g_als[N_NODES * HEADS];
__device__ float g_ald[N_NODES * HEADS];
__device__ int   g_deg[N_NODES];
__device__ int   g_off[N_NODES + 1];
__device__ int   g_cur[N_NODES];
__device__ int   g_adj[ETOT];
__device__ float g_sums[NGRP * DDIM];
__device__ float g_cnt[NGRP];
__device__ __nv_bfloat16 g_wthi[3][DDIM * DDIM];   // W^T hi per layer
__device__ __nv_bfloat16 g_wtlo[3][DDIM * DDIM];   // W^T lo per layer
#define NB_CSR ((N_NODES + 255) / 256)
__device__ int g_bsum[NB_CSR];
__device__ int g_boff[NB_CSR];

// ---------------- W prep: transpose + bf16 hi/lo split ----------------
__global__ void prep_wt_kernel(const float* __restrict__ W,
                               __nv_bfloat16* __restrict__ hi,
                               __nv_bfloat16* __restrict__ lo, int K) {
    int n = blockIdx.x;                    // 0..255
    for (int k = threadIdx.x; k < K; k += blockDim.x) {
        float v = W[(size_t)k * DDIM + n];
        __nv_bfloat16 h = __float2bfloat16(v);
        float r = v - __bfloat162float(h);
        hi[(size_t)n * K + k] = h;
        lo[(size_t)n * K + k] = __float2bfloat16(r);
    }
}

// ---------------- bf16x2 HMMA GEMM + fused attcoef + bf16 proj output ----------------
#define KCH 32
#define LDK 40          // padded smem row stride (bf16 elems); 80 B = 16B multiple
#define TILE_E (128 * LDK)          // bf16 elements per operand buffer (5120)
#define GEMM_SMEM (6 * TILE_E * 2)  // 2 buffers x 3 operands = 61440 bytes

__device__ __forceinline__ void mma_bf16(float* c, uint32_t a0, uint32_t a1,
                                         uint32_t a2, uint32_t a3,
                                         uint32_t b0, uint32_t b1) {
    asm volatile(
        "mma.sync.aligned.m16n8k16.row.col.f32.bf16.bf16.f32 "
        "{%0,%1,%2,%3}, {%4,%5,%6,%7}, {%8,%9}, {%0,%1,%2,%3};"
        : "+f"(c[0]), "+f"(c[1]), "+f"(c[2]), "+f"(c[3])
        : "r"(a0), "r"(a1), "r"(a2), "r"(a3), "r"(b0), "r"(b1));
}

__device__ __forceinline__ void ldsm_x4(uint32_t& d0, uint32_t& d1,
                                        uint32_t& d2, uint32_t& d3, uint32_t saddr) {
    asm volatile("ldmatrix.sync.aligned.m8n8.x4.shared.b16 {%0,%1,%2,%3}, [%4];"
                 : "=r"(d0), "=r"(d1), "=r"(d2), "=r"(d3) : "r"(saddr));
}
__device__ __forceinline__ void ldsm_x2(uint32_t& d0, uint32_t& d1, uint32_t saddr) {
    asm volatile("ldmatrix.sync.aligned.m8n8.x2.shared.b16 {%0,%1}, [%2];"
                 : "=r"(d0), "=r"(d1) : "r"(saddr));
}

__device__ __forceinline__ void cp_async16(uint32_t saddr, const void* gptr) {
    asm volatile("cp.async.cg.shared.global [%0], [%1], 16;"
                 :: "r"(saddr), "l"(gptr) : "memory");
}
#define CP_COMMIT() asm volatile("cp.async.commit_group;" ::: "memory")
#define CP_WAIT(n)  asm volatile("cp.async.wait_group %0;" :: "n"(n) : "memory")

__global__ __launch_bounds__(256) void gemm_mma_kernel(
    const __nv_bfloat16* __restrict__ A,
    const __nv_bfloat16* __restrict__ BH, const __nv_bfloat16* __restrict__ BL,
    const float* __restrict__ a_s, const float* __restrict__ a_d,
    __nv_bfloat16* __restrict__ Pb,
    float* __restrict__ als, float* __restrict__ ald,
    int M, int K) {
    extern __shared__ __align__(16) __nv_bfloat16 gsm[];
    __nv_bfloat16* sA  = gsm;                 // [2][128][LDK]
    __nv_bfloat16* sBh = gsm + 2 * TILE_E;
    __nv_bfloat16* sBl = gsm + 4 * TILE_E;
    uint32_t saA  = (uint32_t)__cvta_generic_to_shared(sA);
    uint32_t saBh = (uint32_t)__cvta_generic_to_shared(sBh);
    uint32_t saBl = (uint32_t)__cvta_generic_to_shared(sBl);

    int tid = threadIdx.x;
    int warp = tid >> 5, lane = tid & 31;
    int g = lane >> 2, tg = lane & 3;
    int warpM = warp & 3, warpN = warp >> 2;   // 4 x 2
    int bm0 = blockIdx.y * 128;
    int bn0 = blockIdx.x * 128;

    float acc[2][8][4];
#pragma unroll
    for (int i = 0; i < 2; i++)
#pragma unroll
        for (int j = 0; j < 8; j++)
#pragma unroll
            for (int q = 0; q < 4; q++) acc[i][j][q] = 0.f;

    int rowLoc = tid >> 1;
    int kq = (tid & 1) * 16;    // 16 bf16 = 32 bytes = 2 x cp.async per operand
    int grow = bm0 + rowLoc;
    int arow = grow < M ? grow : (M - 1);   // clamp: garbage rows feed discarded outputs only
    int nch = K / KCH;

    // ldmatrix lane-geometry (constants per thread)
    int aRow = ((lane >> 3) & 1) * 8 + (lane & 7);   // row-in-16 for A tile t=lane>>3
    int aK   = (lane >> 4) * 8;                      // k-offset 0 or 8 (tiles 2,3)
    int bN   = lane & 7;                             // B row (n within 8-group)
    int bK   = ((lane >> 3) & 1) * 8;                // B k-offset (lanes 0-7:0, 8-15:8)

    uint32_t dstOffBytes = (uint32_t)(rowLoc * LDK + kq) * 2;
    const __nv_bfloat16* apBase = A + (size_t)arow * K + kq;
    const __nv_bfloat16* bhBase = BH + (size_t)(bn0 + rowLoc) * K + kq;
    const __nv_bfloat16* blBase = BL + (size_t)(bn0 + rowLoc) * K + kq;

    // prologue: async-load chunk 0 into buffer 0
    {
        cp_async16(saA  + dstOffBytes,      apBase);
        cp_async16(saA  + dstOffBytes + 16, apBase + 8);
        cp_async16(saBh + dstOffBytes,      bhBase);
        cp_async16(saBh + dstOffBytes + 16, bhBase + 8);
        cp_async16(saBl + dstOffBytes,      blBase);
        cp_async16(saBl + dstOffBytes + 16, blBase + 8);
        CP_COMMIT();
    }

    for (int c = 0; c < nch; c++) {
        int buf = c & 1;
        if (c + 1 < nch) {
            int k0 = (c + 1) * KCH;
            uint32_t nb = ((c + 1) & 1) * (uint32_t)(TILE_E * 2) + dstOffBytes;
            cp_async16(saA  + nb,      apBase + k0);
            cp_async16(saA  + nb + 16, apBase + k0 + 8);
            cp_async16(saBh + nb,      bhBase + k0);
            cp_async16(saBh + nb + 16, bhBase + k0 + 8);
            cp_async16(saBl + nb,      blBase + k0);
            cp_async16(saBl + nb + 16, blBase + k0 + 8);
            CP_COMMIT();
            CP_WAIT(1);
        } else {
            CP_WAIT(0);
        }
        __syncthreads();

        uint32_t aBase  = saA  + buf * (uint32_t)(TILE_E * 2);
        uint32_t bhBs   = saBh + buf * (uint32_t)(TILE_E * 2);
        uint32_t blBs   = saBl + buf * (uint32_t)(TILE_E * 2);
#pragma unroll
        for (int ks = 0; ks < 2; ks++) {
            uint32_t ah[2][4];
#pragma unroll
            for (int mt = 0; mt < 2; mt++) {
                int m = warpM * 32 + mt * 16 + aRow;
                uint32_t addr = aBase + (uint32_t)((m * LDK + ks * 16 + aK) * 2);
                ldsm_x4(ah[mt][0], ah[mt][1], ah[mt][2], ah[mt][3], addr);
            }
            uint32_t boff = (uint32_t)(((warpN * 64 + bN) * LDK + ks * 16 + bK) * 2);
#pragma unroll
            for (int nt = 0; nt < 8; nt++) {
                uint32_t bo = boff + (uint32_t)(nt * 8 * LDK * 2);
                uint32_t bh0, bh1, bl0, bl1;
                ldsm_x2(bh0, bh1, bhBs + bo);
                ldsm_x2(bl0, bl1, blBs + bo);
#pragma unroll
                for (int mt = 0; mt < 2; mt++) {
                    mma_bf16(acc[mt][nt], ah[mt][0], ah[mt][1], ah[mt][2], ah[mt][3], bh0, bh1);
                    mma_bf16(acc[mt][nt], ah[mt][0], ah[mt][1], ah[mt][2], ah[mt][3], bl0, bl1);
                }
            }
        }
        __syncthreads();
    }

    // ---- epilogue: bf16 proj store + fused attention coefficients ----
    int head = (bn0 >> 6) + warpN;
    float asv[16], adv[16];
#pragma unroll
    for (int nt = 0; nt < 8; nt++) {
#pragma unroll
        for (int q = 0; q < 2; q++) {
            int gcol = bn0 + warpN * 64 + nt * 8 + tg * 2 + q;
            asv[nt * 2 + q] = a_s[gcol];
            adv[nt * 2 + q] = a_d[gcol];
        }
    }
#pragma unroll
    for (int mt = 0; mt < 2; mt++) {
        int r0 = bm0 + warpM * 32 + mt * 16 + g;
        float s_lo = 0.f, s_hi = 0.f, d_lo = 0.f, d_hi = 0.f;
#pragma unroll
        for (int nt = 0; nt < 8; nt++) {
            int col = bn0 + warpN * 64 + nt * 8 + tg * 2;
            __nv_bfloat162 p0 = __floats2bfloat162_rn(acc[mt][nt][0], acc[mt][nt][1]);
            __nv_bfloat162 p1 = __floats2bfloat162_rn(acc[mt][nt][2], acc[mt][nt][3]);
            if (r0 < M)     *(__nv_bfloat162*)(Pb + (size_t)r0 * DDIM + col) = p0;
            if (r0 + 8 < M) *(__nv_bfloat162*)(Pb + (size_t)(r0 + 8) * DDIM + col) = p1;
            s_lo += acc[mt][nt][0] * asv[nt * 2] + acc[mt][nt][1] * asv[nt * 2 + 1];
            s_hi += acc[mt][nt][2] * asv[nt * 2] + acc[mt][nt][3] * asv[nt * 2 + 1];
            d_lo += acc[mt][nt][0] * adv[nt * 2] + acc[mt][nt][1] * adv[nt * 2 + 1];
            d_hi += acc[mt][nt][2] * adv[nt * 2] + acc[mt][nt][3] * adv[nt * 2 + 1];
        }
#pragma unroll
        for (int o = 1; o < 4; o <<= 1) {
            s_lo += __shfl_xor_sync(0xFFFFFFFFu, s_lo, o);
            s_hi += __shfl_xor_sync(0xFFFFFFFFu, s_hi, o);
            d_lo += __shfl_xor_sync(0xFFFFFFFFu, d_lo, o);
            d_hi += __shfl_xor_sync(0xFFFFFFFFu, d_hi, o);
        }
        if (tg == 0) {
            if (r0 < M)     { als[r0 * HEADS + head] = s_lo; ald[r0 * HEADS + head] = d_lo; }
            if (r0 + 8 < M) { als[(r0 + 8) * HEADS + head] = s_hi; ald[(r0 + 8) * HEADS + head] = d_hi; }
        }
    }
}

// ---------------- encoder: 64-node tiles, weights cached in smem, bf16 out ----------------
#define ENC_SMEM ((8448 + 8192 + 4352) * 4)
__global__ __launch_bounds__(256) void encoder_kernel(
    const float* __restrict__ x,
    const float* __restrict__ w1, const float* __restrict__ b1,
    const float* __restrict__ gam, const float* __restrict__ bet,
    const float* __restrict__ w2, const float* __restrict__ b2,
    __nv_bfloat16* __restrict__ h0) {
    extern __shared__ float sm[];
    float* xs = sm;             // [64][132]
    float* ws = sm + 8448;      // [128][64] then [64][64]
    float* ys = sm + 16640;     // [64][68]
    int t = threadIdx.x;
    int n0 = blockIdx.x * 64;
    for (int i = t; i < 64 * 128; i += 256) {
        int nd = i >> 7, k = i & 127;
        int gn = n0 + nd;
        xs[nd * 132 + k] = (gn < N_NODES) ? x[(size_t)gn * 128 + k] : 0.f;
    }
    for (int i = t; i < 128 * 64; i += 256) ws[i] = w1[i];
    __syncthreads();
    int tx = t & 15, ty = t >> 4;
    float acc[4][4] = {};
#pragma unroll 4
    for (int k = 0; k < 128; k++) {
        float4 b4 = *(const float4*)&ws[k * 64 + tx * 4];
        float a0 = xs[(ty * 4 + 0) * 132 + k];
        float a1 = xs[(ty * 4 + 1) * 132 + k];
        float a2 = xs[(ty * 4 + 2) * 132 + k];
        float a3 = xs[(ty * 4 + 3) * 132 + k];
        acc[0][0] += a0 * b4.x; acc[0][1] += a0 * b4.y; acc[0][2] += a0 * b4.z; acc[0][3] += a0 * b4.w;
        acc[1][0] += a1 * b4.x; acc[1][1] += a1 * b4.y; acc[1][2] += a1 * b4.z; acc[1][3] += a1 * b4.w;
        acc[2][0] += a2 * b4.x; acc[2][1] += a2 * b4.y; acc[2][2] += a2 * b4.z; acc[2][3] += a2 * b4.w;
        acc[3][0] += a3 * b4.x; acc[3][1] += a3 * b4.y; acc[3][2] += a3 * b4.z; acc[3][3] += a3 * b4.w;
    }
    float4 b1v = *(const float4*)&b1[tx * 4];
#pragma unroll
    for (int i = 0; i < 4; i++)
        *(float4*)&ys[(ty * 4 + i) * 68 + tx * 4] = make_float4(
            acc[i][0] + b1v.x, acc[i][1] + b1v.y, acc[i][2] + b1v.z, acc[i][3] + b1v.w);
    __syncthreads();
    {
        int nd = t >> 2, q = t & 3;
        float s1 = 0.f, s2 = 0.f;
#pragma unroll
        for (int j = 0; j < 16; j++) {
            float v = ys[nd * 68 + q * 16 + j];
            s1 += v; s2 += v * v;
        }
        s1 += __shfl_xor_sync(0xFFFFFFFFu, s1, 1); s2 += __shfl_xor_sync(0xFFFFFFFFu, s2, 1);
        s1 += __shfl_xor_sync(0xFFFFFFFFu, s1, 2); s2 += __shfl_xor_sync(0xFFFFFFFFu, s2, 2);
        float m = s1 * (1.f / 64.f);
        float var = s2 * (1.f / 64.f) - m * m;
        float inv = rsqrtf(var + EPS_LN);
#pragma unroll
        for (int j = 0; j < 16; j++) {
            int col = q * 16 + j;
            float v = ys[nd * 68 + col];
            float z = gam[col] * (v - m) * inv + bet[col];
            ys[nd * 68 + col] = fmaxf(z, 0.f);
        }
    }
    __syncthreads();
    for (int i = t; i < 64 * 64; i += 256) ws[i] = w2[i];
    __syncthreads();
    float acc2[4][4] = {};
#pragma unroll 4
    for (int k = 0; k < 64; k++) {
        float4 b4 = *(const float4*)&ws[k * 64 + tx * 4];
        float a0 = ys[(ty * 4 + 0) * 68 + k];
        float a1 = ys[(ty * 4 + 1) * 68 + k];
        float a2 = ys[(ty * 4 + 2) * 68 + k];
        float a3 = ys[(ty * 4 + 3) * 68 + k];
        acc2[0][0] += a0 * b4.x; acc2[0][1] += a0 * b4.y; acc2[0][2] += a0 * b4.z; acc2[0][3] += a0 * b4.w;
        acc2[1][0] += a1 * b4.x; acc2[1][1] += a1 * b4.y; acc2[1][2] += a1 * b4.z; acc2[1][3] += a1 * b4.w;
        acc2[2][0] += a2 * b4.x; acc2[2][1] += a2 * b4.y; acc2[2][2] += a2 * b4.z; acc2[2][3] += a2 * b4.w;
        acc2[3][0] += a3 * b4.x; acc2[3][1] += a3 * b4.y; acc2[3][2] += a3 * b4.z; acc2[3][3] += a3 * b4.w;
    }
    float4 b2v = *(const float4*)&b2[tx * 4];
#pragma unroll
    for (int i = 0; i < 4; i++) {
        int gn = n0 + ty * 4 + i;
        if (gn < N_NODES) {
            __nv_bfloat162 q0 = __floats2bfloat162_rn(acc2[i][0] + b2v.x, acc2[i][1] + b2v.y);
            __nv_bfloat162 q1 = __floats2bfloat162_rn(acc2[i][2] + b2v.z, acc2[i][3] + b2v.w);
            *(__nv_bfloat162*)(h0 + (size_t)gn * 64 + tx * 4)     = q0;
            *(__nv_bfloat162*)(h0 + (size_t)gn * 64 + tx * 4 + 2) = q1;
        }
    }
}

// ---------------- CSR build (two-level scan) ----------------
__global__ void hist_kernel(const int* __restrict__ ei, int* __restrict__ deg) {
    int e = blockIdx.x * blockDim.x + threadIdx.x;
    if (e >= ETOT) return;
    int dst = (e < N_EDGES) ? ei[N_EDGES + e] : (e - N_EDGES);
    atomicAdd(&deg[dst], 1);
}

__global__ void degsum_kernel(const int* __restrict__ deg, int* __restrict__ bsum) {
    __shared__ int red[256];
    int b = blockIdx.x, t = threadIdx.x;
    int i = b * 256 + t;
    red[t] = (i < N_NODES) ? deg[i] : 0;
    __syncthreads();
    for (int o = 128; o; o >>= 1) { if (t < o) red[t] += red[t + o]; __syncthreads(); }
    if (t == 0) bsum[b] = red[0];
}

__global__ void scanb_kernel(const int* __restrict__ bsum, int* __restrict__ boff) {
    __shared__ int s[256];
    int t = threadIdx.x;
    int v0 = (t < NB_CSR) ? bsum[t] : 0;
    s[t] = v0;
    __syncthreads();
    for (int o = 1; o < 256; o <<= 1) {
        int v = (t >= o) ? s[t - o] : 0;
        __syncthreads();
        s[t] += v;
        __syncthreads();
    }
    if (t < NB_CSR) boff[t] = s[t] - v0;
}

__global__ void offsets_kernel(const int* __restrict__ deg, const int* __restrict__ boff,
                               int* __restrict__ off, int* __restrict__ cur) {
    __shared__ int s[256];
    int b = blockIdx.x, t = threadIdx.x;
    int i = b * 256 + t;
    int d = (i < N_NODES) ? deg[i] : 0;
    s[t] = d;
    __syncthreads();
    for (int o = 1; o < 256; o <<= 1) {
        int v = (t >= o) ? s[t - o] : 0;
        __syncthreads();
        s[t] += v;
        __syncthreads();
    }
    int excl = boff[b] + s[t] - d;
    if (i < N_NODES) { off[i] = excl; cur[i] = excl; }
    if (b == 0 && t == 0) off[N_NODES] = ETOT;
}

__global__ void scatter_kernel(const int* __restrict__ ei,
                               int* __restrict__ cur, int* __restrict__ adj) {
    int e = blockIdx.x * blockDim.x + threadIdx.x;
    if (e >= ETOT) return;
    int src, dst;
    if (e < N_EDGES) { src = ei[e]; dst = ei[N_EDGES + e]; }
    else             { src = dst = e - N_EDGES; }
    int pos = atomicAdd(&cur[dst], 1);
    adj[pos] = src;
}

// ---------------- fused GAT attention + aggregation + bias + ELU (warp per node) ----------------
__device__ __forceinline__ float lrelu(float v) { return v > 0.f ? v : 0.2f * v; }
__device__ __forceinline__ float pick4(float4 v, int h) {
    float lo = (h == 0) ? v.x : v.y;
    float hi = (h == 2) ? v.z : v.w;
    return (h < 2) ? lo : hi;
}

__global__ __launch_bounds__(256) void gat_fused_kernel(
    const int* __restrict__ off, const int* __restrict__ adj,
    const __nv_bfloat16* __restrict__ projb, const float* __restrict__ als,
    const float* __restrict__ ald, const float* __restrict__ bias,
    __nv_bfloat16* __restrict__ hout) {
    __shared__ float sE[8][CAP][4];
    __shared__ int   sS[8][CAP];
    int w = threadIdx.x >> 5, lane = threadIdx.x & 31;
    int n = blockIdx.x * 8 + w;
    if (n >= N_NODES) return;
    int e0 = off[n];
    int deg = off[n + 1] - e0;
    float4 aldn = ((const float4*)ald)[n];

    float4 mx = make_float4(-INFINITY, -INFINITY, -INFINITY, -INFINITY);
    for (int j = lane; j < deg; j += 32) {
        int s = adj[e0 + j];
        float4 a = ((const float4*)als)[s];
        float4 e;
        e.x = lrelu(a.x + aldn.x);
        e.y = lrelu(a.y + aldn.y);
        e.z = lrelu(a.z + aldn.z);
        e.w = lrelu(a.w + aldn.w);
        if (j < CAP) { sS[w][j] = s; *(float4*)sE[w][j] = e; }
        mx.x = fmaxf(mx.x, e.x); mx.y = fmaxf(mx.y, e.y);
        mx.z = fmaxf(mx.z, e.z); mx.w = fmaxf(mx.w, e.w);
    }
#pragma unroll
    for (int o = 16; o; o >>= 1) {
        mx.x = fmaxf(mx.x, __shfl_xor_sync(0xFFFFFFFFu, mx.x, o));
        mx.y = fmaxf(mx.y, __shfl_xor_sync(0xFFFFFFFFu, mx.y, o));
        mx.z = fmaxf(mx.z, __shfl_xor_sync(0xFFFFFFFFu, mx.z, o));
        mx.w = fmaxf(mx.w, __shfl_xor_sync(0xFFFFFFFFu, mx.w, o));
    }

    float4 sum = make_float4(0.f, 0.f, 0.f, 0.f);
    for (int j = lane; j < deg; j += 32) {
        float4 e;
        if (j < CAP) e = *(float4*)sE[w][j];
        else {
            int s = adj[e0 + j];
            float4 a = ((const float4*)als)[s];
            e.x = lrelu(a.x + aldn.x); e.y = lrelu(a.y + aldn.y);
            e.z = lrelu(a.z + aldn.z); e.w = lrelu(a.w + aldn.w);
        }
        float4 g;
        g.x = expf(e.x - mx.x); g.y = expf(e.y - mx.y);
        g.z = expf(e.z - mx.z); g.w = expf(e.w - mx.w);
        if (j < CAP) *(float4*)sE[w][j] = g;
        sum.x += g.x; sum.y += g.y; sum.z += g.z; sum.w += g.w;
    }
#pragma unroll
    for (int o = 16; o; o >>= 1) {
        sum.x += __shfl_xor_sync(0xFFFFFFFFu, sum.x, o);
        sum.y += __shfl_xor_sync(0xFFFFFFFFu, sum.y, o);
        sum.z += __shfl_xor_sync(0xFFFFFFFFu, sum.z, o);
        sum.w += __shfl_xor_sync(0xFFFFFFFFu, sum.w, o);
    }
    int hsel = lane >> 3;      // head for cols lane*8 .. lane*8+7
    float invh = 1.0f / (pick4(sum, hsel) + 1e-16f);
    float mxh  = pick4(mx, hsel);

    // pass 3: weighted aggregation, unrolled x2 for MLP
    float acc0 = 0.f, acc1 = 0.f, acc2 = 0.f, acc3 = 0.f;
    float acc4 = 0.f, acc5 = 0.f, acc6 = 0.f, acc7 = 0.f;
    int j = 0;
    for (; j + 2 <= deg; j += 2) {
        int s0, s1; float g0, g1;
        if (j < CAP) { s0 = sS[w][j]; g0 = sE[w][j][hsel]; }
        else {
            s0 = adj[e0 + j];
            float4 a = ((const float4*)als)[s0];
            g0 = expf(lrelu(pick4(a, hsel) + pick4(aldn, hsel)) - mxh);
        }
        if (j + 1 < CAP) { s1 = sS[w][j + 1]; g1 = sE[w][j + 1][hsel]; }
        else {
            s1 = adj[e0 + j + 1];
            float4 a = ((const float4*)als)[s1];
            g1 = expf(lrelu(pick4(a, hsel) + pick4(aldn, hsel)) - mxh);
        }
        uint4 p0 = ((const uint4*)(projb + (size_t)s0 * DDIM))[lane];
        uint4 p1 = ((const uint4*)(projb + (size_t)s1 * DDIM))[lane];
        float a0 = g0 * invh, a1 = g1 * invh;
        __nv_bfloat162 q;
        q = *(__nv_bfloat162*)&p0.x; acc0 += a0 * __bfloat162float(q.x); acc1 += a0 * __bfloat162float(q.y);
        q = *(__nv_bfloat162*)&p0.y; acc2 += a0 * __bfloat162float(q.x); acc3 += a0 * __bfloat162float(q.y);
        q = *(__nv_bfloat162*)&p0.z; acc4 += a0 * __bfloat162float(q.x); acc5 += a0 * __bfloat162float(q.y);
        q = *(__nv_bfloat162*)&p0.w; acc6 += a0 * __bfloat162float(q.x); acc7 += a0 * __bfloat162float(q.y);
        q = *(__nv_bfloat162*)&p1.x; acc0 += a1 * __bfloat162float(q.x); acc1 += a1 * __bfloat162float(q.y);
        q = *(__nv_bfloat162*)&p1.y; acc2 += a1 * __bfloat162float(q.x); acc3 += a1 * __bfloat162float(q.y);
        q = *(__nv_bfloat162*)&p1.z; acc4 += a1 * __bfloat162float(q.x); acc5 += a1 * __bfloat162float(q.y);
        q = *(__nv_bfloat162*)&p1.w; acc6 += a1 * __bfloat162float(q.x); acc7 += a1 * __bfloat162float(q.y);
    }
    if (j < deg) {
        int s0; float g0;
        if (j < CAP) { s0 = sS[w][j]; g0 = sE[w][j][hsel]; }
        else {
            s0 = adj[e0 + j];
            float4 a = ((const float4*)als)[s0];
            g0 = expf(lrelu(pick4(a, hsel) + pick4(aldn, hsel)) - mxh);
        }
        uint4 p0 = ((const uint4*)(projb + (size_t)s0 * DDIM))[lane];
        float a0 = g0 * invh;
        __nv_bfloat162 q;
        q = *(__nv_bfloat162*)&p0.x; acc0 += a0 * __bfloat162float(q.x); acc1 += a0 * __bfloat162float(q.y);
        q = *(__nv_bfloat162*)&p0.y; acc2 += a0 * __bfloat162float(q.x); acc3 += a0 * __bfloat162float(q.y);
        q = *(__nv_bfloat162*)&p0.z; acc4 += a0 * __bfloat162float(q.x); acc5 += a0 * __bfloat162float(q.y);
        q = *(__nv_bfloat162*)&p0.w; acc6 += a0 * __bfloat162float(q.x); acc7 += a0 * __bfloat162float(q.y);
    }

    const float4* b4 = (const float4*)bias;
    float4 b0 = b4[lane * 2], b1 = b4[lane * 2 + 1];
    float v0 = acc0 + b0.x; v0 = v0 > 0.f ? v0 : expm1f(v0);
    float v1 = acc1 + b0.y; v1 = v1 > 0.f ? v1 : expm1f(v1);
    float v2 = acc2 + b0.z; v2 = v2 > 0.f ? v2 : expm1f(v2);
    float v3 = acc3 + b0.w; v3 = v3 > 0.f ? v3 : expm1f(v3);
    float v4 = acc4 + b1.x; v4 = v4 > 0.f ? v4 : expm1f(v4);
    float v5 = acc5 + b1.y; v5 = v5 > 0.f ? v5 : expm1f(v5);
    float v6 = acc6 + b1.z; v6 = v6 > 0.f ? v6 : expm1f(v6);
    float v7 = acc7 + b1.w; v7 = v7 > 0.f ? v7 : expm1f(v7);
    uint4 ov;
    *(__nv_bfloat162*)&ov.x = __floats2bfloat162_rn(v0, v1);
    *(__nv_bfloat162*)&ov.y = __floats2bfloat162_rn(v2, v3);
    *(__nv_bfloat162*)&ov.z = __floats2bfloat162_rn(v4, v5);
    *(__nv_bfloat162*)&ov.w = __floats2bfloat162_rn(v6, v7);
    ((uint4*)(hout + (size_t)n * DDIM))[lane] = ov;
}

// ---------------- mean pool over sorted batch (bf16 input) ----------------
#define PCHUNK 256
__global__ void pool_kernel(const __nv_bfloat16* __restrict__ h, const int* __restrict__ batch,
                            float* __restrict__ sums, float* __restrict__ cnt) {
    __shared__ int sb[PCHUNK];
    int n0 = blockIdx.x * PCHUNK;
    int n1 = min(N_NODES, n0 + PCHUNK);
    int cnt_local = n1 - n0;
    for (int i = threadIdx.x; i < cnt_local; i += blockDim.x) sb[i] = batch[n0 + i];
    __syncthreads();
    int t = threadIdx.x;
    float acc = 0.0f;
    int gp = sb[0];
    for (int i = 0; i < cnt_local; i++) {
        int g = sb[i];
        if (g != gp) { atomicAdd(&sums[gp * DDIM + t], acc); acc = 0.0f; gp = g; }
        acc += __bfloat162float(h[(size_t)(n0 + i) * DDIM + t]);
    }
    atomicAdd(&sums[gp * DDIM + t], acc);
    if (t == 0) {
        float c = 0.0f; gp = sb[0];
        for (int i = 0; i < cnt_local; i++) {
            int g = sb[i];
            if (g != gp) { atomicAdd(&cnt[gp], c); c = 0.0f; gp = g; }
            c += 1.0f;
        }
        atomicAdd(&cnt[gp], c);
    }
}

// ---------------- decoder ----------------
__global__ void decoder_kernel(const float* __restrict__ sums, const float* __restrict__ cnt,
                               const float* __restrict__ w1, const float* __restrict__ b1,
                               const float* __restrict__ gam, const float* __restrict__ bet,
                               const float* __restrict__ w2, const float* __restrict__ b2,
                               float* __restrict__ out) {
    __shared__ float p[DDIM];
    __shared__ float y[64];
    int t = threadIdx.x;
    for (int gr = 0; gr < NGRP; gr++) {
        float invc = 1.0f / fmaxf(cnt[gr], 1.0f);
        for (int i = t; i < DDIM; i += 64) p[i] = sums[gr * DDIM + i] * invc;
        __syncthreads();
        float acc = b1[t];
        for (int k = 0; k < DDIM; k++) acc += p[k] * w1[k * 64 + t];
        y[t] = acc;
        __syncthreads();
        float m = 0.0f;
        for (int k = 0; k < 64; k++) m += y[k];
        m *= (1.0f / 64.0f);
        float v = 0.0f;
        for (int k = 0; k < 64; k++) { float d = y[k] - m; v += d * d; }
        v *= (1.0f / 64.0f);
        float z = fmaxf(0.0f, gam[t] * (acc - m) * rsqrtf(v + EPS_LN) + bet[t]);
        __syncthreads();
        y[t] = z;
        __syncthreads();
        if (t < OUTF) {
            float o = b2[t];
            for (int k = 0; k < 64; k++) o += y[k] * w2[k * OUTF + t];
            out[gr * OUTF + t] = o;
        }
        __syncthreads();
    }
}

// ---------------- orchestration (forked-stream graph) ----------------
extern "C" void kernel_launch(void* const* d_in, const int* in_sizes, int n_in,
                              void* d_out, int out_size) {
    const float* x      = (const float*)d_in[0];
    const int*   ei     = (const int*)d_in[1];
    const int*   batch  = (const int*)d_in[2];
    const float* enc_w1 = (const float*)d_in[3];
    const float* enc_b1 = (const float*)d_in[4];
    const float* enc_g  = (const float*)d_in[5];
    const float* enc_be = (const float*)d_in[6];
    const float* enc_w2 = (const float*)d_in[7];
    const float* enc_b2 = (const float*)d_in[8];
    const float* convW[3]  = { (const float*)d_in[9],  (const float*)d_in[13], (const float*)d_in[17] };
    const float* convAS[3] = { (const float*)d_in[10], (const float*)d_in[14], (const float*)d_in[18] };
    const float* convAD[3] = { (const float*)d_in[11], (const float*)d_in[15], (const float*)d_in[19] };
    const float* convB[3]  = { (const float*)d_in[12], (const float*)d_in[16], (const float*)d_in[20] };
    const float* dec_w1 = (const float*)d_in[21];
    const float* dec_b1 = (const float*)d_in[22];
    const float* dec_g  = (const float*)d_in[23];
    const float* dec_be = (const float*)d_in[24];
    const float* dec_w2 = (const float*)d_in[25];
    const float* dec_b2 = (const float*)d_in[26];

    float *als, *ald, *sums, *cnt;
    int *deg, *off, *cur, *adj, *bsum, *boff;
    __nv_bfloat16 *projb, *bufA, *bufB;
    __nv_bfloat16 *wthi[3], *wtlo[3];
    cudaGetSymbolAddress((void**)&bufA,  g_bufA);
    cudaGetSymbolAddress((void**)&bufB,  g_bufB);
    cudaGetSymbolAddress((void**)&projb, g_projb);
    cudaGetSymbolAddress((void**)&als,   g_als);
    cudaGetSymbolAddress((void**)&ald,   g_ald);
    cudaGetSymbolAddress((void**)&deg,   g_deg);
    cudaGetSymbolAddress((void**)&off,   g_off);
    cudaGetSymbolAddress((void**)&cur,   g_cur);
    cudaGetSymbolAddress((void**)&adj,   g_adj);
    cudaGetSymbolAddress((void**)&sums,  g_sums);
    cudaGetSymbolAddress((void**)&cnt,   g_cnt);
    cudaGetSymbolAddress((void**)&bsum,  g_bsum);
    cudaGetSymbolAddress((void**)&boff,  g_boff);
    {
        __nv_bfloat16* base;
        cudaGetSymbolAddress((void**)&base, g_wthi);
        wthi[0] = base; wthi[1] = base + DDIM * DDIM; wthi[2] = base + 2 * DDIM * DDIM;
        cudaGetSymbolAddress((void**)&base, g_wtlo);
        wtlo[0] = base; wtlo[1] = base + DDIM * DDIM; wtlo[2] = base + 2 * DDIM * DDIM;
    }

    cudaFuncSetAttribute(encoder_kernel, cudaFuncAttributeMaxDynamicSharedMemorySize, ENC_SMEM);
    cudaFuncSetAttribute(gemm_mma_kernel, cudaFuncAttributeMaxDynamicSharedMemorySize, GEMM_SMEM);

    // one-time side-stream + events (created on the first, uncaptured, call;
    // reused under capture so no stream/event creation happens while capturing)
    static cudaStream_t s2 = 0;
    static cudaEvent_t evFork = 0, evJoin = 0, evPrep = 0;
    if (s2 == 0) {
        cudaStreamCreateWithFlags(&s2, cudaStreamNonBlocking);
        cudaEventCreateWithFlags(&evFork, cudaEventDisableTiming);
        cudaEventCreateWithFlags(&evJoin, cudaEventDisableTiming);
        cudaEventCreateWithFlags(&evPrep, cudaEventDisableTiming);
    }

    // ---- fork: weight prep (all 3 layers) + CSR build + pool clears on side stream ----
    cudaEventRecord(evFork, 0);
    cudaStreamWaitEvent(s2, evFork, 0);
    prep_wt_kernel<<<DDIM, 256, 0, s2>>>(convW[0], wthi[0], wtlo[0], HID);
    prep_wt_kernel<<<DDIM, 256, 0, s2>>>(convW[1], wthi[1], wtlo[1], DDIM);
    prep_wt_kernel<<<DDIM, 256, 0, s2>>>(convW[2], wthi[2], wtlo[2], DDIM);
    cudaEventRecord(evPrep, s2);
    cudaMemsetAsync(deg, 0, N_NODES * sizeof(int), s2);
    hist_kernel<<<(ETOT + 255) / 256, 256, 0, s2>>>(ei, deg);
    degsum_kernel<<<NB_CSR, 256, 0, s2>>>(deg, bsum);
    scanb_kernel<<<1, 256, 0, s2>>>(bsum, boff);
    offsets_kernel<<<NB_CSR, 256, 0, s2>>>(deg, boff, off, cur);
    scatter_kernel<<<(ETOT + 255) / 256, 256, 0, s2>>>(ei, cur, adj);
    cudaMemsetAsync(sums, 0, NGRP * DDIM * sizeof(float), s2);
    cudaMemsetAsync(cnt, 0, NGRP * sizeof(float), s2);
    cudaEventRecord(evJoin, s2);

    // ---- main stream: encoder (independent of side work) ----
    encoder_kernel<<<(N_NODES + 63) / 64, 256, ENC_SMEM>>>(
        x, enc_w1, enc_b1, enc_g, enc_be, enc_w2, enc_b2, bufA);

    cudaStreamWaitEvent(0, evPrep, 0);     // weights ready before first gemm

    __nv_bfloat16* hin = bufA;
    __nv_bfloat16* hout = bufB;
    int Fin = HID;
    for (int L = 0; L < 3; L++) {
        dim3 ggrid(2, (N_NODES + 127) / 128);
        gemm_mma_kernel<<<ggrid, 256, GEMM_SMEM>>>(hin, wthi[L], wtlo[L], convAS[L], convAD[L],
                                                   projb, als, ald, N_NODES, Fin);
        if (L == 0) cudaStreamWaitEvent(0, evJoin, 0);   // join: gat needs CSR
        gat_fused_kernel<<<(N_NODES + 7) / 8, 256>>>(off, adj, projb, als, ald, convB[L], hout);
        __nv_bfloat16* tmp = hin; hin = hout; hout = tmp;
        Fin = DDIM;
    }

    pool_kernel<<<(N_NODES + PCHUNK - 1) / PCHUNK, 256>>>(hin, batch, sums, cnt);
    decoder_kernel<<<1, 64>>>(sums, cnt, dec_w1, dec_b1, dec_g, dec_be, dec_w2, dec_b2,
                              (float*)d_out);
}

// round 17
// speedup vs baseline: 1.0598x; 1.0118x over previous
#include <cuda_runtime.h>
#include <cuda_bf16.h>
#include <math.h>
#include <stdint.h>

#define N_NODES 50000
#define N_EDGES 800000
#define ETOT    850000   // edges + self loops
#define HID     64
#define HEADS   4
#define DDIM    256      // HID*HEADS
#define OUTF    40
#define NGRP    8
#define EPS_LN  1e-5f
#define CAP     96

// ---------------- scratch (device globals; no dynamic alloc allowed) ----------------
__device__ __nv_bfloat16 g_bufA[(size_t)N_NODES * DDIM];
__device__ __nv_bfloat16 g_bufB[(size_t)N_NODES * DDIM];
__device__ __nv_bfloat16 g_projb[(size_t)N_NODES * DDIM];
__device__ float g_als[N_NODES * HEADS];
__device__ float g_ald[N_NODES * HEADS];
__device__ int   g_deg[N_NODES];
__device__ int   g_off[N_NODES + 1];
__device__ int   g_cur[N_NODES];
__device__ int   g_adj[ETOT];
__device__ float g_sums[NGRP * DDIM];
__device__ float g_cnt[NGRP];
__device__ __nv_bfloat16 g_wthi[3][DDIM * DDIM];   // W^T hi per layer
__device__ __nv_bfloat16 g_wtlo[3][DDIM * DDIM];   // W^T lo per layer
#define NB_CSR ((N_NODES + 255) / 256)
__device__ int g_bsum[NB_CSR];
__device__ int g_boff[NB_CSR];

// ---------------- W prep: transpose + bf16 hi/lo split ----------------
__global__ void prep_wt_kernel(const float* __restrict__ W,
                               __nv_bfloat16* __restrict__ hi,
                               __nv_bfloat16* __restrict__ lo, int K) {
    int n = blockIdx.x;                    // 0..255
    for (int k = threadIdx.x; k < K; k += blockDim.x) {
        float v = W[(size_t)k * DDIM + n];
        __nv_bfloat16 h = __float2bfloat16(v);
        float r = v - __bfloat162float(h);
        hi[(size_t)n * K + k] = h;
        lo[(size_t)n * K + k] = __float2bfloat16(r);
    }
}

// ---------------- bf16x2 HMMA GEMM + fused attcoef + bf16 proj output ----------------
#define KCH 32
#define LDK 40          // padded smem row stride (bf16 elems); 80 B = 16B multiple
#define TILE_E (128 * LDK)          // bf16 elements per operand buffer (5120)
#define GEMM_SMEM (6 * TILE_E * 2)  // 2 buffers x 3 operands = 61440 bytes

__device__ __forceinline__ void mma_bf16(float* c, uint32_t a0, uint32_t a1,
                                         uint32_t a2, uint32_t a3,
                                         uint32_t b0, uint32_t b1) {
    asm volatile(
        "mma.sync.aligned.m16n8k16.row.col.f32.bf16.bf16.f32 "
        "{%0,%1,%2,%3}, {%4,%5,%6,%7}, {%8,%9}, {%0,%1,%2,%3};"
        : "+f"(c[0]), "+f"(c[1]), "+f"(c[2]), "+f"(c[3])
        : "r"(a0), "r"(a1), "r"(a2), "r"(a3), "r"(b0), "r"(b1));
}

__device__ __forceinline__ void ldsm_x4(uint32_t& d0, uint32_t& d1,
                                        uint32_t& d2, uint32_t& d3, uint32_t saddr) {
    asm volatile("ldmatrix.sync.aligned.m8n8.x4.shared.b16 {%0,%1,%2,%3}, [%4];"
                 : "=r"(d0), "=r"(d1), "=r"(d2), "=r"(d3) : "r"(saddr));
}
__device__ __forceinline__ void ldsm_x2(uint32_t& d0, uint32_t& d1, uint32_t saddr) {
    asm volatile("ldmatrix.sync.aligned.m8n8.x2.shared.b16 {%0,%1}, [%2];"
                 : "=r"(d0), "=r"(d1) : "r"(saddr));
}

__device__ __forceinline__ void cp_async16(uint32_t saddr, const void* gptr) {
    asm volatile("cp.async.cg.shared.global [%0], [%1], 16;"
                 :: "r"(saddr), "l"(gptr) : "memory");
}
#define CP_COMMIT() asm volatile("cp.async.commit_group;" ::: "memory")
#define CP_WAIT(n)  asm volatile("cp.async.wait_group %0;" :: "n"(n) : "memory")

__device__ __forceinline__ void red_add_v4(float* addr, float a, float b, float c, float d) {
    asm volatile("red.global.add.v4.f32 [%0], {%1,%2,%3,%4};"
                 :: "l"(addr), "f"(a), "f"(b), "f"(c), "f"(d) : "memory");
}

__global__ __launch_bounds__(256) void gemm_mma_kernel(
    const __nv_bfloat16* __restrict__ A,
    const __nv_bfloat16* __restrict__ BH, const __nv_bfloat16* __restrict__ BL,
    const float* __restrict__ a_s, const float* __restrict__ a_d,
    __nv_bfloat16* __restrict__ Pb,
    float* __restrict__ als, float* __restrict__ ald,
    int M, int K) {
    extern __shared__ __align__(16) __nv_bfloat16 gsm[];
    __nv_bfloat16* sA  = gsm;                 // [2][128][LDK]
    __nv_bfloat16* sBh = gsm + 2 * TILE_E;
    __nv_bfloat16* sBl = gsm + 4 * TILE_E;
    uint32_t saA  = (uint32_t)__cvta_generic_to_shared(sA);
    uint32_t saBh = (uint32_t)__cvta_generic_to_shared(sBh);
    uint32_t saBl = (uint32_t)__cvta_generic_to_shared(sBl);

    int tid = threadIdx.x;
    int warp = tid >> 5, lane = tid & 31;
    int g = lane >> 2, tg = lane & 3;
    int warpM = warp & 3, warpN = warp >> 2;   // 4 x 2
    int bm0 = blockIdx.y * 128;
    int bn0 = blockIdx.x * 128;

    float acc[2][8][4];
#pragma unroll
    for (int i = 0; i < 2; i++)
#pragma unroll
        for (int j = 0; j < 8; j++)
#pragma unroll
            for (int q = 0; q < 4; q++) acc[i][j][q] = 0.f;

    int rowLoc = tid >> 1;
    int kq = (tid & 1) * 16;
    int grow = bm0 + rowLoc;
    int arow = grow < M ? grow : (M - 1);
    int nch = K / KCH;

    int aRow = ((lane >> 3) & 1) * 8 + (lane & 7);
    int aK   = (lane >> 4) * 8;
    int bN   = lane & 7;
    int bK   = ((lane >> 3) & 1) * 8;

    uint32_t dstOffBytes = (uint32_t)(rowLoc * LDK + kq) * 2;
    const __nv_bfloat16* apBase = A + (size_t)arow * K + kq;
    const __nv_bfloat16* bhBase = BH + (size_t)(bn0 + rowLoc) * K + kq;
    const __nv_bfloat16* blBase = BL + (size_t)(bn0 + rowLoc) * K + kq;

    {
        cp_async16(saA  + dstOffBytes,      apBase);
        cp_async16(saA  + dstOffBytes + 16, apBase + 8);
        cp_async16(saBh + dstOffBytes,      bhBase);
        cp_async16(saBh + dstOffBytes + 16, bhBase + 8);
        cp_async16(saBl + dstOffBytes,      blBase);
        cp_async16(saBl + dstOffBytes + 16, blBase + 8);
        CP_COMMIT();
    }

    for (int c = 0; c < nch; c++) {
        int buf = c & 1;
        if (c + 1 < nch) {
            int k0 = (c + 1) * KCH;
            uint32_t nb = ((c + 1) & 1) * (uint32_t)(TILE_E * 2) + dstOffBytes;
            cp_async16(saA  + nb,      apBase + k0);
            cp_async16(saA  + nb + 16, apBase + k0 + 8);
            cp_async16(saBh + nb,      bhBase + k0);
            cp_async16(saBh + nb + 16, bhBase + k0 + 8);
            cp_async16(saBl + nb,      blBase + k0);
            cp_async16(saBl + nb + 16, blBase + k0 + 8);
            CP_COMMIT();
            CP_WAIT(1);
        } else {
            CP_WAIT(0);
        }
        __syncthreads();

        uint32_t aBase  = saA  + buf * (uint32_t)(TILE_E * 2);
        uint32_t bhBs   = saBh + buf * (uint32_t)(TILE_E * 2);
        uint32_t blBs   = saBl + buf * (uint32_t)(TILE_E * 2);
#pragma unroll
        for (int ks = 0; ks < 2; ks++) {
            uint32_t ah[2][4];
#pragma unroll
            for (int mt = 0; mt < 2; mt++) {
                int m = warpM * 32 + mt * 16 + aRow;
                uint32_t addr = aBase + (uint32_t)((m * LDK + ks * 16 + aK) * 2);
                ldsm_x4(ah[mt][0], ah[mt][1], ah[mt][2], ah[mt][3], addr);
            }
            uint32_t boff = (uint32_t)(((warpN * 64 + bN) * LDK + ks * 16 + bK) * 2);
#pragma unroll
            for (int nt = 0; nt < 8; nt++) {
                uint32_t bo = boff + (uint32_t)(nt * 8 * LDK * 2);
                uint32_t bh0, bh1, bl0, bl1;
                ldsm_x2(bh0, bh1, bhBs + bo);
                ldsm_x2(bl0, bl1, blBs + bo);
#pragma unroll
                for (int mt = 0; mt < 2; mt++) {
                    mma_bf16(acc[mt][nt], ah[mt][0], ah[mt][1], ah[mt][2], ah[mt][3], bh0, bh1);
                    mma_bf16(acc[mt][nt], ah[mt][0], ah[mt][1], ah[mt][2], ah[mt][3], bl0, bl1);
                }
            }
        }
        __syncthreads();
    }

    // ---- epilogue: bf16 proj store + fused attention coefficients ----
    int head = (bn0 >> 6) + warpN;
    float asv[16], adv[16];
#pragma unroll
    for (int nt = 0; nt < 8; nt++) {
#pragma unroll
        for (int q = 0; q < 2; q++) {
            int gcol = bn0 + warpN * 64 + nt * 8 + tg * 2 + q;
            asv[nt * 2 + q] = a_s[gcol];
            adv[nt * 2 + q] = a_d[gcol];
        }
    }
#pragma unroll
    for (int mt = 0; mt < 2; mt++) {
        int r0 = bm0 + warpM * 32 + mt * 16 + g;
        float s_lo = 0.f, s_hi = 0.f, d_lo = 0.f, d_hi = 0.f;
#pragma unroll
        for (int nt = 0; nt < 8; nt++) {
            int col = bn0 + warpN * 64 + nt * 8 + tg * 2;
            __nv_bfloat162 p0 = __floats2bfloat162_rn(acc[mt][nt][0], acc[mt][nt][1]);
            __nv_bfloat162 p1 = __floats2bfloat162_rn(acc[mt][nt][2], acc[mt][nt][3]);
            if (r0 < M)     *(__nv_bfloat162*)(Pb + (size_t)r0 * DDIM + col) = p0;
            if (r0 + 8 < M) *(__nv_bfloat162*)(Pb + (size_t)(r0 + 8) * DDIM + col) = p1;
            s_lo += acc[mt][nt][0] * asv[nt * 2] + acc[mt][nt][1] * asv[nt * 2 + 1];
            s_hi += acc[mt][nt][2] * asv[nt * 2] + acc[mt][nt][3] * asv[nt * 2 + 1];
            d_lo += acc[mt][nt][0] * adv[nt * 2] + acc[mt][nt][1] * adv[nt * 2 + 1];
            d_hi += acc[mt][nt][2] * adv[nt * 2] + acc[mt][nt][3] * adv[nt * 2 + 1];
        }
#pragma unroll
        for (int o = 1; o < 4; o <<= 1) {
            s_lo += __shfl_xor_sync(0xFFFFFFFFu, s_lo, o);
            s_hi += __shfl_xor_sync(0xFFFFFFFFu, s_hi, o);
            d_lo += __shfl_xor_sync(0xFFFFFFFFu, d_lo, o);
            d_hi += __shfl_xor_sync(0xFFFFFFFFu, d_hi, o);
        }
        if (tg == 0) {
            if (r0 < M)     { als[r0 * HEADS + head] = s_lo; ald[r0 * HEADS + head] = d_lo; }
            if (r0 + 8 < M) { als[(r0 + 8) * HEADS + head] = s_hi; ald[(r0 + 8) * HEADS + head] = d_hi; }
        }
    }
}

// ---------------- encoder: 64-node tiles, weights cached in smem, bf16 out ----------------
#define ENC_SMEM ((8448 + 8192 + 4352) * 4)
__global__ __launch_bounds__(256) void encoder_kernel(
    const float* __restrict__ x,
    const float* __restrict__ w1, const float* __restrict__ b1,
    const float* __restrict__ gam, const float* __restrict__ bet,
    const float* __restrict__ w2, const float* __restrict__ b2,
    __nv_bfloat16* __restrict__ h0) {
    extern __shared__ float sm[];
    float* xs = sm;             // [64][132]
    float* ws = sm + 8448;      // [128][64] then [64][64]
    float* ys = sm + 16640;     // [64][68]
    int t = threadIdx.x;
    int n0 = blockIdx.x * 64;
    for (int i = t; i < 64 * 128; i += 256) {
        int nd = i >> 7, k = i & 127;
        int gn = n0 + nd;
        xs[nd * 132 + k] = (gn < N_NODES) ? x[(size_t)gn * 128 + k] : 0.f;
    }
    for (int i = t; i < 128 * 64; i += 256) ws[i] = w1[i];
    __syncthreads();
    int tx = t & 15, ty = t >> 4;
    float acc[4][4] = {};
#pragma unroll 4
    for (int k = 0; k < 128; k++) {
        float4 b4 = *(const float4*)&ws[k * 64 + tx * 4];
        float a0 = xs[(ty * 4 + 0) * 132 + k];
        float a1 = xs[(ty * 4 + 1) * 132 + k];
        float a2 = xs[(ty * 4 + 2) * 132 + k];
        float a3 = xs[(ty * 4 + 3) * 132 + k];
        acc[0][0] += a0 * b4.x; acc[0][1] += a0 * b4.y; acc[0][2] += a0 * b4.z; acc[0][3] += a0 * b4.w;
        acc[1][0] += a1 * b4.x; acc[1][1] += a1 * b4.y; acc[1][2] += a1 * b4.z; acc[1][3] += a1 * b4.w;
        acc[2][0] += a2 * b4.x; acc[2][1] += a2 * b4.y; acc[2][2] += a2 * b4.z; acc[2][3] += a2 * b4.w;
        acc[3][0] += a3 * b4.x; acc[3][1] += a3 * b4.y; acc[3][2] += a3 * b4.z; acc[3][3] += a3 * b4.w;
    }
    float4 b1v = *(const float4*)&b1[tx * 4];
#pragma unroll
    for (int i = 0; i < 4; i++)
        *(float4*)&ys[(ty * 4 + i) * 68 + tx * 4] = make_float4(
            acc[i][0] + b1v.x, acc[i][1] + b1v.y, acc[i][2] + b1v.z, acc[i][3] + b1v.w);
    __syncthreads();
    {
        int nd = t >> 2, q = t & 3;
        float s1 = 0.f, s2 = 0.f;
#pragma unroll
        for (int j = 0; j < 16; j++) {
            float v = ys[nd * 68 + q * 16 + j];
            s1 += v; s2 += v * v;
        }
        s1 += __shfl_xor_sync(0xFFFFFFFFu, s1, 1); s2 += __shfl_xor_sync(0xFFFFFFFFu, s2, 1);
        s1 += __shfl_xor_sync(0xFFFFFFFFu, s1, 2); s2 += __shfl_xor_sync(0xFFFFFFFFu, s2, 2);
        float m = s1 * (1.f / 64.f);
        float var = s2 * (1.f / 64.f) - m * m;
        float inv = rsqrtf(var + EPS_LN);
#pragma unroll
        for (int j = 0; j < 16; j++) {
            int col = q * 16 + j;
            float v = ys[nd * 68 + col];
            float z = gam[col] * (v - m) * inv + bet[col];
            ys[nd * 68 + col] = fmaxf(z, 0.f);
        }
    }
    __syncthreads();
    for (int i = t; i < 64 * 64; i += 256) ws[i] = w2[i];
    __syncthreads();
    float acc2[4][4] = {};
#pragma unroll 4
    for (int k = 0; k < 64; k++) {
        float4 b4 = *(const float4*)&ws[k * 64 + tx * 4];
        float a0 = ys[(ty * 4 + 0) * 68 + k];
        float a1 = ys[(ty * 4 + 1) * 68 + k];
        float a2 = ys[(ty * 4 + 2) * 68 + k];
        float a3 = ys[(ty * 4 + 3) * 68 + k];
        acc2[0][0] += a0 * b4.x; acc2[0][1] += a0 * b4.y; acc2[0][2] += a0 * b4.z; acc2[0][3] += a0 * b4.w;
        acc2[1][0] += a1 * b4.x; acc2[1][1] += a1 * b4.y; acc2[1][2] += a1 * b4.z; acc2[1][3] += a1 * b4.w;
        acc2[2][0] += a2 * b4.x; acc2[2][1] += a2 * b4.y; acc2[2][2] += a2 * b4.z; acc2[2][3] += a2 * b4.w;
        acc2[3][0] += a3 * b4.x; acc2[3][1] += a3 * b4.y; acc2[3][2] += a3 * b4.z; acc2[3][3] += a3 * b4.w;
    }
    float4 b2v = *(const float4*)&b2[tx * 4];
#pragma unroll
    for (int i = 0; i < 4; i++) {
        int gn = n0 + ty * 4 + i;
        if (gn < N_NODES) {
            __nv_bfloat162 q0 = __floats2bfloat162_rn(acc2[i][0] + b2v.x, acc2[i][1] + b2v.y);
            __nv_bfloat162 q1 = __floats2bfloat162_rn(acc2[i][2] + b2v.z, acc2[i][3] + b2v.w);
            *(__nv_bfloat162*)(h0 + (size_t)gn * 64 + tx * 4)     = q0;
            *(__nv_bfloat162*)(h0 + (size_t)gn * 64 + tx * 4 + 2) = q1;
        }
    }
}

// ---------------- CSR build (two-level scan) ----------------
__global__ void hist_kernel(const int* __restrict__ ei, int* __restrict__ deg) {
    int e = blockIdx.x * blockDim.x + threadIdx.x;
    if (e >= ETOT) return;
    int dst = (e < N_EDGES) ? ei[N_EDGES + e] : (e - N_EDGES);
    atomicAdd(&deg[dst], 1);
}

__global__ void degsum_kernel(const int* __restrict__ deg, int* __restrict__ bsum) {
    __shared__ int red[256];
    int b = blockIdx.x, t = threadIdx.x;
    int i = b * 256 + t;
    red[t] = (i < N_NODES) ? deg[i] : 0;
    __syncthreads();
    for (int o = 128; o; o >>= 1) { if (t < o) red[t] += red[t + o]; __syncthreads(); }
    if (t == 0) bsum[b] = red[0];
}

__global__ void scanb_kernel(const int* __restrict__ bsum, int* __restrict__ boff) {
    __shared__ int s[256];
    int t = threadIdx.x;
    int v0 = (t < NB_CSR) ? bsum[t] : 0;
    s[t] = v0;
    __syncthreads();
    for (int o = 1; o < 256; o <<= 1) {
        int v = (t >= o) ? s[t - o] : 0;
        __syncthreads();
        s[t] += v;
        __syncthreads();
    }
    if (t < NB_CSR) boff[t] = s[t] - v0;
}

__global__ void offsets_kernel(const int* __restrict__ deg, const int* __restrict__ boff,
                               int* __restrict__ off, int* __restrict__ cur) {
    __shared__ int s[256];
    int b = blockIdx.x, t = threadIdx.x;
    int i = b * 256 + t;
    int d = (i < N_NODES) ? deg[i] : 0;
    s[t] = d;
    __syncthreads();
    for (int o = 1; o < 256; o <<= 1) {
        int v = (t >= o) ? s[t - o] : 0;
        __syncthreads();
        s[t] += v;
        __syncthreads();
    }
    int excl = boff[b] + s[t] - d;
    if (i < N_NODES) { off[i] = excl; cur[i] = excl; }
    if (b == 0 && t == 0) off[N_NODES] = ETOT;
}

__global__ void scatter_kernel(const int* __restrict__ ei,
                               int* __restrict__ cur, int* __restrict__ adj) {
    int e = blockIdx.x * blockDim.x + threadIdx.x;
    if (e >= ETOT) return;
    int src, dst;
    if (e < N_EDGES) { src = ei[e]; dst = ei[N_EDGES + e]; }
    else             { src = dst = e - N_EDGES; }
    int pos = atomicAdd(&cur[dst], 1);
    adj[pos] = src;
}

// ---------------- group count (side stream; depends only on batch) ----------------
__global__ void cnt_kernel(const int* __restrict__ batch, float* __restrict__ cnt) {
    __shared__ int loc[NGRP];
    int t = threadIdx.x;
    if (t < NGRP) loc[t] = 0;
    __syncthreads();
    int i = blockIdx.x * 256 + t;
    if (i < N_NODES) atomicAdd(&loc[batch[i]], 1);
    __syncthreads();
    if (t < NGRP && loc[t] > 0) atomicAdd(&cnt[t], (float)loc[t]);
}

// ---------------- fused GAT attention + aggregation + bias + ELU (warp per node) ----------------
// LAST variant accumulates fp32 outputs directly into the pooled sums (no hout).
__device__ __forceinline__ float lrelu(float v) { return v > 0.f ? v : 0.2f * v; }
__device__ __forceinline__ float pick4(float4 v, int h) {
    float lo = (h == 0) ? v.x : v.y;
    float hi = (h == 2) ? v.z : v.w;
    return (h < 2) ? lo : hi;
}

template <bool LAST>
__global__ __launch_bounds__(256) void gat_fused_kernel(
    const int* __restrict__ off, const int* __restrict__ adj,
    const __nv_bfloat16* __restrict__ projb, const float* __restrict__ als,
    const float* __restrict__ ald, const float* __restrict__ bias,
    __nv_bfloat16* __restrict__ hout,
    const int* __restrict__ batch, float* __restrict__ sums) {
    __shared__ float sE[8][CAP][4];
    __shared__ int   sS[8][CAP];
    __shared__ float bsum[DDIM];
    int w = threadIdx.x >> 5, lane = threadIdx.x & 31;
    int n = blockIdx.x * 8 + w;      // grid is exactly N_NODES/8 blocks (50000 = 6250*8)
    if (LAST) {
        for (int i = threadIdx.x; i < DDIM; i += 256) bsum[i] = 0.f;
        __syncthreads();
    }
    int e0 = off[n];
    int deg = off[n + 1] - e0;
    float4 aldn = ((const float4*)ald)[n];

    float4 mx = make_float4(-INFINITY, -INFINITY, -INFINITY, -INFINITY);
    for (int j = lane; j < deg; j += 32) {
        int s = adj[e0 + j];
        float4 a = ((const float4*)als)[s];
        float4 e;
        e.x = lrelu(a.x + aldn.x);
        e.y = lrelu(a.y + aldn.y);
        e.z = lrelu(a.z + aldn.z);
        e.w = lrelu(a.w + aldn.w);
        if (j < CAP) { sS[w][j] = s; *(float4*)sE[w][j] = e; }
        mx.x = fmaxf(mx.x, e.x); mx.y = fmaxf(mx.y, e.y);
        mx.z = fmaxf(mx.z, e.z); mx.w = fmaxf(mx.w, e.w);
    }
#pragma unroll
    for (int o = 16; o; o >>= 1) {
        mx.x = fmaxf(mx.x, __shfl_xor_sync(0xFFFFFFFFu, mx.x, o));
        mx.y = fmaxf(mx.y, __shfl_xor_sync(0xFFFFFFFFu, mx.y, o));
        mx.z = fmaxf(mx.z, __shfl_xor_sync(0xFFFFFFFFu, mx.z, o));
        mx.w = fmaxf(mx.w, __shfl_xor_sync(0xFFFFFFFFu, mx.w, o));
    }

    float4 sum = make_float4(0.f, 0.f, 0.f, 0.f);
    for (int j = lane; j < deg; j += 32) {
        float4 e;
        if (j < CAP) e = *(float4*)sE[w][j];
        else {
            int s = adj[e0 + j];
            float4 a = ((const float4*)als)[s];
            e.x = lrelu(a.x + aldn.x); e.y = lrelu(a.y + aldn.y);
            e.z = lrelu(a.z + aldn.z); e.w = lrelu(a.w + aldn.w);
        }
        float4 g;
        g.x = expf(e.x - mx.x); g.y = expf(e.y - mx.y);
        g.z = expf(e.z - mx.z); g.w = expf(e.w - mx.w);
        if (j < CAP) *(float4*)sE[w][j] = g;
        sum.x += g.x; sum.y += g.y; sum.z += g.z; sum.w += g.w;
    }
#pragma unroll
    for (int o = 16; o; o >>= 1) {
        sum.x += __shfl_xor_sync(0xFFFFFFFFu, sum.x, o);
        sum.y += __shfl_xor_sync(0xFFFFFFFFu, sum.y, o);
        sum.z += __shfl_xor_sync(0xFFFFFFFFu, sum.z, o);
        sum.w += __shfl_xor_sync(0xFFFFFFFFu, sum.w, o);
    }
    int hsel = lane >> 3;      // head for cols lane*8 .. lane*8+7
    float invh = 1.0f / (pick4(sum, hsel) + 1e-16f);
    float mxh  = pick4(mx, hsel);

    // pass 3: weighted aggregation, unrolled x2 for MLP
    float acc0 = 0.f, acc1 = 0.f, acc2 = 0.f, acc3 = 0.f;
    float acc4 = 0.f, acc5 = 0.f, acc6 = 0.f, acc7 = 0.f;
    int j = 0;
    for (; j + 2 <= deg; j += 2) {
        int s0, s1; float g0, g1;
        if (j < CAP) { s0 = sS[w][j]; g0 = sE[w][j][hsel]; }
        else {
            s0 = adj[e0 + j];
            float4 a = ((const float4*)als)[s0];
            g0 = expf(lrelu(pick4(a, hsel) + pick4(aldn, hsel)) - mxh);
        }
        if (j + 1 < CAP) { s1 = sS[w][j + 1]; g1 = sE[w][j + 1][hsel]; }
        else {
            s1 = adj[e0 + j + 1];
            float4 a = ((const float4*)als)[s1];
            g1 = expf(lrelu(pick4(a, hsel) + pick4(aldn, hsel)) - mxh);
        }
        uint4 p0 = ((const uint4*)(projb + (size_t)s0 * DDIM))[lane];
        uint4 p1 = ((const uint4*)(projb + (size_t)s1 * DDIM))[lane];
        float a0 = g0 * invh, a1 = g1 * invh;
        __nv_bfloat162 q;
        q = *(__nv_bfloat162*)&p0.x; acc0 += a0 * __bfloat162float(q.x); acc1 += a0 * __bfloat162float(q.y);
        q = *(__nv_bfloat162*)&p0.y; acc2 += a0 * __bfloat162float(q.x); acc3 += a0 * __bfloat162float(q.y);
        q = *(__nv_bfloat162*)&p0.z; acc4 += a0 * __bfloat162float(q.x); acc5 += a0 * __bfloat162float(q.y);
        q = *(__nv_bfloat162*)&p0.w; acc6 += a0 * __bfloat162float(q.x); acc7 += a0 * __bfloat162float(q.y);
        q = *(__nv_bfloat162*)&p1.x; acc0 += a1 * __bfloat162float(q.x); acc1 += a1 * __bfloat162float(q.y);
        q = *(__nv_bfloat162*)&p1.y; acc2 += a1 * __bfloat162float(q.x); acc3 += a1 * __bfloat162float(q.y);
        q = *(__nv_bfloat162*)&p1.z; acc4 += a1 * __bfloat162float(q.x); acc5 += a1 * __bfloat162float(q.y);
        q = *(__nv_bfloat162*)&p1.w; acc6 += a1 * __bfloat162float(q.x); acc7 += a1 * __bfloat162float(q.y);
    }
    if (j < deg) {
        int s0; float g0;
        if (j < CAP) { s0 = sS[w][j]; g0 = sE[w][j][hsel]; }
        else {
            s0 = adj[e0 + j];
            float4 a = ((const float4*)als)[s0];
            g0 = expf(lrelu(pick4(a, hsel) + pick4(aldn, hsel)) - mxh);
        }
        uint4 p0 = ((const uint4*)(projb + (size_t)s0 * DDIM))[lane];
        float a0 = g0 * invh;
        __nv_bfloat162 q;
        q = *(__nv_bfloat162*)&p0.x; acc0 += a0 * __bfloat162float(q.x); acc1 += a0 * __bfloat162float(q.y);
        q = *(__nv_bfloat162*)&p0.y; acc2 += a0 * __bfloat162float(q.x); acc3 += a0 * __bfloat162float(q.y);
        q = *(__nv_bfloat162*)&p0.z; acc4 += a0 * __bfloat162float(q.x); acc5 += a0 * __bfloat162float(q.y);
        q = *(__nv_bfloat162*)&p0.w; acc6 += a0 * __bfloat162float(q.x); acc7 += a0 * __bfloat162float(q.y);
    }

    const float4* b4 = (const float4*)bias;
    float4 b0 = b4[lane * 2], b1 = b4[lane * 2 + 1];
    float v0 = acc0 + b0.x; v0 = v0 > 0.f ? v0 : expm1f(v0);
    float v1 = acc1 + b0.y; v1 = v1 > 0.f ? v1 : expm1f(v1);
    float v2 = acc2 + b0.z; v2 = v2 > 0.f ? v2 : expm1f(v2);
    float v3 = acc3 + b0.w; v3 = v3 > 0.f ? v3 : expm1f(v3);
    float v4 = acc4 + b1.x; v4 = v4 > 0.f ? v4 : expm1f(v4);
    float v5 = acc5 + b1.y; v5 = v5 > 0.f ? v5 : expm1f(v5);
    float v6 = acc6 + b1.z; v6 = v6 > 0.f ? v6 : expm1f(v6);
    float v7 = acc7 + b1.w; v7 = v7 > 0.f ? v7 : expm1f(v7);

    if (!LAST) {
        uint4 ov;
        *(__nv_bfloat162*)&ov.x = __floats2bfloat162_rn(v0, v1);
        *(__nv_bfloat162*)&ov.y = __floats2bfloat162_rn(v2, v3);
        *(__nv_bfloat162*)&ov.z = __floats2bfloat162_rn(v4, v5);
        *(__nv_bfloat162*)&ov.w = __floats2bfloat162_rn(v6, v7);
        ((uint4*)(hout + (size_t)n * DDIM))[lane] = ov;
    } else {
        int gFirst = batch[blockIdx.x * 8];
        int gLast  = batch[blockIdx.x * 8 + 7];
        if (gFirst == gLast) {
            // single-group block: smem accumulate, then vector red to global
            int c = lane * 8;
            atomicAdd(&bsum[c + 0], v0); atomicAdd(&bsum[c + 1], v1);
            atomicAdd(&bsum[c + 2], v2); atomicAdd(&bsum[c + 3], v3);
            atomicAdd(&bsum[c + 4], v4); atomicAdd(&bsum[c + 5], v5);
            atomicAdd(&bsum[c + 6], v6); atomicAdd(&bsum[c + 7], v7);
            __syncthreads();
            int t = threadIdx.x;
            if (t < 64)
                red_add_v4(sums + gFirst * DDIM + t * 4,
                           bsum[t * 4], bsum[t * 4 + 1], bsum[t * 4 + 2], bsum[t * 4 + 3]);
        } else {
            // rare boundary block: per-node direct reduction (block-uniform branch)
            int gr = batch[n];
            red_add_v4(sums + gr * DDIM + lane * 8,     v0, v1, v2, v3);
            red_add_v4(sums + gr * DDIM + lane * 8 + 4, v4, v5, v6, v7);
            __syncthreads();   // match the other path's barrier
        }
    }
}

// ---------------- decoder ----------------
__global__ void decoder_kernel(const float* __restrict__ sums, const float* __restrict__ cnt,
                               const float* __restrict__ w1, const float* __restrict__ b1,
                               const float* __restrict__ gam, const float* __restrict__ bet,
                               const float* __restrict__ w2, const float* __restrict__ b2,
                               float* __restrict__ out) {
    __shared__ float p[DDIM];
    __shared__ float y[64];
    int t = threadIdx.x;
    for (int gr = 0; gr < NGRP; gr++) {
        float invc = 1.0f / fmaxf(cnt[gr], 1.0f);
        for (int i = t; i < DDIM; i += 64) p[i] = sums[gr * DDIM + i] * invc;
        __syncthreads();
        float acc = b1[t];
        for (int k = 0; k < DDIM; k++) acc += p[k] * w1[k * 64 + t];
        y[t] = acc;
        __syncthreads();
        float m = 0.0f;
        for (int k = 0; k < 64; k++) m += y[k];
        m *= (1.0f / 64.0f);
        float v = 0.0f;
        for (int k = 0; k < 64; k++) { float d = y[k] - m; v += d * d; }
        v *= (1.0f / 64.0f);
        float z = fmaxf(0.0f, gam[t] * (acc - m) * rsqrtf(v + EPS_LN) + bet[t]);
        __syncthreads();
        y[t] = z;
        __syncthreads();
        if (t < OUTF) {
            float o = b2[t];
            for (int k = 0; k < 64; k++) o += y[k] * w2[k * OUTF + t];
            out[gr * OUTF + t] = o;
        }
        __syncthreads();
    }
}

// ---------------- orchestration (forked-stream graph) ----------------
extern "C" void kernel_launch(void* const* d_in, const int* in_sizes, int n_in,
                              void* d_out, int out_size) {
    const float* x      = (const float*)d_in[0];
    const int*   ei     = (const int*)d_in[1];
    const int*   batch  = (const int*)d_in[2];
    const float* enc_w1 = (const float*)d_in[3];
    const float* enc_b1 = (const float*)d_in[4];
    const float* enc_g  = (const float*)d_in[5];
    const float* enc_be = (const float*)d_in[6];
    const float* enc_w2 = (const float*)d_in[7];
    const float* enc_b2 = (const float*)d_in[8];
    const float* convW[3]  = { (const float*)d_in[9],  (const float*)d_in[13], (const float*)d_in[17] };
    const float* convAS[3] = { (const float*)d_in[10], (const float*)d_in[14], (const float*)d_in[18] };
    const float* convAD[3] = { (const float*)d_in[11], (const float*)d_in[15], (const float*)d_in[19] };
    const float* convB[3]  = { (const float*)d_in[12], (const float*)d_in[16], (const float*)d_in[20] };
    const float* dec_w1 = (const float*)d_in[21];
    const float* dec_b1 = (const float*)d_in[22];
    const float* dec_g  = (const float*)d_in[23];
    const float* dec_be = (const float*)d_in[24];
    const float* dec_w2 = (const float*)d_in[25];
    const float* dec_b2 = (const float*)d_in[26];

    float *als, *ald, *sums, *cnt;
    int *deg, *off, *cur, *adj, *bsum, *boff;
    __nv_bfloat16 *projb, *bufA, *bufB;
    __nv_bfloat16 *wthi[3], *wtlo[3];
    cudaGetSymbolAddress((void**)&bufA,  g_bufA);
    cudaGetSymbolAddress((void**)&bufB,  g_bufB);
    cudaGetSymbolAddress((void**)&projb, g_projb);
    cudaGetSymbolAddress((void**)&als,   g_als);
    cudaGetSymbolAddress((void**)&ald,   g_ald);
    cudaGetSymbolAddress((void**)&deg,   g_deg);
    cudaGetSymbolAddress((void**)&off,   g_off);
    cudaGetSymbolAddress((void**)&cur,   g_cur);
    cudaGetSymbolAddress((void**)&adj,   g_adj);
    cudaGetSymbolAddress((void**)&sums,  g_sums);
    cudaGetSymbolAddress((void**)&cnt,   g_cnt);
    cudaGetSymbolAddress((void**)&bsum,  g_bsum);
    cudaGetSymbolAddress((void**)&boff,  g_boff);
    {
        __nv_bfloat16* base;
        cudaGetSymbolAddress((void**)&base, g_wthi);
        wthi[0] = base; wthi[1] = base + DDIM * DDIM; wthi[2] = base + 2 * DDIM * DDIM;
        cudaGetSymbolAddress((void**)&base, g_wtlo);
        wtlo[0] = base; wtlo[1] = base + DDIM * DDIM; wtlo[2] = base + 2 * DDIM * DDIM;
    }

    cudaFuncSetAttribute(encoder_kernel, cudaFuncAttributeMaxDynamicSharedMemorySize, ENC_SMEM);
    cudaFuncSetAttribute(gemm_mma_kernel, cudaFuncAttributeMaxDynamicSharedMemorySize, GEMM_SMEM);

    static cudaStream_t s2 = 0;
    static cudaEvent_t evFork = 0, evJoin = 0, evPrep = 0;
    if (s2 == 0) {
        cudaStreamCreateWithFlags(&s2, cudaStreamNonBlocking);
        cudaEventCreateWithFlags(&evFork, cudaEventDisableTiming);
        cudaEventCreateWithFlags(&evJoin, cudaEventDisableTiming);
        cudaEventCreateWithFlags(&evPrep, cudaEventDisableTiming);
    }

    // ---- fork: weight prep + CSR build + pooling buffers on side stream ----
    cudaEventRecord(evFork, 0);
    cudaStreamWaitEvent(s2, evFork, 0);
    prep_wt_kernel<<<DDIM, 256, 0, s2>>>(convW[0], wthi[0], wtlo[0], HID);
    prep_wt_kernel<<<DDIM, 256, 0, s2>>>(convW[1], wthi[1], wtlo[1], DDIM);
    prep_wt_kernel<<<DDIM, 256, 0, s2>>>(convW[2], wthi[2], wtlo[2], DDIM);
    cudaEventRecord(evPrep, s2);
    cudaMemsetAsync(deg, 0, N_NODES * sizeof(int), s2);
    hist_kernel<<<(ETOT + 255) / 256, 256, 0, s2>>>(ei, deg);
    degsum_kernel<<<NB_CSR, 256, 0, s2>>>(deg, bsum);
    scanb_kernel<<<1, 256, 0, s2>>>(bsum, boff);
    offsets_kernel<<<NB_CSR, 256, 0, s2>>>(deg, boff, off, cur);
    scatter_kernel<<<(ETOT + 255) / 256, 256, 0, s2>>>(ei, cur, adj);
    cudaMemsetAsync(sums, 0, NGRP * DDIM * sizeof(float), s2);
    cudaMemsetAsync(cnt, 0, NGRP * sizeof(float), s2);
    cnt_kernel<<<(N_NODES + 255) / 256, 256, 0, s2>>>(batch, cnt);
    cudaEventRecord(evJoin, s2);

    // ---- main stream: encoder ----
    encoder_kernel<<<(N_NODES + 63) / 64, 256, ENC_SMEM>>>(
        x, enc_w1, enc_b1, enc_g, enc_be, enc_w2, enc_b2, bufA);

    cudaStreamWaitEvent(0, evPrep, 0);

    __nv_bfloat16* hin = bufA;
    __nv_bfloat16* hout = bufB;
    int Fin = HID;
    for (int L = 0; L < 3; L++) {
        dim3 ggrid(2, (N_NODES + 127) / 128);
        gemm_mma_kernel<<<ggrid, 256, GEMM_SMEM>>>(hin, wthi[L], wtlo[L], convAS[L], convAD[L],
                                                   projb, als, ald, N_NODES, Fin);
        if (L == 0) cudaStreamWaitEvent(0, evJoin, 0);
        if (L < 2)
            gat_fused_kernel<false><<<N_NODES / 8, 256>>>(off, adj, projb, als, ald, convB[L],
                                                          hout, batch, sums);
        else
            gat_fused_kernel<true><<<N_NODES / 8, 256>>>(off, adj, projb, als, ald, convB[L],
                                                         hout, batch, sums);
        __nv_bfloat16* tmp = hin; hin = hout; hout = tmp;
        Fin = DDIM;
    }

    decoder_kernel<<<1, 64>>>(sums, cnt, dec_w1, dec_b1, dec_g, dec_be, dec_w2, dec_b2,
                              (float*)d_out);
}